// round 10
// baseline (speedup 1.0000x reference)
#include <cuda_runtime.h>
#include <cuda_bf16.h>
#include <math.h>
#include <stdint.h>

constexpr int V_ = 4;
constexpr int NK = 6;
constexpr int PP = 7;
constexpr int NPC = 9;             // nodes per CTA (M = 64 rows)
constexpr int NT = 256;

// weight blob (identical to R6/R9): per v, per-wg streams of [128n][64k] 16KB
// chunks (L4: [64n][64k] 8KB). wg streams are contiguous -> combined stream.
constexpr int CB  = 16384;
constexpr int CB4 = 8192;
constexpr int L3OFF  = 16 * CB;               // 262144
constexpr int L4OFF  = L3OFF + 16 * CB;       // 524288
constexpr int CTXOFF = L4OFF + 16 * CB4;      // 655360
constexpr int VSTRIDE = CTXOFF + 12 * CB;     // 851968

__device__ uint8_t g_wB[(size_t)V_ * VSTRIDE];
__device__ float   g_cst3[V_][256];

// ---- smem byte offsets (per 110.5KB CTA) ----
constexpr int OFF_W    = 0;        // 32768 (2 x 16KB ring)
constexpr int OFF_AHI  = 32768;    // 32768 (64 slots x 512B)
constexpr int OFF_ALO  = 65536;    // 32768
constexpr int OFF_CTXP = 98304;    // 9*260*4 = 9360
constexpr int OFF_SVOL = 107776;   // 2048 (arowp 1024 overlays after preamble)
constexpr int OFF_ARW  = 109824;   // 256
constexpr int OFF_INVD = 110080;   // 288
constexpr int OFF_DSUM = 110368;   // 96
constexpr int SMEM_BYTES = 110464;

// ============================ PTX helpers ====================================
__device__ __forceinline__ uint32_t su32(const void* p) {
    return (uint32_t)__cvta_generic_to_shared(p);
}
__device__ __forceinline__ void cp16(uint8_t* s, const uint8_t* g) {
    uint32_t sa = su32(s);
    asm volatile("cp.async.cg.shared.global [%0], [%1], 16;" :: "r"(sa), "l"(g));
}
#define CP_COMMIT() asm volatile("cp.async.commit_group;" ::: "memory")
#define CP_WAIT1()  asm volatile("cp.async.wait_group 1;" ::: "memory")
#define CP_WAIT0()  asm volatile("cp.async.wait_group 0;" ::: "memory")

#define MMA_BF16(acc, a, b0, b1) asm volatile( \
    "mma.sync.aligned.m16n8k16.row.col.f32.bf16.bf16.f32 " \
    "{%0,%1,%2,%3}, {%4,%5,%6,%7}, {%8,%9}, {%0,%1,%2,%3};" \
    : "+f"((acc)[0]), "+f"((acc)[1]), "+f"((acc)[2]), "+f"((acc)[3]) \
    : "r"((a).x), "r"((a).y), "r"((a).z), "r"((a).w), "r"(b0), "r"(b1))

#define LDSM4(r0, r1, r2, r3, addr) asm volatile( \
    "ldmatrix.sync.aligned.m8n8.x4.shared.b16 {%0,%1,%2,%3}, [%4];" \
    : "=r"(r0), "=r"(r1), "=r"(r2), "=r"(r3) : "r"(addr))

__device__ __forceinline__ void relu_split(float x, float y, uint32_t& h, uint32_t& l) {
    x = fmaxf(x, 0.f); y = fmaxf(y, 0.f);
    __nv_bfloat162 hb = __float22bfloat162_rn(make_float2(x, y));
    float2 hf = __bfloat1622float2(hb);
    __nv_bfloat162 lb = __float22bfloat162_rn(make_float2(x - hf.x, y - hf.y));
    h = *reinterpret_cast<uint32_t*>(&hb);
    l = *reinterpret_cast<uint32_t*>(&lb);
}
__device__ __forceinline__ void plain_split(float x, float y, uint32_t& h, uint32_t& l) {
    __nv_bfloat162 hb = __float22bfloat162_rn(make_float2(x, y));
    float2 hf = __bfloat1622float2(hb);
    __nv_bfloat162 lb = __float22bfloat162_rn(make_float2(x - hf.x, y - hf.y));
    h = *reinterpret_cast<uint32_t*>(&hb);
    l = *reinterpret_cast<uint32_t*>(&lb);
}
__device__ __forceinline__ void ffma2s(float2& d, float a, float2 b) {
    unsigned long long dd = *reinterpret_cast<unsigned long long*>(&d);
    float2 av = make_float2(a, a);
    unsigned long long aa = *reinterpret_cast<unsigned long long*>(&av);
    unsigned long long bb = *reinterpret_cast<unsigned long long*>(&b);
    asm("fma.rn.f32x2 %0, %1, %2, %0;" : "+l"(dd) : "l"(aa), "l"(bb));
    d = *reinterpret_cast<float2*>(&dd);
}

// ===================== side kernel 1: cst3 (unchanged) =======================
__global__ void cst3_kernel(const float* __restrict__ gpv, const float* __restrict__ gpr,
                            const float* __restrict__ pW, const float* __restrict__ pb,
                            const float* __restrict__ aW1, const float* __restrict__ ab1)
{
    __shared__ float pe[32];
    const int t = threadIdx.x;
    const float p0 = gpv[0] / gpr[0], p1 = gpv[1] / gpr[1];
    if (t < 32) pe[t] = fmaxf(pb[t] + p0 * pW[t] + p1 * pW[32 + t], 0.f);
    __syncthreads();
    for (int idx = t; idx < V_ * 256; idx += blockDim.x) {
        const int v = idx >> 8, c = idx & 255;
        const float* W = aW1 + ((size_t)v * 448 + 416) * 256 + c;
        float s = ab1[v * 256 + c];
#pragma unroll
        for (int k = 0; k < 32; k++) s += pe[k] * W[(size_t)k * 256];
        g_cst3[v][c] = s;
    }
}

// ===================== side kernel 2: weight convert (unchanged blob) ========
__global__ void wconv_kernel(const float* __restrict__ bW2,
                             const float* __restrict__ aW1,
                             const float* __restrict__ aW2)
{
    constexpr int PERV = 131072 + 131072 + 65536 + 98304;   // 425984
    const int total = V_ * PERV;
    for (int idx = blockIdx.x * blockDim.x + threadIdx.x; idx < total;
         idx += gridDim.x * blockDim.x) {
        const int v = idx / PERV;
        int e = idx % PERV;
        size_t dst;
        int n_local, kl;
        bool hiC;
        float w;
        if (e < 131072) {                       // L2
            const int wg = e >> 16, r = e & 65535;
            const int c = r >> 13, rr = r & 8191;
            n_local = rr >> 6; kl = rr & 63;
            const int n = wg * 128 + n_local, k = (c & 3) * 64 + kl;
            hiC = (c < 4);
            w = bW2[((size_t)v * 256 + k) * 256 + n];
            dst = (size_t)wg * 8 * CB + (size_t)c * CB;
        } else if (e < 262144) {                // L3
            e -= 131072;
            const int wg = e >> 16, r = e & 65535;
            const int c = r >> 13, rr = r & 8191;
            n_local = rr >> 6; kl = rr & 63;
            const int n = wg * 128 + n_local, k = (c & 3) * 64 + kl;
            hiC = (c < 4);
            w = aW1[((size_t)v * 448 + k) * 256 + n];
            dst = L3OFF + (size_t)wg * 8 * CB + (size_t)c * CB;
        } else if (e < 327680) {                // L4
            e -= 262144;
            const int wg = e >> 15, r = e & 32767;
            const int c = r >> 12, rr = r & 4095;
            n_local = rr >> 6; kl = rr & 63;
            const int n = wg * 64 + n_local, k = (c & 3) * 64 + kl;
            hiC = (c < 4);
            w = aW2[((size_t)v * 256 + k) * 128 + n];
            dst = L4OFF + (size_t)wg * 8 * CB4 + (size_t)c * CB4;
        } else {                                // CTX (K padded 160->192)
            e -= 327680;
            const int wg2 = e / 49152, r2 = e % 49152;
            const int c = r2 >> 13, rr = r2 & 8191;
            n_local = rr >> 6; kl = rr & 63;
            const int n = wg2 * 128 + n_local, k = (c % 3) * 64 + kl;
            hiC = (c < 3);
            w = (k < 160) ? aW1[((size_t)v * 448 + 256 + k) * 256 + n] : 0.f;
            dst = CTXOFF + (size_t)wg2 * 6 * CB + (size_t)c * CB;
        }
        __nv_bfloat16 hi = __float2bfloat16_rn(w);
        __nv_bfloat16 val = hiC ? hi : __float2bfloat16_rn(w - __bfloat162float(hi));
        uint8_t* p = g_wB + (size_t)v * VSTRIDE + dst
                   + n_local * 128 + (((uint32_t)(kl * 2)) ^ (((uint32_t)n_local & 7) << 4));
        *reinterpret_cast<__nv_bfloat16*>(p) = val;
    }
}

// ===================== copy / prefetch (256 threads) =========================
template <int CBT>
__device__ __forceinline__ void copy_chunkT(uint8_t* dst, const uint8_t* src, int t) {
    constexpr int NCP = CBT / 16 / NT;
#pragma unroll
    for (int i = 0; i < NCP; i++)
        cp16(dst + (t + i * NT) * 16, src + (size_t)(t + i * NT) * 16);
}
template <int CBT>
__device__ __forceinline__ void prefetchT(uint8_t* sbW, const uint8_t* wsrc, int t) {
    copy_chunkT<CBT>(sbW, wsrc, t);              CP_COMMIT();
    copy_chunkT<CBT>(sbW + CBT, wsrc + CBT, t);  CP_COMMIT();
}

// ===================== mainloop ==============================================
// MODE 0: ctx  (12 chunks CB,  M=1 frag, warp = 2 Nfrag/chunk)
// MODE 2: big  (16 chunks CB,  warp = 2 Mfrag x 4 Nfrag/chunk)
// MODE 3: L4   (16 chunks CB4, warp = 2 Mfrag x 2 Nfrag/chunk)
template <int MODE>
__device__ __forceinline__ void run_ml(
    uint8_t* sbW, const uint8_t* wsrc, int t, int lane, int widg,
    const uint4* __restrict__ AHI, const uint4* __restrict__ ALO, float (*acc)[4])
{
    constexpr int NCHUNK = (MODE == 0) ? 12 : 16;
    constexpr int CBT = (MODE == 3) ? CB4 : CB;
    const uint32_t swzc = ((uint32_t)lane & 7) << 4;
    const int lanerow = 8 * ((lane >> 4) & 1) + (lane & 7);
    const int kadd = ((lane >> 3) & 1) * 8;
    const int m2 = widg & 1, n2 = widg >> 1;
#pragma unroll 1
    for (int c = 0; c < NCHUNK; c++) {
        if (c < NCHUNK - 1) CP_WAIT1(); else CP_WAIT0();
        __syncthreads();
        const uint32_t wb = su32(sbW + (c & 1) * CBT);
        int s, cc;
        if constexpr (MODE == 0) { s = c / 6; cc = c % 6; }
        else { s = c >> 3; cc = c & 7; }
        const bool hiB = (MODE == 0) ? (cc < 3) : (cc < 4);
        const int fkb = (MODE == 0) ? (cc % 3) * 4 : (cc & 3) * 4;
#pragma unroll
        for (int sk = 0; sk < 4; sk++) {
            const int fk = fkb + sk;
            const int koff = sk * 16 + kadd;
            if constexpr (MODE == 0) {
                const uint4 a0 = AHI[fk * 32 + lane];
                uint4 al = make_uint4(0, 0, 0, 0);
                if (hiB) al = ALO[fk * 32 + lane];
                const uint32_t ba = wb + (uint32_t)((widg * 16 + lanerow) * 128)
                                  + (((uint32_t)(koff * 2)) ^ swzc);
                uint32_t b0, b1, b2, b3;
                LDSM4(b0, b1, b2, b3, ba);
                MMA_BF16(acc[s * 2 + 0], a0, b0, b1);
                MMA_BF16(acc[s * 2 + 1], a0, b2, b3);
                if (hiB) {
                    MMA_BF16(acc[s * 2 + 0], al, b0, b1);
                    MMA_BF16(acc[s * 2 + 1], al, b2, b3);
                }
            } else if constexpr (MODE == 2) {
                const int sl0 = m2 * 32 + fk, sl1 = sl0 + 16;
                const uint4 a0 = AHI[sl0 * 32 + lane];
                const uint4 a1 = AHI[sl1 * 32 + lane];
                uint4 l0 = make_uint4(0, 0, 0, 0), l1 = l0;
                if (hiB) { l0 = ALO[sl0 * 32 + lane]; l1 = ALO[sl1 * 32 + lane]; }
                const uint32_t ba = wb + (uint32_t)((n2 * 32 + lanerow) * 128)
                                  + (((uint32_t)(koff * 2)) ^ swzc);
#pragma unroll
                for (int jj = 0; jj < 2; jj++) {
                    uint32_t b0, b1, b2, b3;
                    LDSM4(b0, b1, b2, b3, ba + jj * 2048);
                    const int ix = s * 4 + jj * 2;
                    MMA_BF16(acc[ix],         a0, b0, b1);
                    MMA_BF16(acc[ix + 1],     a0, b2, b3);
                    MMA_BF16(acc[8 + ix],     a1, b0, b1);
                    MMA_BF16(acc[8 + ix + 1], a1, b2, b3);
                    if (hiB) {
                        MMA_BF16(acc[ix],         l0, b0, b1);
                        MMA_BF16(acc[ix + 1],     l0, b2, b3);
                        MMA_BF16(acc[8 + ix],     l1, b0, b1);
                        MMA_BF16(acc[8 + ix + 1], l1, b2, b3);
                    }
                }
            } else {
                const int sl0 = m2 * 32 + fk, sl1 = sl0 + 16;
                const uint4 a0 = AHI[sl0 * 32 + lane];
                const uint4 a1 = AHI[sl1 * 32 + lane];
                uint4 l0 = make_uint4(0, 0, 0, 0), l1 = l0;
                if (hiB) { l0 = ALO[sl0 * 32 + lane]; l1 = ALO[sl1 * 32 + lane]; }
                const uint32_t ba = wb + (uint32_t)((n2 * 16 + lanerow) * 128)
                                  + (((uint32_t)(koff * 2)) ^ swzc);
                uint32_t b0, b1, b2, b3;
                LDSM4(b0, b1, b2, b3, ba);
                const int ix = s * 2;
                MMA_BF16(acc[ix],         a0, b0, b1);
                MMA_BF16(acc[ix + 1],     a0, b2, b3);
                MMA_BF16(acc[4 + ix],     a1, b0, b1);
                MMA_BF16(acc[4 + ix + 1], a1, b2, b3);
                if (hiB) {
                    MMA_BF16(acc[ix],         l0, b0, b1);
                    MMA_BF16(acc[ix + 1],     l0, b2, b3);
                    MMA_BF16(acc[4 + ix],     l1, b0, b1);
                    MMA_BF16(acc[4 + ix + 1], l1, b2, b3);
                }
            }
        }
        __syncthreads();
        if (c + 2 < NCHUNK) {
            copy_chunkT<CBT>(sbW + (c & 1) * CBT, wsrc + (size_t)(c + 2) * CBT, t);
            CP_COMMIT();
        }
    }
}

// ===================== epilogue: C frags -> A frags ==========================
// MODE 0: gmem bias via __ldg; MODE 1: per-node ctxp (smem, stride 260).
template <int MODE>
__device__ __forceinline__ void epiA(
    uint8_t* sb, float (*acc)[4], const float* __restrict__ addv,
    int widg, int lane)
{
    uint4* AHI = (uint4*)(sb + OFF_AHI);
    uint4* ALO = (uint4*)(sb + OFF_ALO);
    const int quad = lane >> 2, q4 = lane & 3;
    const int m2 = widg & 1, n2 = widg >> 1;
#pragma unroll
    for (int e = 0; e < 2; e++) {
        const int mfrag = m2 * 2 + e;
        const int r0 = mfrag * 16 + quad;
        int n0 = r0 / 7;       if (n0 > 8) n0 = 8;
        int n1 = (r0 + 8) / 7; if (n1 > 8) n1 = 8;
#pragma unroll
        for (int s = 0; s < 2; s++)
#pragma unroll
            for (int jj = 0; jj < 2; jj++) {
                const int c0 = s * 128 + n2 * 32 + jj * 16 + 2 * q4;
                const int c2 = c0 + 8;
                float2 a00, a01, a10, a11;
                if constexpr (MODE == 0) {
                    a00 = __ldg((const float2*)(addv + c0));
                    a01 = __ldg((const float2*)(addv + c2));
                    a10 = a00; a11 = a01;
                } else {
                    a00 = *(const float2*)(addv + n0 * 260 + c0);
                    a01 = *(const float2*)(addv + n0 * 260 + c2);
                    a10 = *(const float2*)(addv + n1 * 260 + c0);
                    a11 = *(const float2*)(addv + n1 * 260 + c2);
                }
                const float* A = acc[e * 8 + s * 4 + jj * 2];
                const float* B = acc[e * 8 + s * 4 + jj * 2 + 1];
                uint32_t h0, l0, h1, l1, h2, l2, h3, l3;
                relu_split(A[0] + a00.x, A[1] + a00.y, h0, l0);
                relu_split(A[2] + a10.x, A[3] + a10.y, h1, l1);
                relu_split(B[0] + a01.x, B[1] + a01.y, h2, l2);
                relu_split(B[2] + a11.x, B[3] + a11.y, h3, l3);
                const int fi = (mfrag * 16 + s * 8 + n2 * 2 + jj) * 32 + lane;
                AHI[fi] = make_uint4(h0, h1, h2, h3);
                ALO[fi] = make_uint4(l0, l1, l2, l3);
            }
    }
}

// ============================ main kernel ====================================
__global__ void __launch_bounds__(NT, 2)
surface_kernel(
    const float* __restrict__ centers,  const float* __restrict__ enc_g,
    const float* __restrict__ enc_node, const float* __restrict__ neighbors,
    const float* __restrict__ normals,  const float* __restrict__ neigh_normals,
    const float* __restrict__ areas,    const float* __restrict__ neigh_areas,
    const float* __restrict__ basis_W1, const float* __restrict__ basis_b1,
    const float* __restrict__ basis_b2, const float* __restrict__ agg_b2,
    const float* __restrict__ agg_W3,   const float* __restrict__ agg_b3,
    float* __restrict__ out, const int n_nodes)
{
    extern __shared__ uint8_t sb[];
    const int t = threadIdx.x;
    const int widg = t >> 5, lane = t & 31;
    const int quad = lane >> 2, q4 = lane & 3;
    const int base = blockIdx.x * NPC;

    float* ctxp  = (float*)(sb + OFF_CTXP);
    float* svol  = (float*)(sb + OFF_SVOL);
    float* arowp = (float*)(sb + OFF_SVOL);    // overlay after preamble
    float* arow  = (float*)(sb + OFF_ARW);
    float* invd  = (float*)(sb + OFF_INVD);
    float* dsum  = (float*)(sb + OFF_DSUM);
    uint8_t* sbW = sb + OFF_W;
    uint4* AHI = (uint4*)(sb + OFF_AHI);
    uint4* ALO = (uint4*)(sb + OFF_ALO);

    // prefetch v=0 ctx chunks
    prefetchT<CB>(sbW, g_wB + CTXOFF, t);

    // ---- preamble: build 64 vol rows ----
    if (t < 64) {
        float f[8] = {0.f,0.f,0.f,0.f,0.f,0.f,0.f,0.f};
        const int nl = t / PP, p = t % PP;
        const int node = base + nl;
        if (t < NPC * PP && node < n_nodes) {
            if (p == 0) {
                f[0]=centers[node*3+0]; f[1]=centers[node*3+1]; f[2]=centers[node*3+2];
                f[3]=normals[node*3+0]; f[4]=normals[node*3+1]; f[5]=normals[node*3+2];
                f[6]=logf(areas[node]) * 0.1f;
            } else {
                const int nb = node * NK + (p - 1);
                f[0]=neighbors[nb*3+0]+1e-6f; f[1]=neighbors[nb*3+1]+1e-6f;
                f[2]=neighbors[nb*3+2]+1e-6f;
                f[3]=neigh_normals[nb*3+0]+1e-6f; f[4]=neigh_normals[nb*3+1]+1e-6f;
                f[5]=neigh_normals[nb*3+2]+1e-6f;
                f[6]=logf(neigh_areas[nb]) * 0.1f + 1e-6f;
            }
        }
#pragma unroll
        for (int q = 0; q < 8; q++) svol[t * 8 + q] = f[q];
    }
    __syncthreads();
    if (t < NPC * NK) {
        const int nl = t / NK, j = t % NK;
        float d2 = 0.f;
#pragma unroll
        for (int q = 0; q < 7; q++) {
            const float d = svol[(nl*7)*8 + q] - svol[(nl*7 + 1 + j)*8 + q];
            d2 += d * d;
        }
        invd[nl * 8 + j] = 1.f / sqrtf(d2);
    }
    __syncthreads();
    if (t < NPC) {
        float s = 0.f;
#pragma unroll
        for (int j = 0; j < NK; j++) s += invd[t * 8 + j];
        dsum[t] = s;
    }
    __syncthreads();
    // per-warp svol rows for L1 (rowgrp = widg&3, colhalf = widg>>2)
    const int rg = widg & 3, ch = widg >> 2;
    const int r0L = rg * 16 + quad;
    float sv0[7], sv1[7];
#pragma unroll
    for (int q = 0; q < 7; q++) {
        sv0[q] = svol[r0L * 8 + q];
        sv1[q] = svol[(r0L + 8) * 8 + q];
    }
    __syncthreads();   // svol dead; arowp may reuse

    float acc[16][4];

#pragma unroll 1
    for (int v = 0; v < V_; v++) {
        const uint8_t* wv = g_wB + (size_t)v * VSTRIDE;

        // ---- ctx A frags (slots 0..11; M=16 rows = nodes, K padded 192) ----
#pragma unroll
        for (int rep = 0; rep < 2; rep++) {
            const int slot = widg + rep * 8;
            if (slot < 12) {
                const int cc0 = slot * 16 + 2 * q4, cc1 = cc0 + 8;
                auto feat2 = [&](int nl, int k) -> float2 {
                    const int node = base + nl;
                    if (nl < NPC && node < n_nodes && k < 160) {
                        if (k < 32) return *(const float2*)(enc_node + (size_t)node*32 + k);
                        return *(const float2*)(enc_g + (size_t)node*128 + (k - 32));
                    }
                    return make_float2(0.f, 0.f);
                };
                const float2 v00 = feat2(quad, cc0),     v10 = feat2(quad + 8, cc0);
                const float2 v01 = feat2(quad, cc1),     v11 = feat2(quad + 8, cc1);
                uint32_t h0,l0,h1,l1,h2,l2,h3,l3;
                plain_split(v00.x, v00.y, h0, l0);
                plain_split(v10.x, v10.y, h1, l1);
                plain_split(v01.x, v01.y, h2, l2);
                plain_split(v11.x, v11.y, h3, l3);
                AHI[slot * 32 + lane] = make_uint4(h0, h1, h2, h3);
                ALO[slot * 32 + lane] = make_uint4(l0, l1, l2, l3);
            }
        }
        __syncthreads();

        // ---- ctx GEMM ----
#pragma unroll
        for (int i = 0; i < 4; i++)
#pragma unroll
            for (int j = 0; j < 4; j++) acc[i][j] = 0.f;
        run_ml<0>(sbW, wv + CTXOFF, t, lane, widg, AHI, ALO, acc);
        prefetchT<CB>(sbW, wv, t);   // L2 chunks fly during epilogue + L1
        // ctx epilogue: warp widg owns cols s*128 + widg*16 .. +16
        {
            const float* cstv = g_cst3[v];
#pragma unroll
            for (int s = 0; s < 2; s++)
#pragma unroll
                for (int nf = 0; nf < 2; nf++) {
                    const int col = s * 128 + widg * 16 + nf * 8 + 2 * q4;
                    const float2 cst = *(const float2*)(cstv + col);
                    const float* a = acc[s * 2 + nf];
                    if (quad < NPC && base + quad < n_nodes)
                        *(float2*)(ctxp + quad * 260 + col) =
                            make_float2(a[0] + cst.x, a[1] + cst.y);
                    if (quad + 8 < NPC && base + quad + 8 < n_nodes)
                        *(float2*)(ctxp + (quad + 8) * 260 + col) =
                            make_float2(a[2] + cst.x, a[3] + cst.y);
                }
        }
        __syncthreads();   // ctx A slots free

        // ---- L1 scalar -> A frags (overlaps L2 copies) ----
        {
            const float* W1v = basis_W1 + (size_t)v * 1792;
            const float* b1v = basis_b1 + v * 256;
#pragma unroll
            for (int u = 0; u < 8; u++) {
                const int c0 = ch * 128 + u * 16 + 2 * q4;
                const int c2 = c0 + 8;
                float2 a00 = __ldg((const float2*)(b1v + c0));
                float2 a01 = __ldg((const float2*)(b1v + c2));
                float2 a10 = a00, a11 = a01;
#pragma unroll
                for (int q = 0; q < 7; q++) {
                    const float2 w0 = __ldg((const float2*)(W1v + q * 256 + c0));
                    const float2 w2 = __ldg((const float2*)(W1v + q * 256 + c2));
                    ffma2s(a00, sv0[q], w0); ffma2s(a01, sv0[q], w2);
                    ffma2s(a10, sv1[q], w0); ffma2s(a11, sv1[q], w2);
                }
                uint32_t h0, l0, h1, l1, h2, l2, h3, l3;
                relu_split(a00.x, a00.y, h0, l0);
                relu_split(a10.x, a10.y, h1, l1);
                relu_split(a01.x, a01.y, h2, l2);
                relu_split(a11.x, a11.y, h3, l3);
                const int fi = (rg * 16 + ch * 8 + u) * 32 + lane;
                AHI[fi] = make_uint4(h0, h1, h2, h3);
                ALO[fi] = make_uint4(l0, l1, l2, l3);
            }
        }
        __syncthreads();

        // ---- L2 ----
#pragma unroll
        for (int i = 0; i < 16; i++)
#pragma unroll
            for (int j = 0; j < 4; j++) acc[i][j] = 0.f;
        run_ml<2>(sbW, wv, t, lane, widg, AHI, ALO, acc);
        prefetchT<CB>(sbW, wv + L3OFF, t);
        epiA<0>(sb, acc, basis_b2 + v * 256, widg, lane);
        __syncthreads();
        // ---- L3 ----
#pragma unroll
        for (int i = 0; i < 16; i++)
#pragma unroll
            for (int j = 0; j < 4; j++) acc[i][j] = 0.f;
        run_ml<2>(sbW, wv + L3OFF, t, lane, widg, AHI, ALO, acc);
        prefetchT<CB4>(sbW, wv + L4OFF, t);
        epiA<1>(sb, acc, ctxp, widg, lane);
        __syncthreads();
        // ---- L4 + L5 ----
#pragma unroll
        for (int i = 0; i < 8; i++)
#pragma unroll
            for (int j = 0; j < 4; j++) acc[i][j] = 0.f;
        run_ml<3>(sbW, wv + L4OFF, t, lane, widg, AHI, ALO, acc);
        if (v + 1 < V_) prefetchT<CB>(sbW, wv + VSTRIDE + CTXOFF, t);
        {
            const int m2 = widg & 1, n2 = widg >> 1;
            const float* w3v = agg_W3 + v * 128;
            const float* b4v = agg_b2 + v * 128;
            float s4[4] = {0.f, 0.f, 0.f, 0.f};
#pragma unroll
            for (int e = 0; e < 2; e++)
#pragma unroll
                for (int s = 0; s < 2; s++)
#pragma unroll
                    for (int nf = 0; nf < 2; nf++) {
                        const int c0 = s * 64 + n2 * 16 + nf * 8 + 2 * q4;
                        const float2 wv3 = __ldg((const float2*)(w3v + c0));
                        const float2 bv4 = __ldg((const float2*)(b4v + c0));
                        const float* a = acc[e * 4 + s * 2 + nf];
                        s4[e * 2 + 0] += fmaxf(a[0] + bv4.x, 0.f) * wv3.x
                                       + fmaxf(a[1] + bv4.y, 0.f) * wv3.y;
                        s4[e * 2 + 1] += fmaxf(a[2] + bv4.x, 0.f) * wv3.x
                                       + fmaxf(a[3] + bv4.y, 0.f) * wv3.y;
                    }
#pragma unroll
            for (int i = 0; i < 4; i++) {
                s4[i] += __shfl_xor_sync(0xffffffffu, s4[i], 1);
                s4[i] += __shfl_xor_sync(0xffffffffu, s4[i], 2);
            }
            __syncthreads();
            if (q4 == 0) {
                const int rb = m2 * 32 + quad;
                arowp[n2 * 64 + rb]     = s4[0];
                arowp[n2 * 64 + rb + 8] = s4[1];
                arowp[n2 * 64 + rb + 16] = s4[2];
                arowp[n2 * 64 + rb + 24] = s4[3];
            }
        }
        __syncthreads();
        if (t < 64)
            arow[t] = arowp[t] + arowp[64 + t] + arowp[128 + t] + arowp[192 + t]
                    + __ldg(agg_b3 + v);
        __syncthreads();
        if (t < NPC) {
            const int node = base + t;
            if (node < n_nodes) {
                const float c = arow[t * 7];
                float s = 0.f;
#pragma unroll
                for (int j = 0; j < NK; j++) s += arow[t * 7 + 1 + j] * invd[t * 8 + j];
                out[node * V_ + v] = 0.5f * c + 0.5f * s / dsum[t];
            }
        }
        __syncthreads();
    }
}

// ============================ launcher =======================================
extern "C" void kernel_launch(void* const* d_in, const int* in_sizes, int n_in,
                              void* d_out, int out_size)
{
    const float* centers       = (const float*)d_in[0];
    const float* enc_g         = (const float*)d_in[1];
    const float* enc_node      = (const float*)d_in[2];
    const float* neighbors     = (const float*)d_in[3];
    const float* normals       = (const float*)d_in[4];
    const float* neigh_normals = (const float*)d_in[5];
    const float* areas         = (const float*)d_in[6];
    const float* neigh_areas   = (const float*)d_in[7];
    const float* gpv           = (const float*)d_in[8];
    const float* gpr           = (const float*)d_in[9];
    const float* param_W       = (const float*)d_in[10];
    const float* param_b       = (const float*)d_in[11];
    const float* basis_W1      = (const float*)d_in[12];
    const float* basis_b1      = (const float*)d_in[13];
    const float* basis_W2      = (const float*)d_in[14];
    const float* basis_b2      = (const float*)d_in[15];
    const float* agg_W1        = (const float*)d_in[16];
    const float* agg_b1        = (const float*)d_in[17];
    const float* agg_W2        = (const float*)d_in[18];
    const float* agg_b2        = (const float*)d_in[19];
    const float* agg_W3        = (const float*)d_in[20];
    const float* agg_b3        = (const float*)d_in[21];
    float* out = (float*)d_out;

    const int n_nodes = in_sizes[0] / 3;
    const int grid = (n_nodes + NPC - 1) / NPC;

    cudaFuncSetAttribute(surface_kernel,
                         cudaFuncAttributeMaxDynamicSharedMemorySize, SMEM_BYTES);

    cst3_kernel<<<1, 256>>>(gpv, gpr, param_W, param_b, agg_W1, agg_b1);
    wconv_kernel<<<2560, 512>>>(basis_W2, agg_W1, agg_W2);
    surface_kernel<<<grid, NT, SMEM_BYTES>>>(
        centers, enc_g, enc_node, neighbors, normals, neigh_normals,
        areas, neigh_areas,
        basis_W1, basis_b1, basis_b2, agg_b2, agg_W3, agg_b3, out, n_nodes);
}

// round 12
// speedup vs baseline: 3.9278x; 3.9278x over previous
#include <cuda_runtime.h>
#include <cuda_bf16.h>
#include <math.h>
#include <stdint.h>

constexpr int V_ = 4;
constexpr int NK = 6;
constexpr int PP = 7;
constexpr int NPC = 18;
constexpr int ROWS_ = 126;
constexpr int NT = 512;

// weight blob per v, per-warpgroup streams of [128n][64k] (16KB) chunks
// (L4: [64n][64k] 8KB). Per wg: L2 8 chunks, L3 8, L4 8, CTX 6.
// Chunk order INTERLEAVED: d = 2*kk + (hi?0:1)  (h0,l0,h1,l1,...)
constexpr int CB  = 16384;
constexpr int CB4 = 8192;
constexpr int L3OFF  = 16 * CB;               // 262144
constexpr int L4OFF  = L3OFF + 16 * CB;       // 524288
constexpr int CTXOFF = L4OFF + 16 * CB4;      // 655360
constexpr int VSTRIDE = CTXOFF + 12 * CB;     // 851968

__device__ uint8_t g_wB[(size_t)V_ * VSTRIDE];
__device__ float   g_cst3[V_][256];

// ---- smem byte offsets ----
constexpr int OFF_W    = 0;        // 65536: wg0 [0,32K), wg1 [32K,64K)
constexpr int OFF_AHI  = 65536;    // 65536 (A hi frags: 128 slots x 512B)
constexpr int OFF_ALO  = 131072;   // 65536
constexpr int OFF_CTXP = 196608;   // 18*260*4 = 18720
constexpr int OFF_SVOL = 215328;   // 4096
constexpr int OFF_W1S  = 219424;   // 7168
constexpr int OFF_B1S  = 226592;   // 1024
constexpr int OFF_B2S  = 227616;   // 1024
constexpr int OFF_B4S  = 228640;   // 512
constexpr int OFF_W3S  = 229152;   // 512
constexpr int OFF_ARP  = 229664;   // 1024
constexpr int OFF_ARW  = 230688;   // 512
constexpr int OFF_INVD = 231200;   // 576
constexpr int OFF_DSUM = 231776;   // 96
constexpr int SMEM_BYTES = 231872;

// ============================ PTX helpers ====================================
__device__ __forceinline__ uint32_t su32(const void* p) {
    return (uint32_t)__cvta_generic_to_shared(p);
}
__device__ __forceinline__ void cp16(uint8_t* s, const uint8_t* g) {
    uint32_t sa = su32(s);
    asm volatile("cp.async.cg.shared.global [%0], [%1], 16;" :: "r"(sa), "l"(g));
}
#define CP_COMMIT() asm volatile("cp.async.commit_group;" ::: "memory")
#define CP_WAIT1()  asm volatile("cp.async.wait_group 1;" ::: "memory")
#define CP_WAIT0()  asm volatile("cp.async.wait_group 0;" ::: "memory")
// per-warpgroup named barrier (ids 1,2), 256 threads each
#define BARW(g) asm volatile("bar.sync %0, %1;" :: "r"((g) + 1), "r"(256) : "memory")

#define MMA_BF16(acc, a, b0, b1) asm volatile( \
    "mma.sync.aligned.m16n8k16.row.col.f32.bf16.bf16.f32 " \
    "{%0,%1,%2,%3}, {%4,%5,%6,%7}, {%8,%9}, {%0,%1,%2,%3};" \
    : "+f"((acc)[0]), "+f"((acc)[1]), "+f"((acc)[2]), "+f"((acc)[3]) \
    : "r"((a).x), "r"((a).y), "r"((a).z), "r"((a).w), "r"(b0), "r"(b1))

#define LDSM4(r0, r1, r2, r3, addr) asm volatile( \
    "ldmatrix.sync.aligned.m8n8.x4.shared.b16 {%0,%1,%2,%3}, [%4];" \
    : "=r"(r0), "=r"(r1), "=r"(r2), "=r"(r3) : "r"(addr))

__device__ __forceinline__ void relu_split(float x, float y, uint32_t& h, uint32_t& l) {
    x = fmaxf(x, 0.f); y = fmaxf(y, 0.f);
    __nv_bfloat162 hb = __float22bfloat162_rn(make_float2(x, y));
    float2 hf = __bfloat1622float2(hb);
    __nv_bfloat162 lb = __float22bfloat162_rn(make_float2(x - hf.x, y - hf.y));
    h = *reinterpret_cast<uint32_t*>(&hb);
    l = *reinterpret_cast<uint32_t*>(&lb);
}
__device__ __forceinline__ void plain_split(float x, float y, uint32_t& h, uint32_t& l) {
    __nv_bfloat162 hb = __float22bfloat162_rn(make_float2(x, y));
    float2 hf = __bfloat1622float2(hb);
    __nv_bfloat162 lb = __float22bfloat162_rn(make_float2(x - hf.x, y - hf.y));
    h = *reinterpret_cast<uint32_t*>(&hb);
    l = *reinterpret_cast<uint32_t*>(&lb);
}
__device__ __forceinline__ void ffma2s(float2& d, float a, float2 b) {
    unsigned long long dd = *reinterpret_cast<unsigned long long*>(&d);
    float2 av = make_float2(a, a);
    unsigned long long aa = *reinterpret_cast<unsigned long long*>(&av);
    unsigned long long bb = *reinterpret_cast<unsigned long long*>(&b);
    asm("fma.rn.f32x2 %0, %1, %2, %0;" : "+l"(dd) : "l"(aa), "l"(bb));
    d = *reinterpret_cast<float2*>(&dd);
}

// ===================== side kernel 1: cst3 ===================================
__global__ void cst3_kernel(const float* __restrict__ gpv, const float* __restrict__ gpr,
                            const float* __restrict__ pW, const float* __restrict__ pb,
                            const float* __restrict__ aW1, const float* __restrict__ ab1)
{
    __shared__ float pe[32];
    const int t = threadIdx.x;
    const float p0 = gpv[0] / gpr[0], p1 = gpv[1] / gpr[1];
    if (t < 32) pe[t] = fmaxf(pb[t] + p0 * pW[t] + p1 * pW[32 + t], 0.f);
    __syncthreads();
    for (int idx = t; idx < V_ * 256; idx += blockDim.x) {
        const int v = idx >> 8, c = idx & 255;
        const float* W = aW1 + ((size_t)v * 448 + 416) * 256 + c;
        float s = ab1[v * 256 + c];
#pragma unroll
        for (int k = 0; k < 32; k++) s += pe[k] * W[(size_t)k * 256];
        g_cst3[v][c] = s;
    }
}

// ===================== side kernel 2: weight convert =========================
// chunk rows n_local, 128B/row; swizzle byte = n_local*128 + ((2kl)^((n_local&7)<<4))
// INTERLEAVED placement: d = 2*kk + (hi ? 0 : 1)
__global__ void wconv_kernel(const float* __restrict__ bW2,
                             const float* __restrict__ aW1,
                             const float* __restrict__ aW2)
{
    constexpr int PERV = 131072 + 131072 + 65536 + 98304;   // 425984
    const int total = V_ * PERV;
    for (int idx = blockIdx.x * blockDim.x + threadIdx.x; idx < total;
         idx += gridDim.x * blockDim.x) {
        const int v = idx / PERV;
        int e = idx % PERV;
        size_t dst;
        int n_local, kl;
        bool hiC;
        float w;
        if (e < 131072) {                       // L2
            const int wg = e >> 16, r = e & 65535;
            const int c = r >> 13, rr = r & 8191;
            n_local = rr >> 6; kl = rr & 63;
            const int kk = c & 3;
            hiC = (c < 4);
            const int n = wg * 128 + n_local, k = kk * 64 + kl;
            w = bW2[((size_t)v * 256 + k) * 256 + n];
            const int d = 2 * kk + (hiC ? 0 : 1);
            dst = (size_t)wg * 8 * CB + (size_t)d * CB;
        } else if (e < 262144) {                // L3
            e -= 131072;
            const int wg = e >> 16, r = e & 65535;
            const int c = r >> 13, rr = r & 8191;
            n_local = rr >> 6; kl = rr & 63;
            const int kk = c & 3;
            hiC = (c < 4);
            const int n = wg * 128 + n_local, k = kk * 64 + kl;
            w = aW1[((size_t)v * 448 + k) * 256 + n];
            const int d = 2 * kk + (hiC ? 0 : 1);
            dst = L3OFF + (size_t)wg * 8 * CB + (size_t)d * CB;
        } else if (e < 327680) {                // L4
            e -= 262144;
            const int wg = e >> 15, r = e & 32767;
            const int c = r >> 12, rr = r & 4095;
            n_local = rr >> 6; kl = rr & 63;
            const int kk = c & 3;
            hiC = (c < 4);
            const int n = wg * 64 + n_local, k = kk * 64 + kl;
            w = aW2[((size_t)v * 256 + k) * 128 + n];
            const int d = 2 * kk + (hiC ? 0 : 1);
            dst = L4OFF + (size_t)wg * 8 * CB4 + (size_t)d * CB4;
        } else {                                // CTX (K padded 160->192)
            e -= 327680;
            const int wg2 = e / 49152, r2 = e % 49152;
            const int c = r2 >> 13, rr = r2 & 8191;
            n_local = rr >> 6; kl = rr & 63;
            const int kk = c % 3;
            hiC = (c < 3);
            const int n = wg2 * 128 + n_local, k = kk * 64 + kl;
            w = (k < 160) ? aW1[((size_t)v * 448 + 256 + k) * 256 + n] : 0.f;
            const int d = 2 * kk + (hiC ? 0 : 1);
            dst = CTXOFF + (size_t)wg2 * 6 * CB + (size_t)d * CB;
        }
        __nv_bfloat16 hi = __float2bfloat16_rn(w);
        __nv_bfloat16 val = hiC ? hi : __float2bfloat16_rn(w - __bfloat162float(hi));
        uint8_t* p = g_wB + (size_t)v * VSTRIDE + dst
                   + n_local * 128 + (((uint32_t)(kl * 2)) ^ (((uint32_t)n_local & 7) << 4));
        *reinterpret_cast<__nv_bfloat16*>(p) = val;
    }
}

// ===================== per-wg prefetch + mainloop ============================
template <int CBT>
__device__ __forceinline__ void prefetch_wg(uint8_t* sb, const uint8_t* wsrc,
                                            int tw, int wg) {
    constexpr int NCP = CBT / 16 / 256;
    uint8_t* w0 = sb + OFF_W + wg * 32768;
#pragma unroll
    for (int i = 0; i < NCP; i++)
        cp16(w0 + (tw + i * 256) * 16, wsrc + (size_t)(tw + i * 256) * 16);
    CP_COMMIT();
#pragma unroll
    for (int i = 0; i < NCP; i++)
        cp16(w0 + CBT + (tw + i * 256) * 16, wsrc + CBT + (size_t)(tw + i * 256) * 16);
    CP_COMMIT();
}

// requires prefetch_wg<CBT>(wsrc) already issued (2 groups pending).
// INTERLEAVED decode: hiB = !(c&1), fkb = (c>>1)*4.
template <int NCHUNK, int NFRAG, int CBT>
__device__ __forceinline__ void mma_loop_wg(
    uint8_t* sb, const uint8_t* wsrc, int tw, int wg, int lane,
    int aslot0, int nbase, float (*acc)[4])
{
    uint8_t* w0 = sb + OFF_W + wg * 32768;
    const uint4* AHI = (const uint4*)(sb + OFF_AHI);
    const uint4* ALO = (const uint4*)(sb + OFF_ALO);
    const uint32_t swzc = ((uint32_t)lane & 7) << 4;
    const int kadd = ((lane >> 3) & 1) * 8;
    constexpr int NCP = CBT / 16 / 256;
#pragma unroll 1
    for (int c = 0; c < NCHUNK; c++) {
        if (c < NCHUNK - 1) CP_WAIT1(); else CP_WAIT0();
        BARW(wg);
        const uint32_t wb = su32(w0 + (c & 1) * CBT);
        const bool hiB = !(c & 1);          // interleaved: h,l,h,l,...
        const int fkb = (c >> 1) * 4;
#pragma unroll
        for (int s = 0; s < 4; s++) {
            const int fk = fkb + s;
            const uint4 ah = AHI[(aslot0 + fk) * 32 + lane];
            uint4 al = make_uint4(0, 0, 0, 0);
            if (hiB) al = ALO[(aslot0 + fk) * 32 + lane];
            const int koff = s * 16 + kadd;
            const uint32_t ba = wb + (uint32_t)(nbase * 128)
                              + (((uint32_t)(koff * 2)) ^ swzc);
#pragma unroll
            for (int jj = 0; jj < NFRAG / 2; jj++) {
                uint32_t b0, b1, b2, b3;
                LDSM4(b0, b1, b2, b3, ba + jj * 2048);
                MMA_BF16(acc[2 * jj],     ah, b0, b1);
                MMA_BF16(acc[2 * jj + 1], ah, b2, b3);
                if (hiB) {
                    MMA_BF16(acc[2 * jj],     al, b0, b1);
                    MMA_BF16(acc[2 * jj + 1], al, b2, b3);
                }
            }
        }
        BARW(wg);
        if (c + 2 < NCHUNK) {
#pragma unroll
            for (int i = 0; i < NCP; i++)
                cp16(w0 + (c & 1) * CBT + (tw + i * 256) * 16,
                     wsrc + (size_t)(c + 2) * CBT + (size_t)(tw + i * 256) * 16);
            CP_COMMIT();
        }
    }
}

// ===================== epilogue: C frags -> A frags =========================
// wn here = warpgroup id (column half). MODE 0: bias; MODE 1: per-node ctxp.
template <int MODE>
__device__ __forceinline__ void epiA(
    uint8_t* sbH, float (*acc)[4], const float* __restrict__ addv,
    int wm, int wn, int lane)
{
    uint4* AHI = (uint4*)(sbH + OFF_AHI);
    uint4* ALO = (uint4*)(sbH + OFF_ALO);
    const int quad = lane >> 2, q4 = lane & 3;
    const int r0 = 16 * wm + quad;
    int n0 = r0 / 7;       if (n0 > 17) n0 = 17;
    int n1 = (r0 + 8) / 7; if (n1 > 17) n1 = 17;
#pragma unroll
    for (int u = 0; u < 8; u++) {
        const int c0 = wn * 128 + 16 * u + 2 * q4;
        const int c2 = c0 + 8;
        float2 a00, a01, a10, a11;
        if constexpr (MODE == 0) {
            a00 = *(const float2*)(addv + c0);
            a01 = *(const float2*)(addv + c2);
            a10 = a00; a11 = a01;
        } else {
            a00 = *(const float2*)(addv + n0 * 260 + c0);
            a01 = *(const float2*)(addv + n0 * 260 + c2);
            a10 = *(const float2*)(addv + n1 * 260 + c0);
            a11 = *(const float2*)(addv + n1 * 260 + c2);
        }
        uint32_t h0, l0, h1, l1, h2, l2, h3, l3;
        relu_split(acc[2*u][0]   + a00.x, acc[2*u][1]   + a00.y, h0, l0);
        relu_split(acc[2*u][2]   + a10.x, acc[2*u][3]   + a10.y, h1, l1);
        relu_split(acc[2*u+1][0] + a01.x, acc[2*u+1][1] + a01.y, h2, l2);
        relu_split(acc[2*u+1][2] + a11.x, acc[2*u+1][3] + a11.y, h3, l3);
        const int fi = (wm * 16 + 8 * wn + u) * 32 + lane;
        AHI[fi] = make_uint4(h0, h1, h2, h3);
        ALO[fi] = make_uint4(l0, l1, l2, l3);
    }
}

// ============================ main kernel ====================================
__global__ void __launch_bounds__(NT, 1)
surface_kernel(
    const float* __restrict__ centers,  const float* __restrict__ enc_g,
    const float* __restrict__ enc_node, const float* __restrict__ neighbors,
    const float* __restrict__ normals,  const float* __restrict__ neigh_normals,
    const float* __restrict__ areas,    const float* __restrict__ neigh_areas,
    const float* __restrict__ basis_W1, const float* __restrict__ basis_b1,
    const float* __restrict__ basis_b2, const float* __restrict__ agg_b2,
    const float* __restrict__ agg_W3,   const float* __restrict__ agg_b3,
    float* __restrict__ out, const int n_nodes)
{
    extern __shared__ uint8_t sb[];
    const int t = threadIdx.x;
    const int wid = t >> 5, lane = t & 31;
    const int wg = t >> 8;             // warpgroup 0/1 == column half
    const int tw = t & 255;            // thread index within wg
    const int widg = wid & 7;          // warp within wg == wm
    const int quad = lane >> 2, q4 = lane & 3;
    const int base = blockIdx.x * NPC;

    float* ctxps = (float*)(sb + OFF_CTXP);
    float* svol  = (float*)(sb + OFF_SVOL);
    float* W1s   = (float*)(sb + OFF_W1S);
    float* b1s   = (float*)(sb + OFF_B1S);
    float* b2s   = (float*)(sb + OFF_B2S);
    float* b4s   = (float*)(sb + OFF_B4S);
    float* w3s   = (float*)(sb + OFF_W3S);
    float* arowp = (float*)(sb + OFF_ARP);
    float* arow  = (float*)(sb + OFF_ARW);
    float* invd  = (float*)(sb + OFF_INVD);
    float* dsum  = (float*)(sb + OFF_DSUM);

    // prefetch v=0 ctx chunks (per wg stream)
    prefetch_wg<CB>(sb, g_wB + CTXOFF + (size_t)wg * 6 * CB, tw, wg);

    // ---- build vol rows ----
    if (t < 128) {
        float f[8] = {0.f,0.f,0.f,0.f,0.f,0.f,0.f,0.f};
        const int nl = t / PP, p = t % PP;
        const int node = base + nl;
        if (t < ROWS_ && node < n_nodes) {
            if (p == 0) {
                f[0]=centers[node*3+0]; f[1]=centers[node*3+1]; f[2]=centers[node*3+2];
                f[3]=normals[node*3+0]; f[4]=normals[node*3+1]; f[5]=normals[node*3+2];
                f[6]=logf(areas[node]) * 0.1f;
            } else {
                const int nb = node * NK + (p - 1);
                f[0]=neighbors[nb*3+0]+1e-6f; f[1]=neighbors[nb*3+1]+1e-6f;
                f[2]=neighbors[nb*3+2]+1e-6f;
                f[3]=neigh_normals[nb*3+0]+1e-6f; f[4]=neigh_normals[nb*3+1]+1e-6f;
                f[5]=neigh_normals[nb*3+2]+1e-6f;
                f[6]=logf(neigh_areas[nb]) * 0.1f + 1e-6f;
            }
        }
#pragma unroll
        for (int q = 0; q < 8; q++) svol[t * 8 + q] = f[q];
    }
    __syncthreads();
    if (t < NPC * NK) {
        const int nl = t / NK, j = t % NK;
        float d2 = 0.f;
#pragma unroll
        for (int q = 0; q < 7; q++) {
            const float d = svol[(nl*7)*8 + q] - svol[(nl*7 + 1 + j)*8 + q];
            d2 += d * d;
        }
        invd[nl * 8 + j] = 1.f / sqrtf(d2);
    }
    __syncthreads();
    if (t < NPC) {
        float s = 0.f;
#pragma unroll
        for (int j = 0; j < NK; j++) s += invd[t * 8 + j];
        dsum[t] = s;
    }

    const int r0m = 16 * widg + quad;
    float sv0[7], sv1[7];
#pragma unroll
    for (int q = 0; q < 7; q++) {
        sv0[q] = svol[r0m * 8 + q];
        sv1[q] = svol[(r0m + 8) * 8 + q];
    }

#pragma unroll 1
    for (int v = 0; v < V_; v++) {
        const uint8_t* wv = g_wB + (size_t)v * VSTRIDE;
        // per-v constants
        for (int i = t; i < 1792; i += NT) W1s[i] = __ldg(basis_W1 + (size_t)v * 1792 + i);
        if (t < 256) { b1s[t] = __ldg(basis_b1 + v * 256 + t);
                       b2s[t] = __ldg(basis_b2 + v * 256 + t); }
        else if (t < 384) { b4s[t-256] = __ldg(agg_b2 + v * 128 + (t-256)); }
        else { w3s[t-384] = __ldg(agg_W3 + v * 128 + (t-384)); }

        // ---- build ctx A frags (full CTA; M=32, K padded to 192) ----
        {
            uint4* AHI = (uint4*)(sb + OFF_AHI);
            uint4* ALO = (uint4*)(sb + OFF_ALO);
#pragma unroll
            for (int rep = 0; rep < 2; rep++) {
                const int slot = wid + rep * 16;
                if (slot < 24) {
                    const int fm = slot / 12, fk = slot % 12;
                    const int rr0 = fm * 16 + quad, rr1 = rr0 + 8;
                    const int cc0 = fk * 16 + 2 * q4, cc1 = cc0 + 8;
                    float2 vv[4];
                    const int rs[2] = {rr0, rr1};
                    const int cs[2] = {cc0, cc1};
#pragma unroll
                    for (int a = 0; a < 4; a++) {
                        const int r = rs[a & 1], cc = cs[a >> 1];
                        const int node = base + r;
                        float2 val = make_float2(0.f, 0.f);
                        if (r < NPC && node < n_nodes && cc < 160) {
                            if (cc < 32) val = *(const float2*)(enc_node + (size_t)node*32 + cc);
                            else         val = *(const float2*)(enc_g + (size_t)node*128 + (cc-32));
                        }
                        vv[a] = val;
                    }
                    uint32_t h[4], l[4];
#pragma unroll
                    for (int a = 0; a < 4; a++) plain_split(vv[a].x, vv[a].y, h[a], l[a]);
                    AHI[slot * 32 + lane] = make_uint4(h[0], h[1], h[2], h[3]);
                    ALO[slot * 32 + lane] = make_uint4(l[0], l[1], l[2], l[3]);
                }
            }
        }
        __syncthreads();

        // ---- ctx GEMM: ctxps[18][wg cols] = ctx @ Wctx + cst3 ----
        {
            const int cwm = widg & 1, cwn = widg >> 1;     // 2m x 4n within wg
            float cacc[4][4];
#pragma unroll
            for (int i = 0; i < 4; i++)
#pragma unroll
                for (int j = 0; j < 4; j++) cacc[i][j] = 0.f;
            const int cnbase = cwn * 32 + 8 * ((lane >> 4) & 1) + (lane & 7);
            mma_loop_wg<6, 4, CB>(sb, wv + CTXOFF + (size_t)wg * 6 * CB,
                                  tw, wg, lane, cwm * 12, cnbase, cacc);
            prefetch_wg<CB>(sb, wv + (size_t)wg * 8 * CB, tw, wg);   // L2 chunks
            // ctx epilogue (cols disjoint per wg; read later by same wg only)
            const int rr0 = cwm * 16 + quad;
            const float* cstv = g_cst3[v];
#pragma unroll
            for (int jj = 0; jj < 2; jj++)
#pragma unroll
                for (int e = 0; e < 2; e++) {
                    const int col = wg * 128 + cwn * 32 + jj * 16 + e * 8 + 2 * q4;
                    const float2 cst = *(const float2*)(cstv + col);
                    const float* a = cacc[2 * jj + e];
                    if (rr0 < NPC && base + rr0 < n_nodes)
                        *(float2*)(ctxps + rr0 * 260 + col) =
                            make_float2(a[0] + cst.x, a[1] + cst.y);
                    if (rr0 + 8 < NPC && base + rr0 + 8 < n_nodes)
                        *(float2*)(ctxps + (rr0 + 8) * 260 + col) =
                            make_float2(a[2] + cst.x, a[3] + cst.y);
                }
        }
        __syncthreads();   // ctx A slots free; L1 overwrites them

        // ---- L1: produce A frags directly (overlaps L2 weight copies) ----
        {
            uint4* AHI = (uint4*)(sb + OFF_AHI);
            uint4* ALO = (uint4*)(sb + OFF_ALO);
#pragma unroll
            for (int u = 0; u < 8; u++) {
                const int c0 = wg * 128 + 16 * u + 2 * q4;
                const int c2 = c0 + 8;
                float2 a00 = *(const float2*)(b1s + c0);
                float2 a01 = *(const float2*)(b1s + c2);
                float2 a10 = a00, a11 = a01;
#pragma unroll
                for (int q = 0; q < 7; q++) {
                    const float2 w0 = *(const float2*)(W1s + q * 256 + c0);
                    const float2 w2 = *(const float2*)(W1s + q * 256 + c2);
                    ffma2s(a00, sv0[q], w0); ffma2s(a01, sv0[q], w2);
                    ffma2s(a10, sv1[q], w0); ffma2s(a11, sv1[q], w2);
                }
                uint32_t h0, l0, h1, l1, h2, l2, h3, l3;
                relu_split(a00.x, a00.y, h0, l0);
                relu_split(a10.x, a10.y, h1, l1);
                relu_split(a01.x, a01.y, h2, l2);
                relu_split(a11.x, a11.y, h3, l3);
                const int fi = (widg * 16 + 8 * wg + u) * 32 + lane;
                AHI[fi] = make_uint4(h0, h1, h2, h3);
                ALO[fi] = make_uint4(l0, l1, l2, l3);
            }
        }
        __syncthreads();

        const int nbase = 8 * ((lane >> 4) & 1) + (lane & 7);
        // ---- L2 ----
        {
            float acc[16][4];
#pragma unroll
            for (int i = 0; i < 16; i++)
#pragma unroll
                for (int j = 0; j < 4; j++) acc[i][j] = 0.f;
            mma_loop_wg<8, 16, CB>(sb, wv + (size_t)wg * 8 * CB,
                                   tw, wg, lane, widg * 16, nbase, acc);
            prefetch_wg<CB>(sb, wv + L3OFF + (size_t)wg * 8 * CB, tw, wg);
            __syncthreads();   // both wgs done reading L2 A-frags
            epiA<0>(sb, acc, b2s, widg, wg, lane);
        }
        __syncthreads();
        // ---- L3 ----
        {
            float acc[16][4];
#pragma unroll
            for (int i = 0; i < 16; i++)
#pragma unroll
                for (int j = 0; j < 4; j++) acc[i][j] = 0.f;
            mma_loop_wg<8, 16, CB>(sb, wv + L3OFF + (size_t)wg * 8 * CB,
                                   tw, wg, lane, widg * 16, nbase, acc);
            prefetch_wg<CB4>(sb, wv + L4OFF + (size_t)wg * 8 * CB4, tw, wg);
            __syncthreads();
            epiA<1>(sb, acc, ctxps, widg, wg, lane);
        }
        __syncthreads();
        // ---- L4 + L5 ----
        {
            float acc[8][4];
#pragma unroll
            for (int i = 0; i < 8; i++)
#pragma unroll
                for (int j = 0; j < 4; j++) acc[i][j] = 0.f;
            mma_loop_wg<8, 8, CB4>(sb, wv + L4OFF + (size_t)wg * 8 * CB4,
                                   tw, wg, lane, widg * 16, nbase, acc);
            if (v + 1 < V_)
                prefetch_wg<CB>(sb, wv + VSTRIDE + CTXOFF + (size_t)wg * 6 * CB, tw, wg);
            float s0 = 0.f, s1 = 0.f;
#pragma unroll
            for (int j = 0; j < 8; j++) {
                const int c0 = wg * 64 + 8 * j + 2 * q4;
                const float w30 = w3s[c0], w31 = w3s[c0 + 1];
                const float bb0 = b4s[c0], bb1 = b4s[c0 + 1];
                s0 += fmaxf(acc[j][0] + bb0, 0.f) * w30 + fmaxf(acc[j][1] + bb1, 0.f) * w31;
                s1 += fmaxf(acc[j][2] + bb0, 0.f) * w30 + fmaxf(acc[j][3] + bb1, 0.f) * w31;
            }
            s0 += __shfl_xor_sync(0xffffffffu, s0, 1);
            s0 += __shfl_xor_sync(0xffffffffu, s0, 2);
            s1 += __shfl_xor_sync(0xffffffffu, s1, 1);
            s1 += __shfl_xor_sync(0xffffffffu, s1, 2);
            if (q4 == 0) {
                arowp[wg * 128 + r0m] = s0;
                arowp[wg * 128 + r0m + 8] = s1;
            }
        }
        __syncthreads();
        if (t < 128) arow[t] = arowp[t] + arowp[128 + t] + __ldg(agg_b3 + v);
        __syncthreads();
        if (t < NPC) {
            const int node = base + t;
            if (node < n_nodes) {
                const float c = arow[t * 7];
                float s = 0.f;
#pragma unroll
                for (int j = 0; j < NK; j++) s += arow[t * 7 + 1 + j] * invd[t * 8 + j];
                out[node * V_ + v] = 0.5f * c + 0.5f * s / dsum[t];
            }
        }
        __syncthreads();
    }
}

// ============================ launcher =======================================
extern "C" void kernel_launch(void* const* d_in, const int* in_sizes, int n_in,
                              void* d_out, int out_size)
{
    const float* centers       = (const float*)d_in[0];
    const float* enc_g         = (const float*)d_in[1];
    const float* enc_node      = (const float*)d_in[2];
    const float* neighbors     = (const float*)d_in[3];
    const float* normals       = (const float*)d_in[4];
    const float* neigh_normals = (const float*)d_in[5];
    const float* areas         = (const float*)d_in[6];
    const float* neigh_areas   = (const float*)d_in[7];
    const float* gpv           = (const float*)d_in[8];
    const float* gpr           = (const float*)d_in[9];
    const float* param_W       = (const float*)d_in[10];
    const float* param_b       = (const float*)d_in[11];
    const float* basis_W1      = (const float*)d_in[12];
    const float* basis_b1      = (const float*)d_in[13];
    const float* basis_W2      = (const float*)d_in[14];
    const float* basis_b2      = (const float*)d_in[15];
    const float* agg_W1        = (const float*)d_in[16];
    const float* agg_b1        = (const float*)d_in[17];
    const float* agg_W2        = (const float*)d_in[18];
    const float* agg_b2        = (const float*)d_in[19];
    const float* agg_W3        = (const float*)d_in[20];
    const float* agg_b3        = (const float*)d_in[21];
    float* out = (float*)d_out;

    const int n_nodes = in_sizes[0] / 3;
    const int grid = (n_nodes + NPC - 1) / NPC;

    cudaFuncSetAttribute(surface_kernel,
                         cudaFuncAttributeMaxDynamicSharedMemorySize, SMEM_BYTES);

    cst3_kernel<<<1, 256>>>(gpv, gpr, param_W, param_b, agg_W1, agg_b1);
    wconv_kernel<<<2560, 512>>>(basis_W2, agg_W1, agg_W2);
    surface_kernel<<<grid, NT, SMEM_BYTES>>>(
        centers, enc_g, enc_node, neighbors, normals, neigh_normals,
        areas, neigh_areas,
        basis_W1, basis_b1, basis_b2, agg_b2, agg_W3, agg_b3, out, n_nodes);
}

// round 13
// speedup vs baseline: 3.9611x; 1.0085x over previous
#include <cuda_runtime.h>
#include <cuda_bf16.h>
#include <math.h>
#include <stdint.h>

constexpr int V_ = 4;
constexpr int NK = 6;
constexpr int PP = 7;
constexpr int NPC = 18;
constexpr int ROWS_ = 126;
constexpr int NT = 512;

// weight blob per v, per-warpgroup streams of [128n][64k] (16KB) chunks.
// Big layers interleaved h0,l0,h1,l1,...  L4: 4 merged 16KB chunks
// (each = two 8KB [64n][64k] sub-blocks), order hK0,lK0,hK1,lK1.
constexpr int CB  = 16384;
constexpr int CB4 = 8192;
constexpr int L3OFF  = 16 * CB;               // 262144
constexpr int L4OFF  = L3OFF + 16 * CB;       // 524288
constexpr int CTXOFF = L4OFF + 16 * CB4;      // 655360
constexpr int VSTRIDE = CTXOFF + 12 * CB;     // 851968

__device__ uint8_t g_wB[(size_t)V_ * VSTRIDE];
__device__ float   g_cst3[V_][256];

// ---- smem byte offsets ----
constexpr int OFF_W    = 0;        // 65536: wg0 [0,32K), wg1 [32K,64K)
constexpr int OFF_AHI  = 65536;    // 65536 (A hi frags: 128 slots x 512B)
constexpr int OFF_ALO  = 131072;   // 65536
constexpr int OFF_CTXP = 196608;   // 18*260*4 = 18720
constexpr int OFF_SVOL = 215328;   // 4096
constexpr int OFF_W1S  = 219424;   // 7168
constexpr int OFF_B1S  = 226592;   // 1024
constexpr int OFF_B2S  = 227616;   // 1024
constexpr int OFF_B4S  = 228640;   // 512
constexpr int OFF_W3S  = 229152;   // 512
constexpr int OFF_ARP  = 229664;   // 1024
constexpr int OFF_ARW  = 230688;   // 512
constexpr int OFF_INVD = 231200;   // 576
constexpr int OFF_DSUM = 231776;   // 96
constexpr int SMEM_BYTES = 231872;

// ============================ PTX helpers ====================================
__device__ __forceinline__ uint32_t su32(const void* p) {
    return (uint32_t)__cvta_generic_to_shared(p);
}
__device__ __forceinline__ void cp16(uint8_t* s, const uint8_t* g) {
    uint32_t sa = su32(s);
    asm volatile("cp.async.cg.shared.global [%0], [%1], 16;" :: "r"(sa), "l"(g));
}
#define CP_COMMIT() asm volatile("cp.async.commit_group;" ::: "memory")
#define CP_WAIT1()  asm volatile("cp.async.wait_group 1;" ::: "memory")
#define CP_WAIT0()  asm volatile("cp.async.wait_group 0;" ::: "memory")
// per-warpgroup named barrier (ids 1,2), 256 threads each
#define BARW(g) asm volatile("bar.sync %0, %1;" :: "r"((g) + 1), "r"(256) : "memory")

#define MMA_BF16(acc, a, b0, b1) asm volatile( \
    "mma.sync.aligned.m16n8k16.row.col.f32.bf16.bf16.f32 " \
    "{%0,%1,%2,%3}, {%4,%5,%6,%7}, {%8,%9}, {%0,%1,%2,%3};" \
    : "+f"((acc)[0]), "+f"((acc)[1]), "+f"((acc)[2]), "+f"((acc)[3]) \
    : "r"((a).x), "r"((a).y), "r"((a).z), "r"((a).w), "r"(b0), "r"(b1))

#define LDSM4(r0, r1, r2, r3, addr) asm volatile( \
    "ldmatrix.sync.aligned.m8n8.x4.shared.b16 {%0,%1,%2,%3}, [%4];" \
    : "=r"(r0), "=r"(r1), "=r"(r2), "=r"(r3) : "r"(addr))

__device__ __forceinline__ void relu_split(float x, float y, uint32_t& h, uint32_t& l) {
    x = fmaxf(x, 0.f); y = fmaxf(y, 0.f);
    __nv_bfloat162 hb = __float22bfloat162_rn(make_float2(x, y));
    float2 hf = __bfloat1622float2(hb);
    __nv_bfloat162 lb = __float22bfloat162_rn(make_float2(x - hf.x, y - hf.y));
    h = *reinterpret_cast<uint32_t*>(&hb);
    l = *reinterpret_cast<uint32_t*>(&lb);
}
__device__ __forceinline__ void plain_split(float x, float y, uint32_t& h, uint32_t& l) {
    __nv_bfloat162 hb = __float22bfloat162_rn(make_float2(x, y));
    float2 hf = __bfloat1622float2(hb);
    __nv_bfloat162 lb = __float22bfloat162_rn(make_float2(x - hf.x, y - hf.y));
    h = *reinterpret_cast<uint32_t*>(&hb);
    l = *reinterpret_cast<uint32_t*>(&lb);
}
__device__ __forceinline__ void ffma2s(float2& d, float a, float2 b) {
    unsigned long long dd = *reinterpret_cast<unsigned long long*>(&d);
    float2 av = make_float2(a, a);
    unsigned long long aa = *reinterpret_cast<unsigned long long*>(&av);
    unsigned long long bb = *reinterpret_cast<unsigned long long*>(&b);
    asm("fma.rn.f32x2 %0, %1, %2, %0;" : "+l"(dd) : "l"(aa), "l"(bb));
    d = *reinterpret_cast<float2*>(&dd);
}

// ===================== side kernel 1: cst3 (one block per v) =================
__global__ void cst3_kernel(const float* __restrict__ gpv, const float* __restrict__ gpr,
                            const float* __restrict__ pW, const float* __restrict__ pb,
                            const float* __restrict__ aW1, const float* __restrict__ ab1)
{
    __shared__ float pe[32];
    const int t = threadIdx.x;
    const int v = blockIdx.x;
    const float p0 = gpv[0] / gpr[0], p1 = gpv[1] / gpr[1];
    if (t < 32) pe[t] = fmaxf(pb[t] + p0 * pW[t] + p1 * pW[32 + t], 0.f);
    __syncthreads();
    const int c = t;
    const float* W = aW1 + ((size_t)v * 448 + 416) * 256 + c;
    float s = ab1[v * 256 + c];
#pragma unroll
    for (int k = 0; k < 32; k++) s += pe[k] * W[(size_t)k * 256];
    g_cst3[v][c] = s;
}

// ===================== side kernel 2: weight convert =========================
// chunk rows n_local, 128B/row; swizzle byte = n_local*128 + ((2kl)^((n_local&7)<<4))
// Big layers: d = 2*kk + (hi?0:1). L4 merged: d = 2*(kk>>1)+(hi?0:1), sub = kk&1.
__global__ void wconv_kernel(const float* __restrict__ bW2,
                             const float* __restrict__ aW1,
                             const float* __restrict__ aW2)
{
    constexpr int PERV = 131072 + 131072 + 65536 + 98304;   // 425984
    const int total = V_ * PERV;
    for (int idx = blockIdx.x * blockDim.x + threadIdx.x; idx < total;
         idx += gridDim.x * blockDim.x) {
        const int v = idx / PERV;
        int e = idx % PERV;
        size_t dst;
        int n_local, kl;
        bool hiC;
        float w;
        if (e < 131072) {                       // L2
            const int wg = e >> 16, r = e & 65535;
            const int c = r >> 13, rr = r & 8191;
            n_local = rr >> 6; kl = rr & 63;
            const int kk = c & 3;
            hiC = (c < 4);
            const int n = wg * 128 + n_local, k = kk * 64 + kl;
            w = bW2[((size_t)v * 256 + k) * 256 + n];
            const int d = 2 * kk + (hiC ? 0 : 1);
            dst = (size_t)wg * 8 * CB + (size_t)d * CB;
        } else if (e < 262144) {                // L3
            e -= 131072;
            const int wg = e >> 16, r = e & 65535;
            const int c = r >> 13, rr = r & 8191;
            n_local = rr >> 6; kl = rr & 63;
            const int kk = c & 3;
            hiC = (c < 4);
            const int n = wg * 128 + n_local, k = kk * 64 + kl;
            w = aW1[((size_t)v * 448 + k) * 256 + n];
            const int d = 2 * kk + (hiC ? 0 : 1);
            dst = L3OFF + (size_t)wg * 8 * CB + (size_t)d * CB;
        } else if (e < 327680) {                // L4 (merged 16KB chunks)
            e -= 262144;
            const int wg = e >> 15, r = e & 32767;
            const int c = r >> 12, rr = r & 4095;
            n_local = rr >> 6; kl = rr & 63;
            const int kk = c & 3;
            hiC = (c < 4);
            const int n = wg * 64 + n_local, k = kk * 64 + kl;
            w = aW2[((size_t)v * 256 + k) * 128 + n];
            const int d = 2 * (kk >> 1) + (hiC ? 0 : 1);
            const int sub = kk & 1;
            dst = L4OFF + (size_t)wg * 8 * CB4 + (size_t)d * CB + (size_t)sub * CB4;
        } else {                                // CTX (K padded 160->192)
            e -= 327680;
            const int wg2 = e / 49152, r2 = e % 49152;
            const int c = r2 >> 13, rr = r2 & 8191;
            n_local = rr >> 6; kl = rr & 63;
            const int kk = c % 3;
            hiC = (c < 3);
            const int n = wg2 * 128 + n_local, k = kk * 64 + kl;
            w = (k < 160) ? aW1[((size_t)v * 448 + 256 + k) * 256 + n] : 0.f;
            const int d = 2 * kk + (hiC ? 0 : 1);
            dst = CTXOFF + (size_t)wg2 * 6 * CB + (size_t)d * CB;
        }
        __nv_bfloat16 hi = __float2bfloat16_rn(w);
        __nv_bfloat16 val = hiC ? hi : __float2bfloat16_rn(w - __bfloat162float(hi));
        uint8_t* p = g_wB + (size_t)v * VSTRIDE + dst
                   + n_local * 128 + (((uint32_t)(kl * 2)) ^ (((uint32_t)n_local & 7) << 4));
        *reinterpret_cast<__nv_bfloat16*>(p) = val;
    }
}

// ===================== per-wg prefetch + mainloop ============================
template <int CBT>
__device__ __forceinline__ void prefetch_wg(uint8_t* sb, const uint8_t* wsrc,
                                            int tw, int wg) {
    constexpr int NCP = CBT / 16 / 256;
    uint8_t* w0 = sb + OFF_W + wg * 32768;
#pragma unroll
    for (int i = 0; i < NCP; i++)
        cp16(w0 + (tw + i * 256) * 16, wsrc + (size_t)(tw + i * 256) * 16);
    CP_COMMIT();
#pragma unroll
    for (int i = 0; i < NCP; i++)
        cp16(w0 + CBT + (tw + i * 256) * 16, wsrc + CBT + (size_t)(tw + i * 256) * 16);
    CP_COMMIT();
}

// requires prefetch_wg<CBT>(wsrc) already issued (2 groups pending).
// INTERLEAVED decode: hiB = !(c&1), fkb = (c>>1)*4.
// TRIM: ctx K pad — chunk pair (c>>1)==2 has only 2 real k-frags.
template <int NCHUNK, int NFRAG, int CBT, bool TRIM = false>
__device__ __forceinline__ void mma_loop_wg(
    uint8_t* sb, const uint8_t* wsrc, int tw, int wg, int lane,
    int aslot0, int nbase, float (*acc)[4])
{
    uint8_t* w0 = sb + OFF_W + wg * 32768;
    const uint4* AHI = (const uint4*)(sb + OFF_AHI);
    const uint4* ALO = (const uint4*)(sb + OFF_ALO);
    const uint32_t swzc = ((uint32_t)lane & 7) << 4;
    const int kadd = ((lane >> 3) & 1) * 8;
    constexpr int NCP = CBT / 16 / 256;
#pragma unroll 1
    for (int c = 0; c < NCHUNK; c++) {
        if (c < NCHUNK - 1) CP_WAIT1(); else CP_WAIT0();
        BARW(wg);
        const uint32_t wb = su32(w0 + (c & 1) * CBT);
        const bool hiB = !(c & 1);          // interleaved: h,l,h,l,...
        const int fkb = (c >> 1) * 4;
        const int scnt = (TRIM && (c >> 1) == 2) ? 2 : 4;
#pragma unroll
        for (int s = 0; s < 4; s++) {
            if (s < scnt) {
                const int fk = fkb + s;
                const uint4 ah = AHI[(aslot0 + fk) * 32 + lane];
                uint4 al = make_uint4(0, 0, 0, 0);
                if (hiB) al = ALO[(aslot0 + fk) * 32 + lane];
                const int koff = s * 16 + kadd;
                const uint32_t ba = wb + (uint32_t)(nbase * 128)
                                  + (((uint32_t)(koff * 2)) ^ swzc);
#pragma unroll
                for (int jj = 0; jj < NFRAG / 2; jj++) {
                    uint32_t b0, b1, b2, b3;
                    LDSM4(b0, b1, b2, b3, ba + jj * 2048);
                    MMA_BF16(acc[2 * jj],     ah, b0, b1);
                    MMA_BF16(acc[2 * jj + 1], ah, b2, b3);
                    if (hiB) {
                        MMA_BF16(acc[2 * jj],     al, b0, b1);
                        MMA_BF16(acc[2 * jj + 1], al, b2, b3);
                    }
                }
            }
        }
        BARW(wg);
        if (c + 2 < NCHUNK) {
#pragma unroll
            for (int i = 0; i < NCP; i++)
                cp16(w0 + (c & 1) * CBT + (tw + i * 256) * 16,
                     wsrc + (size_t)(c + 2) * CBT + (size_t)(tw + i * 256) * 16);
            CP_COMMIT();
        }
    }
}

// L4 merged mainloop: 4 chunks of 16KB, each = two 8KB [64n][64k] sub-blocks.
__device__ __forceinline__ void mma_loop_l4(
    uint8_t* sb, const uint8_t* wsrc, int tw, int wg, int lane,
    int aslot0, int nbase, float (*acc)[4])
{
    uint8_t* w0 = sb + OFF_W + wg * 32768;
    const uint4* AHI = (const uint4*)(sb + OFF_AHI);
    const uint4* ALO = (const uint4*)(sb + OFF_ALO);
    const uint32_t swzc = ((uint32_t)lane & 7) << 4;
    const int kadd = ((lane >> 3) & 1) * 8;
#pragma unroll 1
    for (int c = 0; c < 4; c++) {
        if (c < 3) CP_WAIT1(); else CP_WAIT0();
        BARW(wg);
        const uint32_t wb = su32(w0 + (c & 1) * CB);
        const bool hiB = !(c & 1);
        const int fkb = (c >> 1) * 8;
#pragma unroll
        for (int s = 0; s < 8; s++) {
            const int fk = fkb + s;
            const uint4 ah = AHI[(aslot0 + fk) * 32 + lane];
            uint4 al = make_uint4(0, 0, 0, 0);
            if (hiB) al = ALO[(aslot0 + fk) * 32 + lane];
            const int koff = (s & 3) * 16 + kadd;
            const uint32_t ba = wb + (uint32_t)((s >> 2) * 8192)
                              + (uint32_t)(nbase * 128)
                              + (((uint32_t)(koff * 2)) ^ swzc);
#pragma unroll
            for (int jj = 0; jj < 4; jj++) {
                uint32_t b0, b1, b2, b3;
                LDSM4(b0, b1, b2, b3, ba + jj * 2048);
                MMA_BF16(acc[2 * jj],     ah, b0, b1);
                MMA_BF16(acc[2 * jj + 1], ah, b2, b3);
                if (hiB) {
                    MMA_BF16(acc[2 * jj],     al, b0, b1);
                    MMA_BF16(acc[2 * jj + 1], al, b2, b3);
                }
            }
        }
        BARW(wg);
        if (c + 2 < 4) {
#pragma unroll
            for (int i = 0; i < 4; i++)
                cp16(w0 + (c & 1) * CB + (tw + i * 256) * 16,
                     wsrc + (size_t)(c + 2) * CB + (size_t)(tw + i * 256) * 16);
            CP_COMMIT();
        }
    }
}

// ===================== epilogue: C frags -> A frags =========================
// wn here = warpgroup id (column half). MODE 0: bias; MODE 1: per-node ctxp.
template <int MODE>
__device__ __forceinline__ void epiA(
    uint8_t* sbH, float (*acc)[4], const float* __restrict__ addv,
    int wm, int wn, int lane)
{
    uint4* AHI = (uint4*)(sbH + OFF_AHI);
    uint4* ALO = (uint4*)(sbH + OFF_ALO);
    const int quad = lane >> 2, q4 = lane & 3;
    const int r0 = 16 * wm + quad;
    int n0 = r0 / 7;       if (n0 > 17) n0 = 17;
    int n1 = (r0 + 8) / 7; if (n1 > 17) n1 = 17;
#pragma unroll
    for (int u = 0; u < 8; u++) {
        const int c0 = wn * 128 + 16 * u + 2 * q4;
        const int c2 = c0 + 8;
        float2 a00, a01, a10, a11;
        if constexpr (MODE == 0) {
            a00 = *(const float2*)(addv + c0);
            a01 = *(const float2*)(addv + c2);
            a10 = a00; a11 = a01;
        } else {
            a00 = *(const float2*)(addv + n0 * 260 + c0);
            a01 = *(const float2*)(addv + n0 * 260 + c2);
            a10 = *(const float2*)(addv + n1 * 260 + c0);
            a11 = *(const float2*)(addv + n1 * 260 + c2);
        }
        uint32_t h0, l0, h1, l1, h2, l2, h3, l3;
        relu_split(acc[2*u][0]   + a00.x, acc[2*u][1]   + a00.y, h0, l0);
        relu_split(acc[2*u][2]   + a10.x, acc[2*u][3]   + a10.y, h1, l1);
        relu_split(acc[2*u+1][0] + a01.x, acc[2*u+1][1] + a01.y, h2, l2);
        relu_split(acc[2*u+1][2] + a11.x, acc[2*u+1][3] + a11.y, h3, l3);
        const int fi = (wm * 16 + 8 * wn + u) * 32 + lane;
        AHI[fi] = make_uint4(h0, h1, h2, h3);
        ALO[fi] = make_uint4(l0, l1, l2, l3);
    }
}

// ============================ main kernel ====================================
__global__ void __launch_bounds__(NT, 1)
surface_kernel(
    const float* __restrict__ centers,  const float* __restrict__ enc_g,
    const float* __restrict__ enc_node, const float* __restrict__ neighbors,
    const float* __restrict__ normals,  const float* __restrict__ neigh_normals,
    const float* __restrict__ areas,    const float* __restrict__ neigh_areas,
    const float* __restrict__ basis_W1, const float* __restrict__ basis_b1,
    const float* __restrict__ basis_b2, const float* __restrict__ agg_b2,
    const float* __restrict__ agg_W3,   const float* __restrict__ agg_b3,
    float* __restrict__ out, const int n_nodes)
{
    extern __shared__ uint8_t sb[];
    const int t = threadIdx.x;
    const int wid = t >> 5, lane = t & 31;
    const int wg = t >> 8;             // warpgroup 0/1 == column half
    const int tw = t & 255;            // thread index within wg
    const int widg = wid & 7;          // warp within wg == wm
    const int quad = lane >> 2, q4 = lane & 3;
    const int base = blockIdx.x * NPC;

    float* ctxps = (float*)(sb + OFF_CTXP);
    float* svol  = (float*)(sb + OFF_SVOL);
    float* W1s   = (float*)(sb + OFF_W1S);
    float* b1s   = (float*)(sb + OFF_B1S);
    float* b2s   = (float*)(sb + OFF_B2S);
    float* b4s   = (float*)(sb + OFF_B4S);
    float* w3s   = (float*)(sb + OFF_W3S);
    float* arowp = (float*)(sb + OFF_ARP);
    float* arow  = (float*)(sb + OFF_ARW);
    float* invd  = (float*)(sb + OFF_INVD);
    float* dsum  = (float*)(sb + OFF_DSUM);

    // prefetch v=0 ctx chunks (per wg stream)
    prefetch_wg<CB>(sb, g_wB + CTXOFF + (size_t)wg * 6 * CB, tw, wg);

    // ---- build vol rows ----
    if (t < 128) {
        float f[8] = {0.f,0.f,0.f,0.f,0.f,0.f,0.f,0.f};
        const int nl = t / PP, p = t % PP;
        const int node = base + nl;
        if (t < ROWS_ && node < n_nodes) {
            if (p == 0) {
                f[0]=centers[node*3+0]; f[1]=centers[node*3+1]; f[2]=centers[node*3+2];
                f[3]=normals[node*3+0]; f[4]=normals[node*3+1]; f[5]=normals[node*3+2];
                f[6]=logf(areas[node]) * 0.1f;
            } else {
                const int nb = node * NK + (p - 1);
                f[0]=neighbors[nb*3+0]+1e-6f; f[1]=neighbors[nb*3+1]+1e-6f;
                f[2]=neighbors[nb*3+2]+1e-6f;
                f[3]=neigh_normals[nb*3+0]+1e-6f; f[4]=neigh_normals[nb*3+1]+1e-6f;
                f[5]=neigh_normals[nb*3+2]+1e-6f;
                f[6]=logf(neigh_areas[nb]) * 0.1f + 1e-6f;
            }
        }
#pragma unroll
        for (int q = 0; q < 8; q++) svol[t * 8 + q] = f[q];
    }
    __syncthreads();
    if (t < NPC * NK) {
        const int nl = t / NK, j = t % NK;
        float d2 = 0.f;
#pragma unroll
        for (int q = 0; q < 7; q++) {
            const float d = svol[(nl*7)*8 + q] - svol[(nl*7 + 1 + j)*8 + q];
            d2 += d * d;
        }
        invd[nl * 8 + j] = 1.f / sqrtf(d2);
    }
    __syncthreads();
    if (t < NPC) {
        float s = 0.f;
#pragma unroll
        for (int j = 0; j < NK; j++) s += invd[t * 8 + j];
        dsum[t] = s;
    }

    const int r0m = 16 * widg + quad;
    float sv0[7], sv1[7];
#pragma unroll
    for (int q = 0; q < 7; q++) {
        sv0[q] = svol[r0m * 8 + q];
        sv1[q] = svol[(r0m + 8) * 8 + q];
    }

#pragma unroll 1
    for (int v = 0; v < V_; v++) {
        const uint8_t* wv = g_wB + (size_t)v * VSTRIDE;
        // per-v constants
        for (int i = t; i < 1792; i += NT) W1s[i] = __ldg(basis_W1 + (size_t)v * 1792 + i);
        if (t < 256) { b1s[t] = __ldg(basis_b1 + v * 256 + t);
                       b2s[t] = __ldg(basis_b2 + v * 256 + t); }
        else if (t < 384) { b4s[t-256] = __ldg(agg_b2 + v * 128 + (t-256)); }
        else { w3s[t-384] = __ldg(agg_W3 + v * 128 + (t-384)); }

        // ---- build ctx A frags (full CTA; M=32, K padded to 192) ----
        {
            uint4* AHI = (uint4*)(sb + OFF_AHI);
            uint4* ALO = (uint4*)(sb + OFF_ALO);
#pragma unroll
            for (int rep = 0; rep < 2; rep++) {
                const int slot = wid + rep * 16;
                if (slot < 24) {
                    const int fm = slot / 12, fk = slot % 12;
                    const int rr0 = fm * 16 + quad, rr1 = rr0 + 8;
                    const int cc0 = fk * 16 + 2 * q4, cc1 = cc0 + 8;
                    float2 vv[4];
                    const int rs[2] = {rr0, rr1};
                    const int cs[2] = {cc0, cc1};
#pragma unroll
                    for (int a = 0; a < 4; a++) {
                        const int r = rs[a & 1], cc = cs[a >> 1];
                        const int node = base + r;
                        float2 val = make_float2(0.f, 0.f);
                        if (r < NPC && node < n_nodes && cc < 160) {
                            if (cc < 32) val = *(const float2*)(enc_node + (size_t)node*32 + cc);
                            else         val = *(const float2*)(enc_g + (size_t)node*128 + (cc-32));
                        }
                        vv[a] = val;
                    }
                    uint32_t h[4], l[4];
#pragma unroll
                    for (int a = 0; a < 4; a++) plain_split(vv[a].x, vv[a].y, h[a], l[a]);
                    AHI[slot * 32 + lane] = make_uint4(h[0], h[1], h[2], h[3]);
                    ALO[slot * 32 + lane] = make_uint4(l[0], l[1], l[2], l[3]);
                }
            }
        }
        __syncthreads();

        // ---- ctx GEMM: ctxps[18][wg cols] = ctx @ Wctx + cst3 ----
        {
            const int cwm = widg & 1, cwn = widg >> 1;     // 2m x 4n within wg
            float cacc[4][4];
#pragma unroll
            for (int i = 0; i < 4; i++)
#pragma unroll
                for (int j = 0; j < 4; j++) cacc[i][j] = 0.f;
            const int cnbase = cwn * 32 + 8 * ((lane >> 4) & 1) + (lane & 7);
            mma_loop_wg<6, 4, CB, true>(sb, wv + CTXOFF + (size_t)wg * 6 * CB,
                                        tw, wg, lane, cwm * 12, cnbase, cacc);
            prefetch_wg<CB>(sb, wv + (size_t)wg * 8 * CB, tw, wg);   // L2 chunks
            // ctx epilogue (cols disjoint per wg; read later by same wg only)
            const int rr0 = cwm * 16 + quad;
            const float* cstv = g_cst3[v];
#pragma unroll
            for (int jj = 0; jj < 2; jj++)
#pragma unroll
                for (int e = 0; e < 2; e++) {
                    const int col = wg * 128 + cwn * 32 + jj * 16 + e * 8 + 2 * q4;
                    const float2 cst = *(const float2*)(cstv + col);
                    const float* a = cacc[2 * jj + e];
                    if (rr0 < NPC && base + rr0 < n_nodes)
                        *(float2*)(ctxps + rr0 * 260 + col) =
                            make_float2(a[0] + cst.x, a[1] + cst.y);
                    if (rr0 + 8 < NPC && base + rr0 + 8 < n_nodes)
                        *(float2*)(ctxps + (rr0 + 8) * 260 + col) =
                            make_float2(a[2] + cst.x, a[3] + cst.y);
                }
        }
        __syncthreads();   // ctx A slots free; L1 overwrites them

        // ---- L1: produce A frags directly (overlaps L2 weight copies) ----
        {
            uint4* AHI = (uint4*)(sb + OFF_AHI);
            uint4* ALO = (uint4*)(sb + OFF_ALO);
#pragma unroll
            for (int u = 0; u < 8; u++) {
                const int c0 = wg * 128 + 16 * u + 2 * q4;
                const int c2 = c0 + 8;
                float2 a00 = *(const float2*)(b1s + c0);
                float2 a01 = *(const float2*)(b1s + c2);
                float2 a10 = a00, a11 = a01;
#pragma unroll
                for (int q = 0; q < 7; q++) {
                    const float2 w0 = *(const float2*)(W1s + q * 256 + c0);
                    const float2 w2 = *(const float2*)(W1s + q * 256 + c2);
                    ffma2s(a00, sv0[q], w0); ffma2s(a01, sv0[q], w2);
                    ffma2s(a10, sv1[q], w0); ffma2s(a11, sv1[q], w2);
                }
                uint32_t h0, l0, h1, l1, h2, l2, h3, l3;
                relu_split(a00.x, a00.y, h0, l0);
                relu_split(a10.x, a10.y, h1, l1);
                relu_split(a01.x, a01.y, h2, l2);
                relu_split(a11.x, a11.y, h3, l3);
                const int fi = (widg * 16 + 8 * wg + u) * 32 + lane;
                AHI[fi] = make_uint4(h0, h1, h2, h3);
                ALO[fi] = make_uint4(l0, l1, l2, l3);
            }
        }
        __syncthreads();

        const int nbase = 8 * ((lane >> 4) & 1) + (lane & 7);
        // ---- L2 ----
        {
            float acc[16][4];
#pragma unroll
            for (int i = 0; i < 16; i++)
#pragma unroll
                for (int j = 0; j < 4; j++) acc[i][j] = 0.f;
            mma_loop_wg<8, 16, CB>(sb, wv + (size_t)wg * 8 * CB,
                                   tw, wg, lane, widg * 16, nbase, acc);
            prefetch_wg<CB>(sb, wv + L3OFF + (size_t)wg * 8 * CB, tw, wg);
            __syncthreads();   // both wgs done reading L2 A-frags
            epiA<0>(sb, acc, b2s, widg, wg, lane);
        }
        __syncthreads();
        // ---- L3 ----
        {
            float acc[16][4];
#pragma unroll
            for (int i = 0; i < 16; i++)
#pragma unroll
                for (int j = 0; j < 4; j++) acc[i][j] = 0.f;
            mma_loop_wg<8, 16, CB>(sb, wv + L3OFF + (size_t)wg * 8 * CB,
                                   tw, wg, lane, widg * 16, nbase, acc);
            prefetch_wg<CB>(sb, wv + L4OFF + (size_t)wg * 8 * CB4, tw, wg);
            __syncthreads();
            epiA<1>(sb, acc, ctxps, widg, wg, lane);
        }
        __syncthreads();
        // ---- L4 + L5 ----
        {
            float acc[8][4];
#pragma unroll
            for (int i = 0; i < 8; i++)
#pragma unroll
                for (int j = 0; j < 4; j++) acc[i][j] = 0.f;
            mma_loop_l4(sb, wv + L4OFF + (size_t)wg * 8 * CB4,
                        tw, wg, lane, widg * 16, nbase, acc);
            if (v + 1 < V_)
                prefetch_wg<CB>(sb, wv + VSTRIDE + CTXOFF + (size_t)wg * 6 * CB, tw, wg);
            float s0 = 0.f, s1 = 0.f;
#pragma unroll
            for (int j = 0; j < 8; j++) {
                const int c0 = wg * 64 + 8 * j + 2 * q4;
                const float w30 = w3s[c0], w31 = w3s[c0 + 1];
                const float bb0 = b4s[c0], bb1 = b4s[c0 + 1];
                s0 += fmaxf(acc[j][0] + bb0, 0.f) * w30 + fmaxf(acc[j][1] + bb1, 0.f) * w31;
                s1 += fmaxf(acc[j][2] + bb0, 0.f) * w30 + fmaxf(acc[j][3] + bb1, 0.f) * w31;
            }
            s0 += __shfl_xor_sync(0xffffffffu, s0, 1);
            s0 += __shfl_xor_sync(0xffffffffu, s0, 2);
            s1 += __shfl_xor_sync(0xffffffffu, s1, 1);
            s1 += __shfl_xor_sync(0xffffffffu, s1, 2);
            if (q4 == 0) {
                arowp[wg * 128 + r0m] = s0;
                arowp[wg * 128 + r0m + 8] = s1;
            }
        }
        __syncthreads();
        if (t < 128) arow[t] = arowp[t] + arowp[128 + t] + __ldg(agg_b3 + v);
        __syncthreads();
        if (t < NPC) {
            const int node = base + t;
            if (node < n_nodes) {
                const float c = arow[t * 7];
                float s = 0.f;
#pragma unroll
                for (int j = 0; j < NK; j++) s += arow[t * 7 + 1 + j] * invd[t * 8 + j];
                out[node * V_ + v] = 0.5f * c + 0.5f * s / dsum[t];
            }
        }
        __syncthreads();
    }
}

// ============================ launcher =======================================
extern "C" void kernel_launch(void* const* d_in, const int* in_sizes, int n_in,
                              void* d_out, int out_size)
{
    const float* centers       = (const float*)d_in[0];
    const float* enc_g         = (const float*)d_in[1];
    const float* enc_node      = (const float*)d_in[2];
    const float* neighbors     = (const float*)d_in[3];
    const float* normals       = (const float*)d_in[4];
    const float* neigh_normals = (const float*)d_in[5];
    const float* areas         = (const float*)d_in[6];
    const float* neigh_areas   = (const float*)d_in[7];
    const float* gpv           = (const float*)d_in[8];
    const float* gpr           = (const float*)d_in[9];
    const float* param_W       = (const float*)d_in[10];
    const float* param_b       = (const float*)d_in[11];
    const float* basis_W1      = (const float*)d_in[12];
    const float* basis_b1      = (const float*)d_in[13];
    const float* basis_W2      = (const float*)d_in[14];
    const float* basis_b2      = (const float*)d_in[15];
    const float* agg_W1        = (const float*)d_in[16];
    const float* agg_b1        = (const float*)d_in[17];
    const float* agg_W2        = (const float*)d_in[18];
    const float* agg_b2        = (const float*)d_in[19];
    const float* agg_W3        = (const float*)d_in[20];
    const float* agg_b3        = (const float*)d_in[21];
    float* out = (float*)d_out;

    const int n_nodes = in_sizes[0] / 3;
    const int grid = (n_nodes + NPC - 1) / NPC;

    cudaFuncSetAttribute(surface_kernel,
                         cudaFuncAttributeMaxDynamicSharedMemorySize, SMEM_BYTES);

    cst3_kernel<<<V_, 256>>>(gpv, gpr, param_W, param_b, agg_W1, agg_b1);
    wconv_kernel<<<2560, 512>>>(basis_W2, agg_W1, agg_W2);
    surface_kernel<<<grid, NT, SMEM_BYTES>>>(
        centers, enc_g, enc_node, neighbors, normals, neigh_normals,
        areas, neigh_areas,
        basis_W1, basis_b1, basis_b2, agg_b2, agg_W3, agg_b3, out, n_nodes);
}

// round 14
// speedup vs baseline: 6.7414x; 1.7019x over previous
#include <cuda_runtime.h>
#include <cuda_fp16.h>
#include <math.h>
#include <stdint.h>

constexpr int V_ = 4;
constexpr int NK = 6;
constexpr int PP = 7;
constexpr int NPC = 18;
constexpr int ROWS_ = 126;
constexpr int NT = 512;

// weight blob per v, per-warpgroup streams of fp16 [128n][64k] (16KB) chunks.
// 2-pass split: B stored hi-only. Per wg: L2 4 chunks, L3 4, L4 2 (merged,
// each two 8KB [64n][64k] subs), CTX 3 (K padded 160->192, chunk2 half-real).
constexpr int CB  = 16384;
constexpr int CB4 = 8192;
constexpr int WGS   = 13 * CB;       // per-wg stream: 212992
constexpr int L3o   = 4 * CB;
constexpr int L4o   = 8 * CB;
constexpr int CTXo  = 10 * CB;
constexpr int VSTRIDE = 2 * WGS;     // 425984

__device__ uint8_t g_wB[(size_t)V_ * VSTRIDE];
__device__ float   g_cst3[V_][256];

// ---- smem byte offsets ----
constexpr int OFF_W    = 0;        // 65536: wg0 [0,32K), wg1 [32K,64K)
constexpr int OFF_AHI  = 65536;    // 65536 (A hi frags: 128 slots x 512B)
constexpr int OFF_ALO  = 131072;   // 65536
constexpr int OFF_CTXP = 196608;   // 18*260*4 = 18720
constexpr int OFF_SVOL = 215328;   // 4096
constexpr int OFF_W1S  = 219424;   // 7168
constexpr int OFF_B1S  = 226592;   // 1024
constexpr int OFF_B2S  = 227616;   // 1024
constexpr int OFF_B4S  = 228640;   // 512
constexpr int OFF_W3S  = 229152;   // 512
constexpr int OFF_ARP  = 229664;   // 1024
constexpr int OFF_ARW  = 230688;   // 512
constexpr int OFF_INVD = 231200;   // 576
constexpr int OFF_DSUM = 231776;   // 96
constexpr int SMEM_BYTES = 231872;

// ============================ PTX helpers ====================================
__device__ __forceinline__ uint32_t su32(const void* p) {
    return (uint32_t)__cvta_generic_to_shared(p);
}
__device__ __forceinline__ void cp16(uint8_t* s, const uint8_t* g) {
    uint32_t sa = su32(s);
    asm volatile("cp.async.cg.shared.global [%0], [%1], 16;" :: "r"(sa), "l"(g));
}
#define CP_COMMIT() asm volatile("cp.async.commit_group;" ::: "memory")
#define CP_WAIT1()  asm volatile("cp.async.wait_group 1;" ::: "memory")
#define CP_WAIT0()  asm volatile("cp.async.wait_group 0;" ::: "memory")
// per-warpgroup named barrier (ids 1,2), 256 threads each
#define BARW(g) asm volatile("bar.sync %0, %1;" :: "r"((g) + 1), "r"(256) : "memory")

#define MMA_F16(acc, a, b0, b1) asm volatile( \
    "mma.sync.aligned.m16n8k16.row.col.f32.f16.f16.f32 " \
    "{%0,%1,%2,%3}, {%4,%5,%6,%7}, {%8,%9}, {%0,%1,%2,%3};" \
    : "+f"((acc)[0]), "+f"((acc)[1]), "+f"((acc)[2]), "+f"((acc)[3]) \
    : "r"((a).x), "r"((a).y), "r"((a).z), "r"((a).w), "r"(b0), "r"(b1))

#define LDSM4(r0, r1, r2, r3, addr) asm volatile( \
    "ldmatrix.sync.aligned.m8n8.x4.shared.b16 {%0,%1,%2,%3}, [%4];" \
    : "=r"(r0), "=r"(r1), "=r"(r2), "=r"(r3) : "r"(addr))

__device__ __forceinline__ void relu_split(float x, float y, uint32_t& h, uint32_t& l) {
    x = fmaxf(x, 0.f); y = fmaxf(y, 0.f);
    __half2 hh = __floats2half2_rn(x, y);
    float2 hf = __half22float2(hh);
    __half2 ll = __floats2half2_rn(x - hf.x, y - hf.y);
    h = *reinterpret_cast<uint32_t*>(&hh);
    l = *reinterpret_cast<uint32_t*>(&ll);
}
__device__ __forceinline__ void plain_split(float x, float y, uint32_t& h, uint32_t& l) {
    __half2 hh = __floats2half2_rn(x, y);
    float2 hf = __half22float2(hh);
    __half2 ll = __floats2half2_rn(x - hf.x, y - hf.y);
    h = *reinterpret_cast<uint32_t*>(&hh);
    l = *reinterpret_cast<uint32_t*>(&ll);
}
__device__ __forceinline__ void ffma2s(float2& d, float a, float2 b) {
    unsigned long long dd = *reinterpret_cast<unsigned long long*>(&d);
    float2 av = make_float2(a, a);
    unsigned long long aa = *reinterpret_cast<unsigned long long*>(&av);
    unsigned long long bb = *reinterpret_cast<unsigned long long*>(&b);
    asm("fma.rn.f32x2 %0, %1, %2, %0;" : "+l"(dd) : "l"(aa), "l"(bb));
    d = *reinterpret_cast<float2*>(&dd);
}

// ===================== side kernel 1: cst3 (one block per v) =================
__global__ void cst3_kernel(const float* __restrict__ gpv, const float* __restrict__ gpr,
                            const float* __restrict__ pW, const float* __restrict__ pb,
                            const float* __restrict__ aW1, const float* __restrict__ ab1)
{
    __shared__ float pe[32];
    const int t = threadIdx.x;
    const int v = blockIdx.x;
    const float p0 = gpv[0] / gpr[0], p1 = gpv[1] / gpr[1];
    if (t < 32) pe[t] = fmaxf(pb[t] + p0 * pW[t] + p1 * pW[32 + t], 0.f);
    __syncthreads();
    const int c = t;
    const float* W = aW1 + ((size_t)v * 448 + 416) * 256 + c;
    float s = ab1[v * 256 + c];
#pragma unroll
    for (int k = 0; k < 32; k++) s += pe[k] * W[(size_t)k * 256];
    g_cst3[v][c] = s;
}

// ===================== side kernel 2: weight convert (fp16 hi-only) ==========
// chunk rows n_local, 128B/row; swizzle byte = n_local*128 + ((2kl)^((n_local&7)<<4))
__global__ void wconv_kernel(const float* __restrict__ bW2,
                             const float* __restrict__ aW1,
                             const float* __restrict__ aW2)
{
    constexpr int PERV = 65536 + 65536 + 32768 + 49152;   // 212992 elements
    const int total = V_ * PERV;
    for (int idx = blockIdx.x * blockDim.x + threadIdx.x; idx < total;
         idx += gridDim.x * blockDim.x) {
        const int v = idx / PERV;
        int e = idx % PERV;
        size_t dst;
        int n_local, kl;
        float w;
        if (e < 65536) {                        // L2: 2wg x 4 chunks
            const int wg = e >> 15, r = e & 32767;
            const int c = r >> 13, rr = r & 8191;
            n_local = rr >> 6; kl = rr & 63;
            const int n = wg * 128 + n_local, k = c * 64 + kl;
            w = bW2[((size_t)v * 256 + k) * 256 + n];
            dst = (size_t)wg * WGS + (size_t)c * CB;
        } else if (e < 131072) {                // L3
            e -= 65536;
            const int wg = e >> 15, r = e & 32767;
            const int c = r >> 13, rr = r & 8191;
            n_local = rr >> 6; kl = rr & 63;
            const int n = wg * 128 + n_local, k = c * 64 + kl;
            w = aW1[((size_t)v * 448 + k) * 256 + n];
            dst = (size_t)wg * WGS + L3o + (size_t)c * CB;
        } else if (e < 163840) {                // L4: 2wg x 2 merged chunks
            e -= 131072;
            const int wg = e >> 14, r = e & 16383;
            const int kk = r >> 12, rr = r & 4095;
            n_local = rr >> 6; kl = rr & 63;
            const int n = wg * 64 + n_local, k = kk * 64 + kl;
            w = aW2[((size_t)v * 256 + k) * 128 + n];
            dst = (size_t)wg * WGS + L4o + (size_t)(kk >> 1) * CB + (size_t)(kk & 1) * CB4;
        } else {                                // CTX: 2wg x 3 chunks (K pad 192)
            e -= 163840;
            const int wg = e / 24576, r = e % 24576;
            const int c = r >> 13, rr = r & 8191;
            n_local = rr >> 6; kl = rr & 63;
            const int n = wg * 128 + n_local, k = c * 64 + kl;
            w = (k < 160) ? aW1[((size_t)v * 448 + 256 + k) * 256 + n] : 0.f;
            dst = (size_t)wg * WGS + CTXo + (size_t)c * CB;
        }
        __half val = __float2half_rn(w);
        uint8_t* p = g_wB + (size_t)v * VSTRIDE + dst
                   + n_local * 128 + (((uint32_t)(kl * 2)) ^ (((uint32_t)n_local & 7) << 4));
        *reinterpret_cast<__half*>(p) = val;
    }
}

// ===================== per-wg prefetch + mainloop ============================
template <int CBT>
__device__ __forceinline__ void prefetch_wg(uint8_t* sb, const uint8_t* wsrc,
                                            int tw, int wg) {
    constexpr int NCP = CBT / 16 / 256;
    uint8_t* w0 = sb + OFF_W + wg * 32768;
#pragma unroll
    for (int i = 0; i < NCP; i++)
        cp16(w0 + (tw + i * 256) * 16, wsrc + (size_t)(tw + i * 256) * 16);
    CP_COMMIT();
#pragma unroll
    for (int i = 0; i < NCP; i++)
        cp16(w0 + CBT + (tw + i * 256) * 16, wsrc + CBT + (size_t)(tw + i * 256) * 16);
    CP_COMMIT();
}

// requires prefetch_wg<CBT>(wsrc) already issued (2 groups pending).
// 2-pass fp16: every chunk runs ah*B and al*B. fkb = c*4.
// TRIM: ctx K pad — chunk 2 has only 2 real k-frags.
template <int NCHUNK, int NFRAG, int CBT, bool TRIM = false>
__device__ __forceinline__ void mma_loop_wg(
    uint8_t* sb, const uint8_t* wsrc, int tw, int wg, int lane,
    int aslot0, int nbase, float (*acc)[4])
{
    uint8_t* w0 = sb + OFF_W + wg * 32768;
    const uint4* AHI = (const uint4*)(sb + OFF_AHI);
    const uint4* ALO = (const uint4*)(sb + OFF_ALO);
    const uint32_t swzc = ((uint32_t)lane & 7) << 4;
    const int kadd = ((lane >> 3) & 1) * 8;
    constexpr int NCP = CBT / 16 / 256;
#pragma unroll 1
    for (int c = 0; c < NCHUNK; c++) {
        if (c < NCHUNK - 1) CP_WAIT1(); else CP_WAIT0();
        BARW(wg);
        const uint32_t wb = su32(w0 + (c & 1) * CBT);
        const int fkb = c * 4;
        const int scnt = (TRIM && c == 2) ? 2 : 4;
#pragma unroll
        for (int s = 0; s < 4; s++) {
            if (s < scnt) {
                const int fk = fkb + s;
                const uint4 ah = AHI[(aslot0 + fk) * 32 + lane];
                const uint4 al = ALO[(aslot0 + fk) * 32 + lane];
                const int koff = s * 16 + kadd;
                const uint32_t ba = wb + (uint32_t)(nbase * 128)
                                  + (((uint32_t)(koff * 2)) ^ swzc);
#pragma unroll
                for (int jj = 0; jj < NFRAG / 2; jj++) {
                    uint32_t b0, b1, b2, b3;
                    LDSM4(b0, b1, b2, b3, ba + jj * 2048);
                    MMA_F16(acc[2 * jj],     ah, b0, b1);
                    MMA_F16(acc[2 * jj + 1], ah, b2, b3);
                    MMA_F16(acc[2 * jj],     al, b0, b1);
                    MMA_F16(acc[2 * jj + 1], al, b2, b3);
                }
            }
        }
        BARW(wg);
        if (c + 2 < NCHUNK) {
#pragma unroll
            for (int i = 0; i < NCP; i++)
                cp16(w0 + (c & 1) * CBT + (tw + i * 256) * 16,
                     wsrc + (size_t)(c + 2) * CBT + (size_t)(tw + i * 256) * 16);
            CP_COMMIT();
        }
    }
}

// L4 merged mainloop: 2 chunks of 16KB, each = two 8KB [64n][64k] sub-blocks.
__device__ __forceinline__ void mma_loop_l4(
    uint8_t* sb, const uint8_t* wsrc, int tw, int wg, int lane,
    int aslot0, int nbase, float (*acc)[4])
{
    uint8_t* w0 = sb + OFF_W + wg * 32768;
    const uint4* AHI = (const uint4*)(sb + OFF_AHI);
    const uint4* ALO = (const uint4*)(sb + OFF_ALO);
    const uint32_t swzc = ((uint32_t)lane & 7) << 4;
    const int kadd = ((lane >> 3) & 1) * 8;
#pragma unroll 1
    for (int c = 0; c < 2; c++) {
        if (c < 1) CP_WAIT1(); else CP_WAIT0();
        BARW(wg);
        const uint32_t wb = su32(w0 + (c & 1) * CB);
        const int fkb = c * 8;
#pragma unroll
        for (int s = 0; s < 8; s++) {
            const int fk = fkb + s;
            const uint4 ah = AHI[(aslot0 + fk) * 32 + lane];
            const uint4 al = ALO[(aslot0 + fk) * 32 + lane];
            const int koff = (s & 3) * 16 + kadd;
            const uint32_t ba = wb + (uint32_t)((s >> 2) * 8192)
                              + (uint32_t)(nbase * 128)
                              + (((uint32_t)(koff * 2)) ^ swzc);
#pragma unroll
            for (int jj = 0; jj < 4; jj++) {
                uint32_t b0, b1, b2, b3;
                LDSM4(b0, b1, b2, b3, ba + jj * 2048);
                MMA_F16(acc[2 * jj],     ah, b0, b1);
                MMA_F16(acc[2 * jj + 1], ah, b2, b3);
                MMA_F16(acc[2 * jj],     al, b0, b1);
                MMA_F16(acc[2 * jj + 1], al, b2, b3);
            }
        }
        BARW(wg);
    }
}

// ===================== epilogue: C frags -> A frags =========================
// wn here = warpgroup id (column half). MODE 0: bias; MODE 1: per-node ctxp.
template <int MODE>
__device__ __forceinline__ void epiA(
    uint8_t* sbH, float (*acc)[4], const float* __restrict__ addv,
    int wm, int wn, int lane)
{
    uint4* AHI = (uint4*)(sbH + OFF_AHI);
    uint4* ALO = (uint4*)(sbH + OFF_ALO);
    const int quad = lane >> 2, q4 = lane & 3;
    const int r0 = 16 * wm + quad;
    int n0 = r0 / 7;       if (n0 > 17) n0 = 17;
    int n1 = (r0 + 8) / 7; if (n1 > 17) n1 = 17;
#pragma unroll
    for (int u = 0; u < 8; u++) {
        const int c0 = wn * 128 + 16 * u + 2 * q4;
        const int c2 = c0 + 8;
        float2 a00, a01, a10, a11;
        if constexpr (MODE == 0) {
            a00 = *(const float2*)(addv + c0);
            a01 = *(const float2*)(addv + c2);
            a10 = a00; a11 = a01;
        } else {
            a00 = *(const float2*)(addv + n0 * 260 + c0);
            a01 = *(const float2*)(addv + n0 * 260 + c2);
            a10 = *(const float2*)(addv + n1 * 260 + c0);
            a11 = *(const float2*)(addv + n1 * 260 + c2);
        }
        uint32_t h0, l0, h1, l1, h2, l2, h3, l3;
        relu_split(acc[2*u][0]   + a00.x, acc[2*u][1]   + a00.y, h0, l0);
        relu_split(acc[2*u][2]   + a10.x, acc[2*u][3]   + a10.y, h1, l1);
        relu_split(acc[2*u+1][0] + a01.x, acc[2*u+1][1] + a01.y, h2, l2);
        relu_split(acc[2*u+1][2] + a11.x, acc[2*u+1][3] + a11.y, h3, l3);
        const int fi = (wm * 16 + 8 * wn + u) * 32 + lane;
        AHI[fi] = make_uint4(h0, h1, h2, h3);
        ALO[fi] = make_uint4(l0, l1, l2, l3);
    }
}

// ============================ main kernel ====================================
__global__ void __launch_bounds__(NT, 1)
surface_kernel(
    const float* __restrict__ centers,  const float* __restrict__ enc_g,
    const float* __restrict__ enc_node, const float* __restrict__ neighbors,
    const float* __restrict__ normals,  const float* __restrict__ neigh_normals,
    const float* __restrict__ areas,    const float* __restrict__ neigh_areas,
    const float* __restrict__ basis_W1, const float* __restrict__ basis_b1,
    const float* __restrict__ basis_b2, const float* __restrict__ agg_b2,
    const float* __restrict__ agg_W3,   const float* __restrict__ agg_b3,
    float* __restrict__ out, const int n_nodes)
{
    extern __shared__ uint8_t sb[];
    const int t = threadIdx.x;
    const int wid = t >> 5, lane = t & 31;
    const int wg = t >> 8;             // warpgroup 0/1 == column half
    const int tw = t & 255;            // thread index within wg
    const int widg = wid & 7;          // warp within wg == wm
    const int quad = lane >> 2, q4 = lane & 3;
    const int base = blockIdx.x * NPC;

    float* ctxps = (float*)(sb + OFF_CTXP);
    float* svol  = (float*)(sb + OFF_SVOL);
    float* W1s   = (float*)(sb + OFF_W1S);
    float* b1s   = (float*)(sb + OFF_B1S);
    float* b2s   = (float*)(sb + OFF_B2S);
    float* b4s   = (float*)(sb + OFF_B4S);
    float* w3s   = (float*)(sb + OFF_W3S);
    float* arowp = (float*)(sb + OFF_ARP);
    float* arow  = (float*)(sb + OFF_ARW);
    float* invd  = (float*)(sb + OFF_INVD);
    float* dsum  = (float*)(sb + OFF_DSUM);

    // prefetch v=0 ctx chunks (per wg stream)
    prefetch_wg<CB>(sb, g_wB + (size_t)wg * WGS + CTXo, tw, wg);

    // ---- build vol rows ----
    if (t < 128) {
        float f[8] = {0.f,0.f,0.f,0.f,0.f,0.f,0.f,0.f};
        const int nl = t / PP, p = t % PP;
        const int node = base + nl;
        if (t < ROWS_ && node < n_nodes) {
            if (p == 0) {
                f[0]=centers[node*3+0]; f[1]=centers[node*3+1]; f[2]=centers[node*3+2];
                f[3]=normals[node*3+0]; f[4]=normals[node*3+1]; f[5]=normals[node*3+2];
                f[6]=logf(areas[node]) * 0.1f;
            } else {
                const int nb = node * NK + (p - 1);
                f[0]=neighbors[nb*3+0]+1e-6f; f[1]=neighbors[nb*3+1]+1e-6f;
                f[2]=neighbors[nb*3+2]+1e-6f;
                f[3]=neigh_normals[nb*3+0]+1e-6f; f[4]=neigh_normals[nb*3+1]+1e-6f;
                f[5]=neigh_normals[nb*3+2]+1e-6f;
                f[6]=logf(neigh_areas[nb]) * 0.1f + 1e-6f;
            }
        }
#pragma unroll
        for (int q = 0; q < 8; q++) svol[t * 8 + q] = f[q];
    }
    __syncthreads();
    if (t < NPC * NK) {
        const int nl = t / NK, j = t % NK;
        float d2 = 0.f;
#pragma unroll
        for (int q = 0; q < 7; q++) {
            const float d = svol[(nl*7)*8 + q] - svol[(nl*7 + 1 + j)*8 + q];
            d2 += d * d;
        }
        invd[nl * 8 + j] = 1.f / sqrtf(d2);
    }
    __syncthreads();
    if (t < NPC) {
        float s = 0.f;
#pragma unroll
        for (int j = 0; j < NK; j++) s += invd[t * 8 + j];
        dsum[t] = s;
    }

    const int r0m = 16 * widg + quad;
    float sv0[7], sv1[7];
#pragma unroll
    for (int q = 0; q < 7; q++) {
        sv0[q] = svol[r0m * 8 + q];
        sv1[q] = svol[(r0m + 8) * 8 + q];
    }

#pragma unroll 1
    for (int v = 0; v < V_; v++) {
        const uint8_t* wv = g_wB + (size_t)v * VSTRIDE + (size_t)wg * WGS;
        // per-v constants
        for (int i = t; i < 1792; i += NT) W1s[i] = __ldg(basis_W1 + (size_t)v * 1792 + i);
        if (t < 256) { b1s[t] = __ldg(basis_b1 + v * 256 + t);
                       b2s[t] = __ldg(basis_b2 + v * 256 + t); }
        else if (t < 384) { b4s[t-256] = __ldg(agg_b2 + v * 128 + (t-256)); }
        else { w3s[t-384] = __ldg(agg_W3 + v * 128 + (t-384)); }

        // ---- build ctx A frags (full CTA; M=32, K padded to 192) ----
        {
            uint4* AHI = (uint4*)(sb + OFF_AHI);
            uint4* ALO = (uint4*)(sb + OFF_ALO);
#pragma unroll
            for (int rep = 0; rep < 2; rep++) {
                const int slot = wid + rep * 16;
                if (slot < 24) {
                    const int fm = slot / 12, fk = slot % 12;
                    const int rr0 = fm * 16 + quad, rr1 = rr0 + 8;
                    const int cc0 = fk * 16 + 2 * q4, cc1 = cc0 + 8;
                    float2 vv[4];
                    const int rs[2] = {rr0, rr1};
                    const int cs[2] = {cc0, cc1};
#pragma unroll
                    for (int a = 0; a < 4; a++) {
                        const int r = rs[a & 1], cc = cs[a >> 1];
                        const int node = base + r;
                        float2 val = make_float2(0.f, 0.f);
                        if (r < NPC && node < n_nodes && cc < 160) {
                            if (cc < 32) val = *(const float2*)(enc_node + (size_t)node*32 + cc);
                            else         val = *(const float2*)(enc_g + (size_t)node*128 + (cc-32));
                        }
                        vv[a] = val;
                    }
                    uint32_t h[4], l[4];
#pragma unroll
                    for (int a = 0; a < 4; a++) plain_split(vv[a].x, vv[a].y, h[a], l[a]);
                    AHI[slot * 32 + lane] = make_uint4(h[0], h[1], h[2], h[3]);
                    ALO[slot * 32 + lane] = make_uint4(l[0], l[1], l[2], l[3]);
                }
            }
        }
        __syncthreads();

        // ---- ctx GEMM: ctxps[18][wg cols] = ctx @ Wctx + cst3 ----
        {
            const int cwm = widg & 1, cwn = widg >> 1;     // 2m x 4n within wg
            float cacc[4][4];
#pragma unroll
            for (int i = 0; i < 4; i++)
#pragma unroll
                for (int j = 0; j < 4; j++) cacc[i][j] = 0.f;
            const int cnbase = cwn * 32 + 8 * ((lane >> 4) & 1) + (lane & 7);
            mma_loop_wg<3, 4, CB, true>(sb, wv + CTXo,
                                        tw, wg, lane, cwm * 12, cnbase, cacc);
            prefetch_wg<CB>(sb, wv, tw, wg);   // L2 chunks
            // ctx epilogue (cols disjoint per wg; read later by same wg only)
            const int rr0 = cwm * 16 + quad;
            const float* cstv = g_cst3[v];
#pragma unroll
            for (int jj = 0; jj < 2; jj++)
#pragma unroll
                for (int e = 0; e < 2; e++) {
                    const int col = wg * 128 + cwn * 32 + jj * 16 + e * 8 + 2 * q4;
                    const float2 cst = *(const float2*)(cstv + col);
                    const float* a = cacc[2 * jj + e];
                    if (rr0 < NPC && base + rr0 < n_nodes)
                        *(float2*)(ctxps + rr0 * 260 + col) =
                            make_float2(a[0] + cst.x, a[1] + cst.y);
                    if (rr0 + 8 < NPC && base + rr0 + 8 < n_nodes)
                        *(float2*)(ctxps + (rr0 + 8) * 260 + col) =
                            make_float2(a[2] + cst.x, a[3] + cst.y);
                }
        }
        __syncthreads();   // ctx A slots free; L1 overwrites them

        // ---- L1: produce A frags directly (overlaps L2 weight copies) ----
        {
            uint4* AHI = (uint4*)(sb + OFF_AHI);
            uint4* ALO = (uint4*)(sb + OFF_ALO);
#pragma unroll
            for (int u = 0; u < 8; u++) {
                const int c0 = wg * 128 + 16 * u + 2 * q4;
                const int c2 = c0 + 8;
                float2 a00 = *(const float2*)(b1s + c0);
                float2 a01 = *(const float2*)(b1s + c2);
                float2 a10 = a00, a11 = a01;
#pragma unroll
                for (int q = 0; q < 7; q++) {
                    const float2 w0 = *(const float2*)(W1s + q * 256 + c0);
                    const float2 w2 = *(const float2*)(W1s + q * 256 + c2);
                    ffma2s(a00, sv0[q], w0); ffma2s(a01, sv0[q], w2);
                    ffma2s(a10, sv1[q], w0); ffma2s(a11, sv1[q], w2);
                }
                uint32_t h0, l0, h1, l1, h2, l2, h3, l3;
                relu_split(a00.x, a00.y, h0, l0);
                relu_split(a10.x, a10.y, h1, l1);
                relu_split(a01.x, a01.y, h2, l2);
                relu_split(a11.x, a11.y, h3, l3);
                const int fi = (widg * 16 + 8 * wg + u) * 32 + lane;
                AHI[fi] = make_uint4(h0, h1, h2, h3);
                ALO[fi] = make_uint4(l0, l1, l2, l3);
            }
        }
        __syncthreads();

        const int nbase = 8 * ((lane >> 4) & 1) + (lane & 7);
        // ---- L2 ----
        {
            float acc[16][4];
#pragma unroll
            for (int i = 0; i < 16; i++)
#pragma unroll
                for (int j = 0; j < 4; j++) acc[i][j] = 0.f;
            mma_loop_wg<4, 16, CB>(sb, wv, tw, wg, lane, widg * 16, nbase, acc);
            prefetch_wg<CB>(sb, wv + L3o, tw, wg);
            __syncthreads();   // both wgs done reading L1 A-frags
            epiA<0>(sb, acc, b2s, widg, wg, lane);
        }
        __syncthreads();
        // ---- L3 ----
        {
            float acc[16][4];
#pragma unroll
            for (int i = 0; i < 16; i++)
#pragma unroll
                for (int j = 0; j < 4; j++) acc[i][j] = 0.f;
            mma_loop_wg<4, 16, CB>(sb, wv + L3o, tw, wg, lane, widg * 16, nbase, acc);
            prefetch_wg<CB>(sb, wv + L4o, tw, wg);
            __syncthreads();
            epiA<1>(sb, acc, ctxps, widg, wg, lane);
        }
        __syncthreads();
        // ---- L4 + L5 ----
        {
            float acc[8][4];
#pragma unroll
            for (int i = 0; i < 8; i++)
#pragma unroll
                for (int j = 0; j < 4; j++) acc[i][j] = 0.f;
            mma_loop_l4(sb, wv + L4o, tw, wg, lane, widg * 16, nbase, acc);
            if (v + 1 < V_)
                prefetch_wg<CB>(sb, wv + VSTRIDE + CTXo, tw, wg);
            float s0 = 0.f, s1 = 0.f;
#pragma unroll
            for (int j = 0; j < 8; j++) {
                const int c0 = wg * 64 + 8 * j + 2 * q4;
                const float w30 = w3s[c0], w31 = w3s[c0 + 1];
                const float bb0 = b4s[c0], bb1 = b4s[c0 + 1];
                s0 += fmaxf(acc[j][0] + bb0, 0.f) * w30 + fmaxf(acc[j][1] + bb1, 0.f) * w31;
                s1 += fmaxf(acc[j][2] + bb0, 0.f) * w30 + fmaxf(acc[j][3] + bb1, 0.f) * w31;
            }
            s0 += __shfl_xor_sync(0xffffffffu, s0, 1);
            s0 += __shfl_xor_sync(0xffffffffu, s0, 2);
            s1 += __shfl_xor_sync(0xffffffffu, s1, 1);
            s1 += __shfl_xor_sync(0xffffffffu, s1, 2);
            if (q4 == 0) {
                arowp[wg * 128 + r0m] = s0;
                arowp[wg * 128 + r0m + 8] = s1;
            }
        }
        __syncthreads();
        if (t < 128) arow[t] = arowp[t] + arowp[128 + t] + __ldg(agg_b3 + v);
        __syncthreads();
        if (t < NPC) {
            const int node = base + t;
            if (node < n_nodes) {
                const float c = arow[t * 7];
                float s = 0.f;
#pragma unroll
                for (int j = 0; j < NK; j++) s += arow[t * 7 + 1 + j] * invd[t * 8 + j];
                out[node * V_ + v] = 0.5f * c + 0.5f * s / dsum[t];
            }
        }
        __syncthreads();
    }
}

// ============================ launcher =======================================
extern "C" void kernel_launch(void* const* d_in, const int* in_sizes, int n_in,
                              void* d_out, int out_size)
{
    const float* centers       = (const float*)d_in[0];
    const float* enc_g         = (const float*)d_in[1];
    const float* enc_node      = (const float*)d_in[2];
    const float* neighbors     = (const float*)d_in[3];
    const float* normals       = (const float*)d_in[4];
    const float* neigh_normals = (const float*)d_in[5];
    const float* areas         = (const float*)d_in[6];
    const float* neigh_areas   = (const float*)d_in[7];
    const float* gpv           = (const float*)d_in[8];
    const float* gpr           = (const float*)d_in[9];
    const float* param_W       = (const float*)d_in[10];
    const float* param_b       = (const float*)d_in[11];
    const float* basis_W1      = (const float*)d_in[12];
    const float* basis_b1      = (const float*)d_in[13];
    const float* basis_W2      = (const float*)d_in[14];
    const float* basis_b2      = (const float*)d_in[15];
    const float* agg_W1        = (const float*)d_in[16];
    const float* agg_b1        = (const float*)d_in[17];
    const float* agg_W2        = (const float*)d_in[18];
    const float* agg_b2        = (const float*)d_in[19];
    const float* agg_W3        = (const float*)d_in[20];
    const float* agg_b3        = (const float*)d_in[21];
    float* out = (float*)d_out;

    const int n_nodes = in_sizes[0] / 3;
    const int grid = (n_nodes + NPC - 1) / NPC;

    cudaFuncSetAttribute(surface_kernel,
                         cudaFuncAttributeMaxDynamicSharedMemorySize, SMEM_BYTES);

    cst3_kernel<<<V_, 256>>>(gpv, gpr, param_W, param_b, agg_W1, agg_b1);
    wconv_kernel<<<2560, 512>>>(basis_W2, agg_W1, agg_W2);
    surface_kernel<<<grid, NT, SMEM_BYTES>>>(
        centers, enc_g, enc_node, neighbors, normals, neigh_normals,
        areas, neigh_areas,
        basis_W1, basis_b1, basis_b2, agg_b2, agg_W3, agg_b3, out, n_nodes);
}

// round 15
// speedup vs baseline: 7.1087x; 1.0545x over previous
#include <cuda_runtime.h>
#include <cuda_fp16.h>
#include <math.h>
#include <stdint.h>

constexpr int V_ = 4;
constexpr int NK = 6;
constexpr int PP = 7;
constexpr int NPC = 18;
constexpr int ROWS_ = 126;
constexpr int NT = 512;

// weight blob per v, per-warpgroup streams of fp16 [128n][64k] (16KB) chunks.
// 2-pass split: B stored hi-only. Per wg: L2 4 chunks, L3 4, L4 2 (merged,
// each two 8KB [64n][64k] subs), CTX 3 (K padded 160->192, chunk2 half-real).
constexpr int CB  = 16384;
constexpr int CB4 = 8192;
constexpr int WGS   = 13 * CB;       // per-wg stream: 212992
constexpr int L3o   = 4 * CB;
constexpr int L4o   = 8 * CB;
constexpr int CTXo  = 10 * CB;
constexpr int VSTRIDE = 2 * WGS;     // 425984

__device__ uint8_t g_wB[(size_t)V_ * VSTRIDE];
__device__ float   g_cst3[V_][256];

// ---- smem byte offsets ----
constexpr int OFF_W    = 0;        // 65536: wg0 [0,32K), wg1 [32K,64K)
constexpr int OFF_AHI  = 65536;    // 65536 (A hi frags: 128 slots x 512B)
constexpr int OFF_ALO  = 131072;   // 65536
constexpr int OFF_CTXP = 196608;   // 18*260*4 = 18720
constexpr int OFF_SVOL = 215328;   // 4096
constexpr int OFF_W1S  = 219424;   // 7168
constexpr int OFF_B1S  = 226592;   // 1024
constexpr int OFF_B2S  = 227616;   // 1024
constexpr int OFF_B4S  = 228640;   // 512
constexpr int OFF_W3S  = 229152;   // 512
constexpr int OFF_ARP  = 229664;   // 1024
constexpr int OFF_ARW  = 230688;   // 512
constexpr int OFF_INVD = 231200;   // 576
constexpr int OFF_DSUM = 231776;   // 96
constexpr int SMEM_BYTES = 231872;

// ============================ PTX helpers ====================================
__device__ __forceinline__ uint32_t su32(const void* p) {
    return (uint32_t)__cvta_generic_to_shared(p);
}
__device__ __forceinline__ void cp16(uint8_t* s, const uint8_t* g) {
    uint32_t sa = su32(s);
    asm volatile("cp.async.cg.shared.global [%0], [%1], 16;" :: "r"(sa), "l"(g));
}
#define CP_COMMIT() asm volatile("cp.async.commit_group;" ::: "memory")
#define CP_WAIT1()  asm volatile("cp.async.wait_group 1;" ::: "memory")
#define CP_WAIT0()  asm volatile("cp.async.wait_group 0;" ::: "memory")
// per-warpgroup named barrier (ids 1,2), 256 threads each
#define BARW(g) asm volatile("bar.sync %0, %1;" :: "r"((g) + 1), "r"(256) : "memory")

#define MMA_F16(acc, a, b0, b1) asm volatile( \
    "mma.sync.aligned.m16n8k16.row.col.f32.f16.f16.f32 " \
    "{%0,%1,%2,%3}, {%4,%5,%6,%7}, {%8,%9}, {%0,%1,%2,%3};" \
    : "+f"((acc)[0]), "+f"((acc)[1]), "+f"((acc)[2]), "+f"((acc)[3]) \
    : "r"((a).x), "r"((a).y), "r"((a).z), "r"((a).w), "r"(b0), "r"(b1))

#define LDSM4(r0, r1, r2, r3, addr) asm volatile( \
    "ldmatrix.sync.aligned.m8n8.x4.shared.b16 {%0,%1,%2,%3}, [%4];" \
    : "=r"(r0), "=r"(r1), "=r"(r2), "=r"(r3) : "r"(addr))

__device__ __forceinline__ void relu_split(float x, float y, uint32_t& h, uint32_t& l) {
    x = fmaxf(x, 0.f); y = fmaxf(y, 0.f);
    __half2 hh = __floats2half2_rn(x, y);
    float2 hf = __half22float2(hh);
    __half2 ll = __floats2half2_rn(x - hf.x, y - hf.y);
    h = *reinterpret_cast<uint32_t*>(&hh);
    l = *reinterpret_cast<uint32_t*>(&ll);
}
__device__ __forceinline__ uint32_t relu_hi(float x, float y) {
    x = fmaxf(x, 0.f); y = fmaxf(y, 0.f);
    __half2 hh = __floats2half2_rn(x, y);
    return *reinterpret_cast<uint32_t*>(&hh);
}
__device__ __forceinline__ void plain_split(float x, float y, uint32_t& h, uint32_t& l) {
    __half2 hh = __floats2half2_rn(x, y);
    float2 hf = __half22float2(hh);
    __half2 ll = __floats2half2_rn(x - hf.x, y - hf.y);
    h = *reinterpret_cast<uint32_t*>(&hh);
    l = *reinterpret_cast<uint32_t*>(&ll);
}
__device__ __forceinline__ void ffma2s(float2& d, float a, float2 b) {
    unsigned long long dd = *reinterpret_cast<unsigned long long*>(&d);
    float2 av = make_float2(a, a);
    unsigned long long aa = *reinterpret_cast<unsigned long long*>(&av);
    unsigned long long bb = *reinterpret_cast<unsigned long long*>(&b);
    asm("fma.rn.f32x2 %0, %1, %2, %0;" : "+l"(dd) : "l"(aa), "l"(bb));
    d = *reinterpret_cast<float2*>(&dd);
}

// ===================== side kernel 1: cst3 (one block per v) =================
__global__ void cst3_kernel(const float* __restrict__ gpv, const float* __restrict__ gpr,
                            const float* __restrict__ pW, const float* __restrict__ pb,
                            const float* __restrict__ aW1, const float* __restrict__ ab1)
{
    __shared__ float pe[32];
    const int t = threadIdx.x;
    const int v = blockIdx.x;
    const float p0 = gpv[0] / gpr[0], p1 = gpv[1] / gpr[1];
    if (t < 32) pe[t] = fmaxf(pb[t] + p0 * pW[t] + p1 * pW[32 + t], 0.f);
    __syncthreads();
    const int c = t;
    const float* W = aW1 + ((size_t)v * 448 + 416) * 256 + c;
    float s = ab1[v * 256 + c];
#pragma unroll
    for (int k = 0; k < 32; k++) s += pe[k] * W[(size_t)k * 256];
    g_cst3[v][c] = s;
}

// ===================== side kernel 2: weight convert (fp16 hi-only) ==========
__global__ void wconv_kernel(const float* __restrict__ bW2,
                             const float* __restrict__ aW1,
                             const float* __restrict__ aW2)
{
    constexpr int PERV = 65536 + 65536 + 32768 + 49152;   // 212992 elements
    const int total = V_ * PERV;
    for (int idx = blockIdx.x * blockDim.x + threadIdx.x; idx < total;
         idx += gridDim.x * blockDim.x) {
        const int v = idx / PERV;
        int e = idx % PERV;
        size_t dst;
        int n_local, kl;
        float w;
        if (e < 65536) {                        // L2: 2wg x 4 chunks
            const int wg = e >> 15, r = e & 32767;
            const int c = r >> 13, rr = r & 8191;
            n_local = rr >> 6; kl = rr & 63;
            const int n = wg * 128 + n_local, k = c * 64 + kl;
            w = bW2[((size_t)v * 256 + k) * 256 + n];
            dst = (size_t)wg * WGS + (size_t)c * CB;
        } else if (e < 131072) {                // L3
            e -= 65536;
            const int wg = e >> 15, r = e & 32767;
            const int c = r >> 13, rr = r & 8191;
            n_local = rr >> 6; kl = rr & 63;
            const int n = wg * 128 + n_local, k = c * 64 + kl;
            w = aW1[((size_t)v * 448 + k) * 256 + n];
            dst = (size_t)wg * WGS + L3o + (size_t)c * CB;
        } else if (e < 163840) {                // L4: 2wg x 2 merged chunks
            e -= 131072;
            const int wg = e >> 14, r = e & 16383;
            const int kk = r >> 12, rr = r & 4095;
            n_local = rr >> 6; kl = rr & 63;
            const int n = wg * 64 + n_local, k = kk * 64 + kl;
            w = aW2[((size_t)v * 256 + k) * 128 + n];
            dst = (size_t)wg * WGS + L4o + (size_t)(kk >> 1) * CB + (size_t)(kk & 1) * CB4;
        } else {                                // CTX: 2wg x 3 chunks (K pad 192)
            e -= 163840;
            const int wg = e / 24576, r = e % 24576;
            const int c = r >> 13, rr = r & 8191;
            n_local = rr >> 6; kl = rr & 63;
            const int n = wg * 128 + n_local, k = c * 64 + kl;
            w = (k < 160) ? aW1[((size_t)v * 448 + 256 + k) * 256 + n] : 0.f;
            dst = (size_t)wg * WGS + CTXo + (size_t)c * CB;
        }
        __half val = __float2half_rn(w);
        uint8_t* p = g_wB + (size_t)v * VSTRIDE + dst
                   + n_local * 128 + (((uint32_t)(kl * 2)) ^ (((uint32_t)n_local & 7) << 4));
        *reinterpret_cast<__half*>(p) = val;
    }
}

// ===================== per-wg prefetch + mainloop ============================
template <int CBT>
__device__ __forceinline__ void prefetch_wg(uint8_t* sb, const uint8_t* wsrc,
                                            int tw, int wg) {
    constexpr int NCP = CBT / 16 / 256;
    uint8_t* w0 = sb + OFF_W + wg * 32768;
#pragma unroll
    for (int i = 0; i < NCP; i++)
        cp16(w0 + (tw + i * 256) * 16, wsrc + (size_t)(tw + i * 256) * 16);
    CP_COMMIT();
#pragma unroll
    for (int i = 0; i < NCP; i++)
        cp16(w0 + CBT + (tw + i * 256) * 16, wsrc + CBT + (size_t)(tw + i * 256) * 16);
    CP_COMMIT();
}

// requires prefetch_wg<CBT>(wsrc) already issued (2 groups pending).
// 2-pass fp16: every chunk runs ah*B and al*B. fkb = c*4.
// TRIM: ctx K pad — chunk 2 has only 2 real k-frags.
template <int NCHUNK, int NFRAG, int CBT, bool TRIM = false>
__device__ __forceinline__ void mma_loop_wg(
    uint8_t* sb, const uint8_t* wsrc, int tw, int wg, int lane,
    int aslot0, int nbase, float (*acc)[4])
{
    uint8_t* w0 = sb + OFF_W + wg * 32768;
    const uint4* AHI = (const uint4*)(sb + OFF_AHI);
    const uint4* ALO = (const uint4*)(sb + OFF_ALO);
    const uint32_t swzc = ((uint32_t)lane & 7) << 4;
    const int kadd = ((lane >> 3) & 1) * 8;
    constexpr int NCP = CBT / 16 / 256;
#pragma unroll 1
    for (int c = 0; c < NCHUNK; c++) {
        if (c < NCHUNK - 1) CP_WAIT1(); else CP_WAIT0();
        BARW(wg);
        const uint32_t wb = su32(w0 + (c & 1) * CBT);
        const int fkb = c * 4;
        const int scnt = (TRIM && c == 2) ? 2 : 4;
#pragma unroll
        for (int s = 0; s < 4; s++) {
            if (s < scnt) {
                const int fk = fkb + s;
                const uint4 ah = AHI[(aslot0 + fk) * 32 + lane];
                const uint4 al = ALO[(aslot0 + fk) * 32 + lane];
                const int koff = s * 16 + kadd;
                const uint32_t ba = wb + (uint32_t)(nbase * 128)
                                  + (((uint32_t)(koff * 2)) ^ swzc);
#pragma unroll
                for (int jj = 0; jj < NFRAG / 2; jj++) {
                    uint32_t b0, b1, b2, b3;
                    LDSM4(b0, b1, b2, b3, ba + jj * 2048);
                    MMA_F16(acc[2 * jj],     ah, b0, b1);
                    MMA_F16(acc[2 * jj + 1], ah, b2, b3);
                    MMA_F16(acc[2 * jj],     al, b0, b1);
                    MMA_F16(acc[2 * jj + 1], al, b2, b3);
                }
            }
        }
        BARW(wg);
        if (c + 2 < NCHUNK) {
#pragma unroll
            for (int i = 0; i < NCP; i++)
                cp16(w0 + (c & 1) * CBT + (tw + i * 256) * 16,
                     wsrc + (size_t)(c + 2) * CBT + (size_t)(tw + i * 256) * 16);
            CP_COMMIT();
        }
    }
}

// L4 merged mainloop: 2 chunks of 16KB, each = two 8KB [64n][64k] sub-blocks.
// HI-ONLY pass (L3 output consumed as plain fp16; al pass dropped).
__device__ __forceinline__ void mma_loop_l4(
    uint8_t* sb, const uint8_t* wsrc, int tw, int wg, int lane,
    int aslot0, int nbase, float (*acc)[4])
{
    uint8_t* w0 = sb + OFF_W + wg * 32768;
    const uint4* AHI = (const uint4*)(sb + OFF_AHI);
    const uint32_t swzc = ((uint32_t)lane & 7) << 4;
    const int kadd = ((lane >> 3) & 1) * 8;
#pragma unroll 1
    for (int c = 0; c < 2; c++) {
        if (c < 1) CP_WAIT1(); else CP_WAIT0();
        BARW(wg);
        const uint32_t wb = su32(w0 + (c & 1) * CB);
        const int fkb = c * 8;
#pragma unroll
        for (int s = 0; s < 8; s++) {
            const int fk = fkb + s;
            const uint4 ah = AHI[(aslot0 + fk) * 32 + lane];
            const int koff = (s & 3) * 16 + kadd;
            const uint32_t ba = wb + (uint32_t)((s >> 2) * 8192)
                              + (uint32_t)(nbase * 128)
                              + (((uint32_t)(koff * 2)) ^ swzc);
#pragma unroll
            for (int jj = 0; jj < 4; jj++) {
                uint32_t b0, b1, b2, b3;
                LDSM4(b0, b1, b2, b3, ba + jj * 2048);
                MMA_F16(acc[2 * jj],     ah, b0, b1);
                MMA_F16(acc[2 * jj + 1], ah, b2, b3);
            }
        }
        BARW(wg);
    }
}

// ===================== epilogue: C frags -> A frags =========================
// wn = warpgroup id (column half). MODE 0: bias; MODE 1: per-node ctxp.
// LO: whether to compute/store the lo fragments (next layer's al pass).
template <int MODE, bool LO = true>
__device__ __forceinline__ void epiA(
    uint8_t* sbH, float (*acc)[4], const float* __restrict__ addv,
    int wm, int wn, int lane)
{
    uint4* AHI = (uint4*)(sbH + OFF_AHI);
    uint4* ALO = (uint4*)(sbH + OFF_ALO);
    const int quad = lane >> 2, q4 = lane & 3;
    const int r0 = 16 * wm + quad;
    int n0 = r0 / 7;       if (n0 > 17) n0 = 17;
    int n1 = (r0 + 8) / 7; if (n1 > 17) n1 = 17;
#pragma unroll
    for (int u = 0; u < 8; u++) {
        const int c0 = wn * 128 + 16 * u + 2 * q4;
        const int c2 = c0 + 8;
        float2 a00, a01, a10, a11;
        if constexpr (MODE == 0) {
            a00 = *(const float2*)(addv + c0);
            a01 = *(const float2*)(addv + c2);
            a10 = a00; a11 = a01;
        } else {
            a00 = *(const float2*)(addv + n0 * 260 + c0);
            a01 = *(const float2*)(addv + n0 * 260 + c2);
            a10 = *(const float2*)(addv + n1 * 260 + c0);
            a11 = *(const float2*)(addv + n1 * 260 + c2);
        }
        const int fi = (wm * 16 + 8 * wn + u) * 32 + lane;
        if constexpr (LO) {
            uint32_t h0, l0, h1, l1, h2, l2, h3, l3;
            relu_split(acc[2*u][0]   + a00.x, acc[2*u][1]   + a00.y, h0, l0);
            relu_split(acc[2*u][2]   + a10.x, acc[2*u][3]   + a10.y, h1, l1);
            relu_split(acc[2*u+1][0] + a01.x, acc[2*u+1][1] + a01.y, h2, l2);
            relu_split(acc[2*u+1][2] + a11.x, acc[2*u+1][3] + a11.y, h3, l3);
            AHI[fi] = make_uint4(h0, h1, h2, h3);
            ALO[fi] = make_uint4(l0, l1, l2, l3);
        } else {
            const uint32_t h0 = relu_hi(acc[2*u][0]   + a00.x, acc[2*u][1]   + a00.y);
            const uint32_t h1 = relu_hi(acc[2*u][2]   + a10.x, acc[2*u][3]   + a10.y);
            const uint32_t h2 = relu_hi(acc[2*u+1][0] + a01.x, acc[2*u+1][1] + a01.y);
            const uint32_t h3 = relu_hi(acc[2*u+1][2] + a11.x, acc[2*u+1][3] + a11.y);
            AHI[fi] = make_uint4(h0, h1, h2, h3);
        }
    }
}

// ============================ main kernel ====================================
__global__ void __launch_bounds__(NT, 1)
surface_kernel(
    const float* __restrict__ centers,  const float* __restrict__ enc_g,
    const float* __restrict__ enc_node, const float* __restrict__ neighbors,
    const float* __restrict__ normals,  const float* __restrict__ neigh_normals,
    const float* __restrict__ areas,    const float* __restrict__ neigh_areas,
    const float* __restrict__ basis_W1, const float* __restrict__ basis_b1,
    const float* __restrict__ basis_b2, const float* __restrict__ agg_b2,
    const float* __restrict__ agg_W3,   const float* __restrict__ agg_b3,
    float* __restrict__ out, const int n_nodes)
{
    extern __shared__ uint8_t sb[];
    const int t = threadIdx.x;
    const int wid = t >> 5, lane = t & 31;
    const int wg = t >> 8;             // warpgroup 0/1 == column half
    const int tw = t & 255;            // thread index within wg
    const int widg = wid & 7;          // warp within wg == wm
    const int quad = lane >> 2, q4 = lane & 3;
    const int base = blockIdx.x * NPC;

    float* ctxps = (float*)(sb + OFF_CTXP);
    float* svol  = (float*)(sb + OFF_SVOL);
    float* W1s   = (float*)(sb + OFF_W1S);
    float* b1s   = (float*)(sb + OFF_B1S);
    float* b2s   = (float*)(sb + OFF_B2S);
    float* b4s   = (float*)(sb + OFF_B4S);
    float* w3s   = (float*)(sb + OFF_W3S);
    float* arowp = (float*)(sb + OFF_ARP);
    float* arow  = (float*)(sb + OFF_ARW);
    float* invd  = (float*)(sb + OFF_INVD);
    float* dsum  = (float*)(sb + OFF_DSUM);

    // prefetch v=0 ctx chunks (per wg stream)
    prefetch_wg<CB>(sb, g_wB + (size_t)wg * WGS + CTXo, tw, wg);

    // ---- build vol rows ----
    if (t < 128) {
        float f[8] = {0.f,0.f,0.f,0.f,0.f,0.f,0.f,0.f};
        const int nl = t / PP, p = t % PP;
        const int node = base + nl;
        if (t < ROWS_ && node < n_nodes) {
            if (p == 0) {
                f[0]=centers[node*3+0]; f[1]=centers[node*3+1]; f[2]=centers[node*3+2];
                f[3]=normals[node*3+0]; f[4]=normals[node*3+1]; f[5]=normals[node*3+2];
                f[6]=logf(areas[node]) * 0.1f;
            } else {
                const int nb = node * NK + (p - 1);
                f[0]=neighbors[nb*3+0]+1e-6f; f[1]=neighbors[nb*3+1]+1e-6f;
                f[2]=neighbors[nb*3+2]+1e-6f;
                f[3]=neigh_normals[nb*3+0]+1e-6f; f[4]=neigh_normals[nb*3+1]+1e-6f;
                f[5]=neigh_normals[nb*3+2]+1e-6f;
                f[6]=logf(neigh_areas[nb]) * 0.1f + 1e-6f;
            }
        }
#pragma unroll
        for (int q = 0; q < 8; q++) svol[t * 8 + q] = f[q];
    }
    __syncthreads();
    if (t < NPC * NK) {
        const int nl = t / NK, j = t % NK;
        float d2 = 0.f;
#pragma unroll
        for (int q = 0; q < 7; q++) {
            const float d = svol[(nl*7)*8 + q] - svol[(nl*7 + 1 + j)*8 + q];
            d2 += d * d;
        }
        invd[nl * 8 + j] = 1.f / sqrtf(d2);
    }
    __syncthreads();
    if (t < NPC) {
        float s = 0.f;
#pragma unroll
        for (int j = 0; j < NK; j++) s += invd[t * 8 + j];
        dsum[t] = s;
    }

    const int r0m = 16 * widg + quad;
    float sv0[7], sv1[7];
#pragma unroll
    for (int q = 0; q < 7; q++) {
        sv0[q] = svol[r0m * 8 + q];
        sv1[q] = svol[(r0m + 8) * 8 + q];
    }

#pragma unroll 1
    for (int v = 0; v < V_; v++) {
        const uint8_t* wv = g_wB + (size_t)v * VSTRIDE + (size_t)wg * WGS;
        // per-v constants
        for (int i = t; i < 1792; i += NT) W1s[i] = __ldg(basis_W1 + (size_t)v * 1792 + i);
        if (t < 256) { b1s[t] = __ldg(basis_b1 + v * 256 + t);
                       b2s[t] = __ldg(basis_b2 + v * 256 + t); }
        else if (t < 384) { b4s[t-256] = __ldg(agg_b2 + v * 128 + (t-256)); }
        else { w3s[t-384] = __ldg(agg_W3 + v * 128 + (t-384)); }

        // ---- build ctx A frags (full CTA; M=32, K padded to 192) ----
        {
            uint4* AHI = (uint4*)(sb + OFF_AHI);
            uint4* ALO = (uint4*)(sb + OFF_ALO);
#pragma unroll
            for (int rep = 0; rep < 2; rep++) {
                const int slot = wid + rep * 16;
                if (slot < 24) {
                    const int fm = slot / 12, fk = slot % 12;
                    const int rr0 = fm * 16 + quad, rr1 = rr0 + 8;
                    const int cc0 = fk * 16 + 2 * q4, cc1 = cc0 + 8;
                    float2 vv[4];
                    const int rs[2] = {rr0, rr1};
                    const int cs[2] = {cc0, cc1};
#pragma unroll
                    for (int a = 0; a < 4; a++) {
                        const int r = rs[a & 1], cc = cs[a >> 1];
                        const int node = base + r;
                        float2 val = make_float2(0.f, 0.f);
                        if (r < NPC && node < n_nodes && cc < 160) {
                            if (cc < 32) val = *(const float2*)(enc_node + (size_t)node*32 + cc);
                            else         val = *(const float2*)(enc_g + (size_t)node*128 + (cc-32));
                        }
                        vv[a] = val;
                    }
                    uint32_t h[4], l[4];
#pragma unroll
                    for (int a = 0; a < 4; a++) plain_split(vv[a].x, vv[a].y, h[a], l[a]);
                    AHI[slot * 32 + lane] = make_uint4(h[0], h[1], h[2], h[3]);
                    ALO[slot * 32 + lane] = make_uint4(l[0], l[1], l[2], l[3]);
                }
            }
        }
        __syncthreads();

        // ---- ctx GEMM: ctxps[18][wg cols] = ctx @ Wctx + cst3 ----
        {
            const int cwm = widg & 1, cwn = widg >> 1;     // 2m x 4n within wg
            float cacc[4][4];
#pragma unroll
            for (int i = 0; i < 4; i++)
#pragma unroll
                for (int j = 0; j < 4; j++) cacc[i][j] = 0.f;
            const int cnbase = cwn * 32 + 8 * ((lane >> 4) & 1) + (lane & 7);
            mma_loop_wg<3, 4, CB, true>(sb, wv + CTXo,
                                        tw, wg, lane, cwm * 12, cnbase, cacc);
            prefetch_wg<CB>(sb, wv, tw, wg);   // L2 chunks
            // ctx epilogue (cols disjoint per wg; read later by same wg only)
            const int rr0 = cwm * 16 + quad;
            const float* cstv = g_cst3[v];
#pragma unroll
            for (int jj = 0; jj < 2; jj++)
#pragma unroll
                for (int e = 0; e < 2; e++) {
                    const int col = wg * 128 + cwn * 32 + jj * 16 + e * 8 + 2 * q4;
                    const float2 cst = *(const float2*)(cstv + col);
                    const float* a = cacc[2 * jj + e];
                    if (rr0 < NPC && base + rr0 < n_nodes)
                        *(float2*)(ctxps + rr0 * 260 + col) =
                            make_float2(a[0] + cst.x, a[1] + cst.y);
                    if (rr0 + 8 < NPC && base + rr0 + 8 < n_nodes)
                        *(float2*)(ctxps + (rr0 + 8) * 260 + col) =
                            make_float2(a[2] + cst.x, a[3] + cst.y);
                }
        }
        __syncthreads();   // ctx A slots free; L1 overwrites them

        // ---- L1: produce A frags directly (overlaps L2 weight copies) ----
        {
            uint4* AHI = (uint4*)(sb + OFF_AHI);
            uint4* ALO = (uint4*)(sb + OFF_ALO);
#pragma unroll
            for (int u = 0; u < 8; u++) {
                const int c0 = wg * 128 + 16 * u + 2 * q4;
                const int c2 = c0 + 8;
                float2 a00 = *(const float2*)(b1s + c0);
                float2 a01 = *(const float2*)(b1s + c2);
                float2 a10 = a00, a11 = a01;
#pragma unroll
                for (int q = 0; q < 7; q++) {
                    const float2 w0 = *(const float2*)(W1s + q * 256 + c0);
                    const float2 w2 = *(const float2*)(W1s + q * 256 + c2);
                    ffma2s(a00, sv0[q], w0); ffma2s(a01, sv0[q], w2);
                    ffma2s(a10, sv1[q], w0); ffma2s(a11, sv1[q], w2);
                }
                uint32_t h0, l0, h1, l1, h2, l2, h3, l3;
                relu_split(a00.x, a00.y, h0, l0);
                relu_split(a10.x, a10.y, h1, l1);
                relu_split(a01.x, a01.y, h2, l2);
                relu_split(a11.x, a11.y, h3, l3);
                const int fi = (widg * 16 + 8 * wg + u) * 32 + lane;
                AHI[fi] = make_uint4(h0, h1, h2, h3);
                ALO[fi] = make_uint4(l0, l1, l2, l3);
            }
        }
        __syncthreads();

        const int nbase = 8 * ((lane >> 4) & 1) + (lane & 7);
        // ---- L2 ----
        {
            float acc[16][4];
#pragma unroll
            for (int i = 0; i < 16; i++)
#pragma unroll
                for (int j = 0; j < 4; j++) acc[i][j] = 0.f;
            mma_loop_wg<4, 16, CB>(sb, wv, tw, wg, lane, widg * 16, nbase, acc);
            prefetch_wg<CB>(sb, wv + L3o, tw, wg);
            __syncthreads();   // both wgs done reading L1 A-frags
            epiA<0>(sb, acc, b2s, widg, wg, lane);
        }
        __syncthreads();
        // ---- L3 ----
        {
            float acc[16][4];
#pragma unroll
            for (int i = 0; i < 16; i++)
#pragma unroll
                for (int j = 0; j < 4; j++) acc[i][j] = 0.f;
            mma_loop_wg<4, 16, CB>(sb, wv + L3o, tw, wg, lane, widg * 16, nbase, acc);
            prefetch_wg<CB>(sb, wv + L4o, tw, wg);
            __syncthreads();
            epiA<1, false>(sb, acc, ctxps, widg, wg, lane);   // hi-only: L4 drops al
        }
        __syncthreads();
        // ---- L4 + L5 (hi-only pass) ----
        {
            float acc[8][4];
#pragma unroll
            for (int i = 0; i < 8; i++)
#pragma unroll
                for (int j = 0; j < 4; j++) acc[i][j] = 0.f;
            mma_loop_l4(sb, wv + L4o, tw, wg, lane, widg * 16, nbase, acc);
            if (v + 1 < V_)
                prefetch_wg<CB>(sb, wv + VSTRIDE + CTXo, tw, wg);
            float s0 = 0.f, s1 = 0.f;
#pragma unroll
            for (int j = 0; j < 8; j++) {
                const int c0 = wg * 64 + 8 * j + 2 * q4;
                const float w30 = w3s[c0], w31 = w3s[c0 + 1];
                const float bb0 = b4s[c0], bb1 = b4s[c0 + 1];
                s0 += fmaxf(acc[j][0] + bb0, 0.f) * w30 + fmaxf(acc[j][1] + bb1, 0.f) * w31;
                s1 += fmaxf(acc[j][2] + bb0, 0.f) * w30 + fmaxf(acc[j][3] + bb1, 0.f) * w31;
            }
            s0 += __shfl_xor_sync(0xffffffffu, s0, 1);
            s0 += __shfl_xor_sync(0xffffffffu, s0, 2);
            s1 += __shfl_xor_sync(0xffffffffu, s1, 1);
            s1 += __shfl_xor_sync(0xffffffffu, s1, 2);
            if (q4 == 0) {
                arowp[wg * 128 + r0m] = s0;
                arowp[wg * 128 + r0m + 8] = s1;
            }
        }
        __syncthreads();
        if (t < 128) arow[t] = arowp[t] + arowp[128 + t] + __ldg(agg_b3 + v);
        __syncthreads();
        if (t < NPC) {
            const int node = base + t;
            if (node < n_nodes) {
                const float c = arow[t * 7];
                float s = 0.f;
#pragma unroll
                for (int j = 0; j < NK; j++) s += arow[t * 7 + 1 + j] * invd[t * 8 + j];
                out[node * V_ + v] = 0.5f * c + 0.5f * s / dsum[t];
            }
        }
        __syncthreads();
    }
}

// ============================ launcher =======================================
extern "C" void kernel_launch(void* const* d_in, const int* in_sizes, int n_in,
                              void* d_out, int out_size)
{
    const float* centers       = (const float*)d_in[0];
    const float* enc_g         = (const float*)d_in[1];
    const float* enc_node      = (const float*)d_in[2];
    const float* neighbors     = (const float*)d_in[3];
    const float* normals       = (const float*)d_in[4];
    const float* neigh_normals = (const float*)d_in[5];
    const float* areas         = (const float*)d_in[6];
    const float* neigh_areas   = (const float*)d_in[7];
    const float* gpv           = (const float*)d_in[8];
    const float* gpr           = (const float*)d_in[9];
    const float* param_W       = (const float*)d_in[10];
    const float* param_b       = (const float*)d_in[11];
    const float* basis_W1      = (const float*)d_in[12];
    const float* basis_b1      = (const float*)d_in[13];
    const float* basis_W2      = (const float*)d_in[14];
    const float* basis_b2      = (const float*)d_in[15];
    const float* agg_W1        = (const float*)d_in[16];
    const float* agg_b1        = (const float*)d_in[17];
    const float* agg_W2        = (const float*)d_in[18];
    const float* agg_b2        = (const float*)d_in[19];
    const float* agg_W3        = (const float*)d_in[20];
    const float* agg_b3        = (const float*)d_in[21];
    float* out = (float*)d_out;

    const int n_nodes = in_sizes[0] / 3;
    const int grid = (n_nodes + NPC - 1) / NPC;

    cudaFuncSetAttribute(surface_kernel,
                         cudaFuncAttributeMaxDynamicSharedMemorySize, SMEM_BYTES);

    cst3_kernel<<<V_, 256>>>(gpv, gpr, param_W, param_b, agg_W1, agg_b1);
    wconv_kernel<<<2560, 512>>>(basis_W2, agg_W1, agg_W2);
    surface_kernel<<<grid, NT, SMEM_BYTES>>>(
        centers, enc_g, enc_node, neighbors, normals, neigh_normals,
        areas, neigh_areas,
        basis_W1, basis_b1, basis_b2, agg_b2, agg_W3, agg_b3, out, n_nodes);
}

// round 16
// speedup vs baseline: 9.7512x; 1.3717x over previous
#include <cuda_runtime.h>
#include <cuda_fp16.h>
#include <math.h>
#include <stdint.h>

constexpr int V_ = 4;
constexpr int NK = 6;
constexpr int PP = 7;
constexpr int NPC = 18;
constexpr int ROWS_ = 126;
constexpr int NT = 512;

// weight blob per v, per-warpgroup streams of fp16 [128n][64k] (16KB) chunks.
// Plain fp16 (fp32 accum). Per wg: L2 4 chunks, L3 4, L4 2 (merged,
// each two 8KB [64n][64k] subs), CTX 3 (K padded 160->192, chunk2 half-real).
constexpr int CB  = 16384;
constexpr int CB4 = 8192;
constexpr int WGS   = 13 * CB;       // per-wg stream: 212992
constexpr int L3o   = 4 * CB;
constexpr int L4o   = 8 * CB;
constexpr int CTXo  = 10 * CB;
constexpr int VSTRIDE = 2 * WGS;     // 425984

__device__ uint8_t g_wB[(size_t)V_ * VSTRIDE];
__device__ float   g_cst3[V_][256];

// ---- smem byte offsets (ALO region now unused; layout preserved) ----
constexpr int OFF_W    = 0;        // 65536: wg0 [0,32K), wg1 [32K,64K)
constexpr int OFF_AHI  = 65536;    // 65536 (A frags: 128 slots x 512B)
constexpr int OFF_CTXP = 196608;   // 18*260*4 = 18720
constexpr int OFF_SVOL = 215328;   // 4096
constexpr int OFF_W1S  = 219424;   // 7168
constexpr int OFF_B1S  = 226592;   // 1024
constexpr int OFF_B2S  = 227616;   // 1024
constexpr int OFF_B4S  = 228640;   // 512
constexpr int OFF_W3S  = 229152;   // 512
constexpr int OFF_ARP  = 229664;   // 1024
constexpr int OFF_ARW  = 230688;   // 512
constexpr int OFF_INVD = 231200;   // 576
constexpr int OFF_DSUM = 231776;   // 96
constexpr int SMEM_BYTES = 231872;

// ============================ PTX helpers ====================================
__device__ __forceinline__ uint32_t su32(const void* p) {
    return (uint32_t)__cvta_generic_to_shared(p);
}
__device__ __forceinline__ void cp16(uint8_t* s, const uint8_t* g) {
    uint32_t sa = su32(s);
    asm volatile("cp.async.cg.shared.global [%0], [%1], 16;" :: "r"(sa), "l"(g));
}
#define CP_COMMIT() asm volatile("cp.async.commit_group;" ::: "memory")
#define CP_WAIT1()  asm volatile("cp.async.wait_group 1;" ::: "memory")
#define CP_WAIT0()  asm volatile("cp.async.wait_group 0;" ::: "memory")
// per-warpgroup named barrier (ids 1,2), 256 threads each
#define BARW(g) asm volatile("bar.sync %0, %1;" :: "r"((g) + 1), "r"(256) : "memory")

#define MMA_F16(acc, a, b0, b1) asm volatile( \
    "mma.sync.aligned.m16n8k16.row.col.f32.f16.f16.f32 " \
    "{%0,%1,%2,%3}, {%4,%5,%6,%7}, {%8,%9}, {%0,%1,%2,%3};" \
    : "+f"((acc)[0]), "+f"((acc)[1]), "+f"((acc)[2]), "+f"((acc)[3]) \
    : "r"((a).x), "r"((a).y), "r"((a).z), "r"((a).w), "r"(b0), "r"(b1))

#define LDSM4(r0, r1, r2, r3, addr) asm volatile( \
    "ldmatrix.sync.aligned.m8n8.x4.shared.b16 {%0,%1,%2,%3}, [%4];" \
    : "=r"(r0), "=r"(r1), "=r"(r2), "=r"(r3) : "r"(addr))

__device__ __forceinline__ uint32_t relu_hi(float x, float y) {
    x = fmaxf(x, 0.f); y = fmaxf(y, 0.f);
    __half2 hh = __floats2half2_rn(x, y);
    return *reinterpret_cast<uint32_t*>(&hh);
}
__device__ __forceinline__ uint32_t pack_h2(float x, float y) {
    __half2 hh = __floats2half2_rn(x, y);
    return *reinterpret_cast<uint32_t*>(&hh);
}
__device__ __forceinline__ void ffma2s(float2& d, float a, float2 b) {
    unsigned long long dd = *reinterpret_cast<unsigned long long*>(&d);
    float2 av = make_float2(a, a);
    unsigned long long aa = *reinterpret_cast<unsigned long long*>(&av);
    unsigned long long bb = *reinterpret_cast<unsigned long long*>(&b);
    asm("fma.rn.f32x2 %0, %1, %2, %0;" : "+l"(dd) : "l"(aa), "l"(bb));
    d = *reinterpret_cast<float2*>(&dd);
}

// ===================== side kernel 1: cst3 (one block per v) =================
__global__ void cst3_kernel(const float* __restrict__ gpv, const float* __restrict__ gpr,
                            const float* __restrict__ pW, const float* __restrict__ pb,
                            const float* __restrict__ aW1, const float* __restrict__ ab1)
{
    __shared__ float pe[32];
    const int t = threadIdx.x;
    const int v = blockIdx.x;
    const float p0 = gpv[0] / gpr[0], p1 = gpv[1] / gpr[1];
    if (t < 32) pe[t] = fmaxf(pb[t] + p0 * pW[t] + p1 * pW[32 + t], 0.f);
    __syncthreads();
    const int c = t;
    const float* W = aW1 + ((size_t)v * 448 + 416) * 256 + c;
    float s = ab1[v * 256 + c];
#pragma unroll
    for (int k = 0; k < 32; k++) s += pe[k] * W[(size_t)k * 256];
    g_cst3[v][c] = s;
}

// ===================== side kernel 2: weight convert (fp16) ==================
__global__ void wconv_kernel(const float* __restrict__ bW2,
                             const float* __restrict__ aW1,
                             const float* __restrict__ aW2)
{
    constexpr int PERV = 65536 + 65536 + 32768 + 49152;   // 212992 elements
    const int total = V_ * PERV;
    for (int idx = blockIdx.x * blockDim.x + threadIdx.x; idx < total;
         idx += gridDim.x * blockDim.x) {
        const int v = idx / PERV;
        int e = idx % PERV;
        size_t dst;
        int n_local, kl;
        float w;
        if (e < 65536) {                        // L2: 2wg x 4 chunks
            const int wg = e >> 15, r = e & 32767;
            const int c = r >> 13, rr = r & 8191;
            n_local = rr >> 6; kl = rr & 63;
            const int n = wg * 128 + n_local, k = c * 64 + kl;
            w = bW2[((size_t)v * 256 + k) * 256 + n];
            dst = (size_t)wg * WGS + (size_t)c * CB;
        } else if (e < 131072) {                // L3
            e -= 65536;
            const int wg = e >> 15, r = e & 32767;
            const int c = r >> 13, rr = r & 8191;
            n_local = rr >> 6; kl = rr & 63;
            const int n = wg * 128 + n_local, k = c * 64 + kl;
            w = aW1[((size_t)v * 448 + k) * 256 + n];
            dst = (size_t)wg * WGS + L3o + (size_t)c * CB;
        } else if (e < 163840) {                // L4: 2wg x 2 merged chunks
            e -= 131072;
            const int wg = e >> 14, r = e & 16383;
            const int kk = r >> 12, rr = r & 4095;
            n_local = rr >> 6; kl = rr & 63;
            const int n = wg * 64 + n_local, k = kk * 64 + kl;
            w = aW2[((size_t)v * 256 + k) * 128 + n];
            dst = (size_t)wg * WGS + L4o + (size_t)(kk >> 1) * CB + (size_t)(kk & 1) * CB4;
        } else {                                // CTX: 2wg x 3 chunks (K pad 192)
            e -= 163840;
            const int wg = e / 24576, r = e % 24576;
            const int c = r >> 13, rr = r & 8191;
            n_local = rr >> 6; kl = rr & 63;
            const int n = wg * 128 + n_local, k = c * 64 + kl;
            w = (k < 160) ? aW1[((size_t)v * 448 + 256 + k) * 256 + n] : 0.f;
            dst = (size_t)wg * WGS + CTXo + (size_t)c * CB;
        }
        __half val = __float2half_rn(w);
        uint8_t* p = g_wB + (size_t)v * VSTRIDE + dst
                   + n_local * 128 + (((uint32_t)(kl * 2)) ^ (((uint32_t)n_local & 7) << 4));
        *reinterpret_cast<__half*>(p) = val;
    }
}

// ===================== per-wg prefetch + mainloop ============================
template <int CBT>
__device__ __forceinline__ void prefetch_wg(uint8_t* sb, const uint8_t* wsrc,
                                            int tw, int wg) {
    constexpr int NCP = CBT / 16 / 256;
    uint8_t* w0 = sb + OFF_W + wg * 32768;
#pragma unroll
    for (int i = 0; i < NCP; i++)
        cp16(w0 + (tw + i * 256) * 16, wsrc + (size_t)(tw + i * 256) * 16);
    CP_COMMIT();
#pragma unroll
    for (int i = 0; i < NCP; i++)
        cp16(w0 + CBT + (tw + i * 256) * 16, wsrc + CBT + (size_t)(tw + i * 256) * 16);
    CP_COMMIT();
}

// requires prefetch_wg<CBT>(wsrc) already issued (2 groups pending).
// Plain fp16: one pass per chunk. fkb = c*4.
// TRIM: ctx K pad — chunk 2 has only 2 real k-frags.
template <int NCHUNK, int NFRAG, int CBT, bool TRIM = false>
__device__ __forceinline__ void mma_loop_wg(
    uint8_t* sb, const uint8_t* wsrc, int tw, int wg, int lane,
    int aslot0, int nbase, float (*acc)[4])
{
    uint8_t* w0 = sb + OFF_W + wg * 32768;
    const uint4* AHI = (const uint4*)(sb + OFF_AHI);
    const uint32_t swzc = ((uint32_t)lane & 7) << 4;
    const int kadd = ((lane >> 3) & 1) * 8;
    constexpr int NCP = CBT / 16 / 256;
#pragma unroll 1
    for (int c = 0; c < NCHUNK; c++) {
        if (c < NCHUNK - 1) CP_WAIT1(); else CP_WAIT0();
        BARW(wg);
        const uint32_t wb = su32(w0 + (c & 1) * CBT);
        const int fkb = c * 4;
        const int scnt = (TRIM && c == 2) ? 2 : 4;
#pragma unroll
        for (int s = 0; s < 4; s++) {
            if (s < scnt) {
                const int fk = fkb + s;
                const uint4 ah = AHI[(aslot0 + fk) * 32 + lane];
                const int koff = s * 16 + kadd;
                const uint32_t ba = wb + (uint32_t)(nbase * 128)
                                  + (((uint32_t)(koff * 2)) ^ swzc);
#pragma unroll
                for (int jj = 0; jj < NFRAG / 2; jj++) {
                    uint32_t b0, b1, b2, b3;
                    LDSM4(b0, b1, b2, b3, ba + jj * 2048);
                    MMA_F16(acc[2 * jj],     ah, b0, b1);
                    MMA_F16(acc[2 * jj + 1], ah, b2, b3);
                }
            }
        }
        BARW(wg);
        if (c + 2 < NCHUNK) {
#pragma unroll
            for (int i = 0; i < NCP; i++)
                cp16(w0 + (c & 1) * CBT + (tw + i * 256) * 16,
                     wsrc + (size_t)(c + 2) * CBT + (size_t)(tw + i * 256) * 16);
            CP_COMMIT();
        }
    }
}

// L4 merged mainloop: 2 chunks of 16KB, each = two 8KB [64n][64k] sub-blocks.
__device__ __forceinline__ void mma_loop_l4(
    uint8_t* sb, const uint8_t* wsrc, int tw, int wg, int lane,
    int aslot0, int nbase, float (*acc)[4])
{
    uint8_t* w0 = sb + OFF_W + wg * 32768;
    const uint4* AHI = (const uint4*)(sb + OFF_AHI);
    const uint32_t swzc = ((uint32_t)lane & 7) << 4;
    const int kadd = ((lane >> 3) & 1) * 8;
#pragma unroll 1
    for (int c = 0; c < 2; c++) {
        if (c < 1) CP_WAIT1(); else CP_WAIT0();
        BARW(wg);
        const uint32_t wb = su32(w0 + (c & 1) * CB);
        const int fkb = c * 8;
#pragma unroll
        for (int s = 0; s < 8; s++) {
            const int fk = fkb + s;
            const uint4 ah = AHI[(aslot0 + fk) * 32 + lane];
            const int koff = (s & 3) * 16 + kadd;
            const uint32_t ba = wb + (uint32_t)((s >> 2) * 8192)
                              + (uint32_t)(nbase * 128)
                              + (((uint32_t)(koff * 2)) ^ swzc);
#pragma unroll
            for (int jj = 0; jj < 4; jj++) {
                uint32_t b0, b1, b2, b3;
                LDSM4(b0, b1, b2, b3, ba + jj * 2048);
                MMA_F16(acc[2 * jj],     ah, b0, b1);
                MMA_F16(acc[2 * jj + 1], ah, b2, b3);
            }
        }
        BARW(wg);
    }
}

// ===================== epilogue: C frags -> A frags (hi-only) ===============
// wn = warpgroup id (column half). MODE 0: bias; MODE 1: per-node ctxp.
template <int MODE>
__device__ __forceinline__ void epiA(
    uint8_t* sbH, float (*acc)[4], const float* __restrict__ addv,
    int wm, int wn, int lane)
{
    uint4* AHI = (uint4*)(sbH + OFF_AHI);
    const int quad = lane >> 2, q4 = lane & 3;
    const int r0 = 16 * wm + quad;
    int n0 = r0 / 7;       if (n0 > 17) n0 = 17;
    int n1 = (r0 + 8) / 7; if (n1 > 17) n1 = 17;
#pragma unroll
    for (int u = 0; u < 8; u++) {
        const int c0 = wn * 128 + 16 * u + 2 * q4;
        const int c2 = c0 + 8;
        float2 a00, a01, a10, a11;
        if constexpr (MODE == 0) {
            a00 = *(const float2*)(addv + c0);
            a01 = *(const float2*)(addv + c2);
            a10 = a00; a11 = a01;
        } else {
            a00 = *(const float2*)(addv + n0 * 260 + c0);
            a01 = *(const float2*)(addv + n0 * 260 + c2);
            a10 = *(const float2*)(addv + n1 * 260 + c0);
            a11 = *(const float2*)(addv + n1 * 260 + c2);
        }
        const uint32_t h0 = relu_hi(acc[2*u][0]   + a00.x, acc[2*u][1]   + a00.y);
        const uint32_t h1 = relu_hi(acc[2*u][2]   + a10.x, acc[2*u][3]   + a10.y);
        const uint32_t h2 = relu_hi(acc[2*u+1][0] + a01.x, acc[2*u+1][1] + a01.y);
        const uint32_t h3 = relu_hi(acc[2*u+1][2] + a11.x, acc[2*u+1][3] + a11.y);
        const int fi = (wm * 16 + 8 * wn + u) * 32 + lane;
        AHI[fi] = make_uint4(h0, h1, h2, h3);
    }
}

// ============================ main kernel ====================================
__global__ void __launch_bounds__(NT, 1)
surface_kernel(
    const float* __restrict__ centers,  const float* __restrict__ enc_g,
    const float* __restrict__ enc_node, const float* __restrict__ neighbors,
    const float* __restrict__ normals,  const float* __restrict__ neigh_normals,
    const float* __restrict__ areas,    const float* __restrict__ neigh_areas,
    const float* __restrict__ basis_W1, const float* __restrict__ basis_b1,
    const float* __restrict__ basis_b2, const float* __restrict__ agg_b2,
    const float* __restrict__ agg_W3,   const float* __restrict__ agg_b3,
    float* __restrict__ out, const int n_nodes)
{
    extern __shared__ uint8_t sb[];
    const int t = threadIdx.x;
    const int wid = t >> 5, lane = t & 31;
    const int wg = t >> 8;             // warpgroup 0/1 == column half
    const int tw = t & 255;            // thread index within wg
    const int widg = wid & 7;          // warp within wg == wm
    const int quad = lane >> 2, q4 = lane & 3;
    const int base = blockIdx.x * NPC;

    float* ctxps = (float*)(sb + OFF_CTXP);
    float* svol  = (float*)(sb + OFF_SVOL);
    float* W1s   = (float*)(sb + OFF_W1S);
    float* b1s   = (float*)(sb + OFF_B1S);
    float* b2s   = (float*)(sb + OFF_B2S);
    float* b4s   = (float*)(sb + OFF_B4S);
    float* w3s   = (float*)(sb + OFF_W3S);
    float* arowp = (float*)(sb + OFF_ARP);
    float* arow  = (float*)(sb + OFF_ARW);
    float* invd  = (float*)(sb + OFF_INVD);
    float* dsum  = (float*)(sb + OFF_DSUM);

    // prefetch v=0 ctx chunks (per wg stream)
    prefetch_wg<CB>(sb, g_wB + (size_t)wg * WGS + CTXo, tw, wg);

    // ---- build vol rows ----
    if (t < 128) {
        float f[8] = {0.f,0.f,0.f,0.f,0.f,0.f,0.f,0.f};
        const int nl = t / PP, p = t % PP;
        const int node = base + nl;
        if (t < ROWS_ && node < n_nodes) {
            if (p == 0) {
                f[0]=centers[node*3+0]; f[1]=centers[node*3+1]; f[2]=centers[node*3+2];
                f[3]=normals[node*3+0]; f[4]=normals[node*3+1]; f[5]=normals[node*3+2];
                f[6]=logf(areas[node]) * 0.1f;
            } else {
                const int nb = node * NK + (p - 1);
                f[0]=neighbors[nb*3+0]+1e-6f; f[1]=neighbors[nb*3+1]+1e-6f;
                f[2]=neighbors[nb*3+2]+1e-6f;
                f[3]=neigh_normals[nb*3+0]+1e-6f; f[4]=neigh_normals[nb*3+1]+1e-6f;
                f[5]=neigh_normals[nb*3+2]+1e-6f;
                f[6]=logf(neigh_areas[nb]) * 0.1f + 1e-6f;
            }
        }
#pragma unroll
        for (int q = 0; q < 8; q++) svol[t * 8 + q] = f[q];
    }
    __syncthreads();
    if (t < NPC * NK) {
        const int nl = t / NK, j = t % NK;
        float d2 = 0.f;
#pragma unroll
        for (int q = 0; q < 7; q++) {
            const float d = svol[(nl*7)*8 + q] - svol[(nl*7 + 1 + j)*8 + q];
            d2 += d * d;
        }
        invd[nl * 8 + j] = 1.f / sqrtf(d2);
    }
    __syncthreads();
    if (t < NPC) {
        float s = 0.f;
#pragma unroll
        for (int j = 0; j < NK; j++) s += invd[t * 8 + j];
        dsum[t] = s;
    }

    const int r0m = 16 * widg + quad;
    float sv0[7], sv1[7];
#pragma unroll
    for (int q = 0; q < 7; q++) {
        sv0[q] = svol[r0m * 8 + q];
        sv1[q] = svol[(r0m + 8) * 8 + q];
    }

#pragma unroll 1
    for (int v = 0; v < V_; v++) {
        const uint8_t* wv = g_wB + (size_t)v * VSTRIDE + (size_t)wg * WGS;
        // per-v constants
        for (int i = t; i < 1792; i += NT) W1s[i] = __ldg(basis_W1 + (size_t)v * 1792 + i);
        if (t < 256) { b1s[t] = __ldg(basis_b1 + v * 256 + t);
                       b2s[t] = __ldg(basis_b2 + v * 256 + t); }
        else if (t < 384) { b4s[t-256] = __ldg(agg_b2 + v * 128 + (t-256)); }
        else { w3s[t-384] = __ldg(agg_W3 + v * 128 + (t-384)); }

        // ---- build ctx A frags (full CTA; M=32, K padded to 192) ----
        {
            uint4* AHI = (uint4*)(sb + OFF_AHI);
#pragma unroll
            for (int rep = 0; rep < 2; rep++) {
                const int slot = wid + rep * 16;
                if (slot < 24) {
                    const int fm = slot / 12, fk = slot % 12;
                    const int rr0 = fm * 16 + quad, rr1 = rr0 + 8;
                    const int cc0 = fk * 16 + 2 * q4, cc1 = cc0 + 8;
                    float2 vv[4];
                    const int rs[2] = {rr0, rr1};
                    const int cs[2] = {cc0, cc1};
#pragma unroll
                    for (int a = 0; a < 4; a++) {
                        const int r = rs[a & 1], cc = cs[a >> 1];
                        const int node = base + r;
                        float2 val = make_float2(0.f, 0.f);
                        if (r < NPC && node < n_nodes && cc < 160) {
                            if (cc < 32) val = *(const float2*)(enc_node + (size_t)node*32 + cc);
                            else         val = *(const float2*)(enc_g + (size_t)node*128 + (cc-32));
                        }
                        vv[a] = val;
                    }
                    AHI[slot * 32 + lane] = make_uint4(
                        pack_h2(vv[0].x, vv[0].y), pack_h2(vv[1].x, vv[1].y),
                        pack_h2(vv[2].x, vv[2].y), pack_h2(vv[3].x, vv[3].y));
                }
            }
        }
        __syncthreads();

        // ---- ctx GEMM: ctxps[18][wg cols] = ctx @ Wctx + cst3 ----
        {
            const int cwm = widg & 1, cwn = widg >> 1;     // 2m x 4n within wg
            float cacc[4][4];
#pragma unroll
            for (int i = 0; i < 4; i++)
#pragma unroll
                for (int j = 0; j < 4; j++) cacc[i][j] = 0.f;
            const int cnbase = cwn * 32 + 8 * ((lane >> 4) & 1) + (lane & 7);
            mma_loop_wg<3, 4, CB, true>(sb, wv + CTXo,
                                        tw, wg, lane, cwm * 12, cnbase, cacc);
            prefetch_wg<CB>(sb, wv, tw, wg);   // L2 chunks
            // ctx epilogue (cols disjoint per wg; read later by same wg only)
            const int rr0 = cwm * 16 + quad;
            const float* cstv = g_cst3[v];
#pragma unroll
            for (int jj = 0; jj < 2; jj++)
#pragma unroll
                for (int e = 0; e < 2; e++) {
                    const int col = wg * 128 + cwn * 32 + jj * 16 + e * 8 + 2 * q4;
                    const float2 cst = *(const float2*)(cstv + col);
                    const float* a = cacc[2 * jj + e];
                    if (rr0 < NPC && base + rr0 < n_nodes)
                        *(float2*)(ctxps + rr0 * 260 + col) =
                            make_float2(a[0] + cst.x, a[1] + cst.y);
                    if (rr0 + 8 < NPC && base + rr0 + 8 < n_nodes)
                        *(float2*)(ctxps + (rr0 + 8) * 260 + col) =
                            make_float2(a[2] + cst.x, a[3] + cst.y);
                }
        }
        __syncthreads();   // ctx A slots free; L1 overwrites them

        // ---- L1: produce A frags directly (overlaps L2 weight copies) ----
        {
            uint4* AHI = (uint4*)(sb + OFF_AHI);
#pragma unroll
            for (int u = 0; u < 8; u++) {
                const int c0 = wg * 128 + 16 * u + 2 * q4;
                const int c2 = c0 + 8;
                float2 a00 = *(const float2*)(b1s + c0);
                float2 a01 = *(const float2*)(b1s + c2);
                float2 a10 = a00, a11 = a01;
#pragma unroll
                for (int q = 0; q < 7; q++) {
                    const float2 w0 = *(const float2*)(W1s + q * 256 + c0);
                    const float2 w2 = *(const float2*)(W1s + q * 256 + c2);
                    ffma2s(a00, sv0[q], w0); ffma2s(a01, sv0[q], w2);
                    ffma2s(a10, sv1[q], w0); ffma2s(a11, sv1[q], w2);
                }
                const int fi = (widg * 16 + 8 * wg + u) * 32 + lane;
                AHI[fi] = make_uint4(
                    relu_hi(a00.x, a00.y), relu_hi(a10.x, a10.y),
                    relu_hi(a01.x, a01.y), relu_hi(a11.x, a11.y));
            }
        }
        __syncthreads();

        const int nbase = 8 * ((lane >> 4) & 1) + (lane & 7);
        // ---- L2 ----
        {
            float acc[16][4];
#pragma unroll
            for (int i = 0; i < 16; i++)
#pragma unroll
                for (int j = 0; j < 4; j++) acc[i][j] = 0.f;
            mma_loop_wg<4, 16, CB>(sb, wv, tw, wg, lane, widg * 16, nbase, acc);
            prefetch_wg<CB>(sb, wv + L3o, tw, wg);
            __syncthreads();   // both wgs done reading L1 A-frags
            epiA<0>(sb, acc, b2s, widg, wg, lane);
        }
        __syncthreads();
        // ---- L3 ----
        {
            float acc[16][4];
#pragma unroll
            for (int i = 0; i < 16; i++)
#pragma unroll
                for (int j = 0; j < 4; j++) acc[i][j] = 0.f;
            mma_loop_wg<4, 16, CB>(sb, wv + L3o, tw, wg, lane, widg * 16, nbase, acc);
            prefetch_wg<CB>(sb, wv + L4o, tw, wg);
            __syncthreads();
            epiA<1>(sb, acc, ctxps, widg, wg, lane);
        }
        __syncthreads();
        // ---- L4 + L5 ----
        {
            float acc[8][4];
#pragma unroll
            for (int i = 0; i < 8; i++)
#pragma unroll
                for (int j = 0; j < 4; j++) acc[i][j] = 0.f;
            mma_loop_l4(sb, wv + L4o, tw, wg, lane, widg * 16, nbase, acc);
            if (v + 1 < V_)
                prefetch_wg<CB>(sb, wv + VSTRIDE + CTXo, tw, wg);
            float s0 = 0.f, s1 = 0.f;
#pragma unroll
            for (int j = 0; j < 8; j++) {
                const int c0 = wg * 64 + 8 * j + 2 * q4;
                const float w30 = w3s[c0], w31 = w3s[c0 + 1];
                const float bb0 = b4s[c0], bb1 = b4s[c0 + 1];
                s0 += fmaxf(acc[j][0] + bb0, 0.f) * w30 + fmaxf(acc[j][1] + bb1, 0.f) * w31;
                s1 += fmaxf(acc[j][2] + bb0, 0.f) * w30 + fmaxf(acc[j][3] + bb1, 0.f) * w31;
            }
            s0 += __shfl_xor_sync(0xffffffffu, s0, 1);
            s0 += __shfl_xor_sync(0xffffffffu, s0, 2);
            s1 += __shfl_xor_sync(0xffffffffu, s1, 1);
            s1 += __shfl_xor_sync(0xffffffffu, s1, 2);
            if (q4 == 0) {
                arowp[wg * 128 + r0m] = s0;
                arowp[wg * 128 + r0m + 8] = s1;
            }
        }
        __syncthreads();
        if (t < 128) arow[t] = arowp[t] + arowp[128 + t] + __ldg(agg_b3 + v);
        __syncthreads();
        if (t < NPC) {
            const int node = base + t;
            if (node < n_nodes) {
                const float c = arow[t * 7];
                float s = 0.f;
#pragma unroll
                for (int j = 0; j < NK; j++) s += arow[t * 7 + 1 + j] * invd[t * 8 + j];
                out[node * V_ + v] = 0.5f * c + 0.5f * s / dsum[t];
            }
        }
        __syncthreads();
    }
}

// ============================ launcher =======================================
extern "C" void kernel_launch(void* const* d_in, const int* in_sizes, int n_in,
                              void* d_out, int out_size)
{
    const float* centers       = (const float*)d_in[0];
    const float* enc_g         = (const float*)d_in[1];
    const float* enc_node      = (const float*)d_in[2];
    const float* neighbors     = (const float*)d_in[3];
    const float* normals       = (const float*)d_in[4];
    const float* neigh_normals = (const float*)d_in[5];
    const float* areas         = (const float*)d_in[6];
    const float* neigh_areas   = (const float*)d_in[7];
    const float* gpv           = (const float*)d_in[8];
    const float* gpr           = (const float*)d_in[9];
    const float* param_W       = (const float*)d_in[10];
    const float* param_b       = (const float*)d_in[11];
    const float* basis_W1      = (const float*)d_in[12];
    const float* basis_b1      = (const float*)d_in[13];
    const float* basis_W2      = (const float*)d_in[14];
    const float* basis_b2      = (const float*)d_in[15];
    const float* agg_W1        = (const float*)d_in[16];
    const float* agg_b1        = (const float*)d_in[17];
    const float* agg_W2        = (const float*)d_in[18];
    const float* agg_b2        = (const float*)d_in[19];
    const float* agg_W3        = (const float*)d_in[20];
    const float* agg_b3        = (const float*)d_in[21];
    float* out = (float*)d_out;

    const int n_nodes = in_sizes[0] / 3;
    const int grid = (n_nodes + NPC - 1) / NPC;

    cudaFuncSetAttribute(surface_kernel,
                         cudaFuncAttributeMaxDynamicSharedMemorySize, SMEM_BYTES);

    cst3_kernel<<<V_, 256>>>(gpv, gpr, param_W, param_b, agg_W1, agg_b1);
    wconv_kernel<<<2560, 512>>>(basis_W2, agg_W1, agg_W2);
    surface_kernel<<<grid, NT, SMEM_BYTES>>>(
        centers, enc_g, enc_node, neighbors, normals, neigh_normals,
        areas, neigh_areas,
        basis_W1, basis_b1, basis_b2, agg_b2, agg_W3, agg_b3, out, n_nodes);
}

// round 17
// speedup vs baseline: 10.1219x; 1.0380x over previous
#include <cuda_runtime.h>
#include <cuda_fp16.h>
#include <math.h>
#include <stdint.h>

constexpr int V_ = 4;
constexpr int NK = 6;
constexpr int PP = 7;
constexpr int NPC = 18;
constexpr int ROWS_ = 126;
constexpr int NT = 512;

// weight blob per v, per-warpgroup streams of fp16 [128n][64k] (16KB) chunks.
// Plain fp16 (fp32 accum). Per wg: L2 4 chunks, L3 4, L4 2 (merged,
// each two 8KB [64n][64k] subs), CTX 3 (K padded 160->192, chunk2 half-real).
constexpr int CB  = 16384;
constexpr int CB4 = 8192;
constexpr int WGS   = 13 * CB;       // per-wg stream: 212992
constexpr int L3o   = 4 * CB;
constexpr int L4o   = 8 * CB;
constexpr int CTXo  = 10 * CB;
constexpr int VSTRIDE = 2 * WGS;     // 425984

__device__ uint8_t g_wB[(size_t)V_ * VSTRIDE];
__device__ float   g_cst3[V_][256];

// ---- smem byte offsets ----
constexpr int OFF_W    = 0;        // 65536: wg0 [0,32K), wg1 [32K,64K)
constexpr int OFF_AHI  = 65536;    // 65536 (A frags: 128 slots x 512B)
constexpr int OFF_ACX  = 131072;   // 12288 (ctx A frags: 24 slots, v-invariant)
constexpr int OFF_CTXP = 196608;   // 18*260*4 = 18720
constexpr int OFF_SVOL = 215328;   // 4096
constexpr int OFF_W1S  = 219424;   // 7168
constexpr int OFF_B1S  = 226592;   // 1024
constexpr int OFF_B2S  = 227616;   // 1024
constexpr int OFF_B4S  = 228640;   // 512
constexpr int OFF_W3S  = 229152;   // 512
constexpr int OFF_ARP  = 229664;   // 1024
constexpr int OFF_ARW  = 230688;   // 512
constexpr int OFF_INVD = 231200;   // 576
constexpr int OFF_DSUM = 231776;   // 96
constexpr int SMEM_BYTES = 231872;

// ============================ PTX helpers ====================================
__device__ __forceinline__ uint32_t su32(const void* p) {
    return (uint32_t)__cvta_generic_to_shared(p);
}
__device__ __forceinline__ void cp16(uint8_t* s, const uint8_t* g) {
    uint32_t sa = su32(s);
    asm volatile("cp.async.cg.shared.global [%0], [%1], 16;" :: "r"(sa), "l"(g));
}
#define CP_COMMIT() asm volatile("cp.async.commit_group;" ::: "memory")
#define CP_WAIT1()  asm volatile("cp.async.wait_group 1;" ::: "memory")
#define CP_WAIT0()  asm volatile("cp.async.wait_group 0;" ::: "memory")
// per-warpgroup named barrier (ids 1,2), 256 threads each
#define BARW(g) asm volatile("bar.sync %0, %1;" :: "r"((g) + 1), "r"(256) : "memory")

#define MMA_F16(acc, a, b0, b1) asm volatile( \
    "mma.sync.aligned.m16n8k16.row.col.f32.f16.f16.f32 " \
    "{%0,%1,%2,%3}, {%4,%5,%6,%7}, {%8,%9}, {%0,%1,%2,%3};" \
    : "+f"((acc)[0]), "+f"((acc)[1]), "+f"((acc)[2]), "+f"((acc)[3]) \
    : "r"((a).x), "r"((a).y), "r"((a).z), "r"((a).w), "r"(b0), "r"(b1))

#define LDSM4(r0, r1, r2, r3, addr) asm volatile( \
    "ldmatrix.sync.aligned.m8n8.x4.shared.b16 {%0,%1,%2,%3}, [%4];" \
    : "=r"(r0), "=r"(r1), "=r"(r2), "=r"(r3) : "r"(addr))

__device__ __forceinline__ uint32_t relu_hi(float x, float y) {
    x = fmaxf(x, 0.f); y = fmaxf(y, 0.f);
    __half2 hh = __floats2half2_rn(x, y);
    return *reinterpret_cast<uint32_t*>(&hh);
}
__device__ __forceinline__ uint32_t pack_h2(float x, float y) {
    __half2 hh = __floats2half2_rn(x, y);
    return *reinterpret_cast<uint32_t*>(&hh);
}
__device__ __forceinline__ void ffma2s(float2& d, float a, float2 b) {
    unsigned long long dd = *reinterpret_cast<unsigned long long*>(&d);
    float2 av = make_float2(a, a);
    unsigned long long aa = *reinterpret_cast<unsigned long long*>(&av);
    unsigned long long bb = *reinterpret_cast<unsigned long long*>(&b);
    asm("fma.rn.f32x2 %0, %1, %2, %0;" : "+l"(dd) : "l"(aa), "l"(bb));
    d = *reinterpret_cast<float2*>(&dd);
}

// ===================== side kernel 1: cst3 (one block per v) =================
__global__ void cst3_kernel(const float* __restrict__ gpv, const float* __restrict__ gpr,
                            const float* __restrict__ pW, const float* __restrict__ pb,
                            const float* __restrict__ aW1, const float* __restrict__ ab1)
{
    __shared__ float pe[32];
    const int t = threadIdx.x;
    const int v = blockIdx.x;
    const float p0 = gpv[0] / gpr[0], p1 = gpv[1] / gpr[1];
    if (t < 32) pe[t] = fmaxf(pb[t] + p0 * pW[t] + p1 * pW[32 + t], 0.f);
    __syncthreads();
    const int c = t;
    const float* W = aW1 + ((size_t)v * 448 + 416) * 256 + c;
    float s = ab1[v * 256 + c];
#pragma unroll
    for (int k = 0; k < 32; k++) s += pe[k] * W[(size_t)k * 256];
    g_cst3[v][c] = s;
}

// ===================== side kernel 2: weight convert (fp16) ==================
__global__ void wconv_kernel(const float* __restrict__ bW2,
                             const float* __restrict__ aW1,
                             const float* __restrict__ aW2)
{
    constexpr int PERV = 65536 + 65536 + 32768 + 49152;   // 212992 elements
    const int total = V_ * PERV;
    for (int idx = blockIdx.x * blockDim.x + threadIdx.x; idx < total;
         idx += gridDim.x * blockDim.x) {
        const int v = idx / PERV;
        int e = idx % PERV;
        size_t dst;
        int n_local, kl;
        float w;
        if (e < 65536) {                        // L2: 2wg x 4 chunks
            const int wg = e >> 15, r = e & 32767;
            const int c = r >> 13, rr = r & 8191;
            n_local = rr >> 6; kl = rr & 63;
            const int n = wg * 128 + n_local, k = c * 64 + kl;
            w = bW2[((size_t)v * 256 + k) * 256 + n];
            dst = (size_t)wg * WGS + (size_t)c * CB;
        } else if (e < 131072) {                // L3
            e -= 65536;
            const int wg = e >> 15, r = e & 32767;
            const int c = r >> 13, rr = r & 8191;
            n_local = rr >> 6; kl = rr & 63;
            const int n = wg * 128 + n_local, k = c * 64 + kl;
            w = aW1[((size_t)v * 448 + k) * 256 + n];
            dst = (size_t)wg * WGS + L3o + (size_t)c * CB;
        } else if (e < 163840) {                // L4: 2wg x 2 merged chunks
            e -= 131072;
            const int wg = e >> 14, r = e & 16383;
            const int kk = r >> 12, rr = r & 4095;
            n_local = rr >> 6; kl = rr & 63;
            const int n = wg * 64 + n_local, k = kk * 64 + kl;
            w = aW2[((size_t)v * 256 + k) * 128 + n];
            dst = (size_t)wg * WGS + L4o + (size_t)(kk >> 1) * CB + (size_t)(kk & 1) * CB4;
        } else {                                // CTX: 2wg x 3 chunks (K pad 192)
            e -= 163840;
            const int wg = e / 24576, r = e % 24576;
            const int c = r >> 13, rr = r & 8191;
            n_local = rr >> 6; kl = rr & 63;
            const int n = wg * 128 + n_local, k = c * 64 + kl;
            w = (k < 160) ? aW1[((size_t)v * 448 + 256 + k) * 256 + n] : 0.f;
            dst = (size_t)wg * WGS + CTXo + (size_t)c * CB;
        }
        __half val = __float2half_rn(w);
        uint8_t* p = g_wB + (size_t)v * VSTRIDE + dst
                   + n_local * 128 + (((uint32_t)(kl * 2)) ^ (((uint32_t)n_local & 7) << 4));
        *reinterpret_cast<__half*>(p) = val;
    }
}

// ===================== per-wg prefetch + mainloop ============================
template <int CBT>
__device__ __forceinline__ void prefetch_wg(uint8_t* sb, const uint8_t* wsrc,
                                            int tw, int wg) {
    constexpr int NCP = CBT / 16 / 256;
    uint8_t* w0 = sb + OFF_W + wg * 32768;
#pragma unroll
    for (int i = 0; i < NCP; i++)
        cp16(w0 + (tw + i * 256) * 16, wsrc + (size_t)(tw + i * 256) * 16);
    CP_COMMIT();
#pragma unroll
    for (int i = 0; i < NCP; i++)
        cp16(w0 + CBT + (tw + i * 256) * 16, wsrc + CBT + (size_t)(tw + i * 256) * 16);
    CP_COMMIT();
}

// requires prefetch_wg<CBT>(wsrc) already issued (2 groups pending).
// Plain fp16: one pass per chunk. fkb = c*4.
// TRIM: ctx K pad — chunk 2 has only 2 real k-frags.
template <int NCHUNK, int NFRAG, int CBT, bool TRIM = false>
__device__ __forceinline__ void mma_loop_wg(
    uint8_t* sb, const uint8_t* wsrc, const uint4* __restrict__ Ab,
    int tw, int wg, int lane, int aslot0, int nbase, float (*acc)[4])
{
    uint8_t* w0 = sb + OFF_W + wg * 32768;
    const uint32_t swzc = ((uint32_t)lane & 7) << 4;
    const int kadd = ((lane >> 3) & 1) * 8;
    constexpr int NCP = CBT / 16 / 256;
#pragma unroll 1
    for (int c = 0; c < NCHUNK; c++) {
        if (c < NCHUNK - 1) CP_WAIT1(); else CP_WAIT0();
        BARW(wg);
        const uint32_t wb = su32(w0 + (c & 1) * CBT);
        const int fkb = c * 4;
        const int scnt = (TRIM && c == 2) ? 2 : 4;
#pragma unroll
        for (int s = 0; s < 4; s++) {
            if (s < scnt) {
                const int fk = fkb + s;
                const uint4 ah = Ab[(aslot0 + fk) * 32 + lane];
                const int koff = s * 16 + kadd;
                const uint32_t ba = wb + (uint32_t)(nbase * 128)
                                  + (((uint32_t)(koff * 2)) ^ swzc);
#pragma unroll
                for (int jj = 0; jj < NFRAG / 2; jj++) {
                    uint32_t b0, b1, b2, b3;
                    LDSM4(b0, b1, b2, b3, ba + jj * 2048);
                    MMA_F16(acc[2 * jj],     ah, b0, b1);
                    MMA_F16(acc[2 * jj + 1], ah, b2, b3);
                }
            }
        }
        BARW(wg);
        if (c + 2 < NCHUNK) {
#pragma unroll
            for (int i = 0; i < NCP; i++)
                cp16(w0 + (c & 1) * CBT + (tw + i * 256) * 16,
                     wsrc + (size_t)(c + 2) * CBT + (size_t)(tw + i * 256) * 16);
            CP_COMMIT();
        }
    }
}

// L4 one-shot: both 16KB buffers (4 x 8KB [64n][64k] subs) in one barrier window.
__device__ __forceinline__ void mma_loop_l4(
    uint8_t* sb, const uint4* __restrict__ Ab, int wg, int lane,
    int aslot0, int nbase, float (*acc)[4])
{
    uint8_t* w0 = sb + OFF_W + wg * 32768;
    const uint32_t swzc = ((uint32_t)lane & 7) << 4;
    const int kadd = ((lane >> 3) & 1) * 8;
    CP_WAIT0();
    BARW(wg);
#pragma unroll
    for (int c = 0; c < 2; c++) {
        const uint32_t wb = su32(w0 + c * CB);
        const int fkb = c * 8;
#pragma unroll
        for (int s = 0; s < 8; s++) {
            const int fk = fkb + s;
            const uint4 ah = Ab[(aslot0 + fk) * 32 + lane];
            const int koff = (s & 3) * 16 + kadd;
            const uint32_t ba = wb + (uint32_t)((s >> 2) * 8192)
                              + (uint32_t)(nbase * 128)
                              + (((uint32_t)(koff * 2)) ^ swzc);
#pragma unroll
            for (int jj = 0; jj < 4; jj++) {
                uint32_t b0, b1, b2, b3;
                LDSM4(b0, b1, b2, b3, ba + jj * 2048);
                MMA_F16(acc[2 * jj],     ah, b0, b1);
                MMA_F16(acc[2 * jj + 1], ah, b2, b3);
            }
        }
    }
    BARW(wg);
}

// ===================== epilogue: C frags -> A frags (hi-only) ===============
// wn = warpgroup id (column half). MODE 0: bias; MODE 1: per-node ctxp.
template <int MODE>
__device__ __forceinline__ void epiA(
    uint8_t* sbH, float (*acc)[4], const float* __restrict__ addv,
    int wm, int wn, int lane)
{
    uint4* AHI = (uint4*)(sbH + OFF_AHI);
    const int quad = lane >> 2, q4 = lane & 3;
    const int r0 = 16 * wm + quad;
    int n0 = r0 / 7;       if (n0 > 17) n0 = 17;
    int n1 = (r0 + 8) / 7; if (n1 > 17) n1 = 17;
#pragma unroll
    for (int u = 0; u < 8; u++) {
        const int c0 = wn * 128 + 16 * u + 2 * q4;
        const int c2 = c0 + 8;
        float2 a00, a01, a10, a11;
        if constexpr (MODE == 0) {
            a00 = *(const float2*)(addv + c0);
            a01 = *(const float2*)(addv + c2);
            a10 = a00; a11 = a01;
        } else {
            a00 = *(const float2*)(addv + n0 * 260 + c0);
            a01 = *(const float2*)(addv + n0 * 260 + c2);
            a10 = *(const float2*)(addv + n1 * 260 + c0);
            a11 = *(const float2*)(addv + n1 * 260 + c2);
        }
        const uint32_t h0 = relu_hi(acc[2*u][0]   + a00.x, acc[2*u][1]   + a00.y);
        const uint32_t h1 = relu_hi(acc[2*u][2]   + a10.x, acc[2*u][3]   + a10.y);
        const uint32_t h2 = relu_hi(acc[2*u+1][0] + a01.x, acc[2*u+1][1] + a01.y);
        const uint32_t h3 = relu_hi(acc[2*u+1][2] + a11.x, acc[2*u+1][3] + a11.y);
        const int fi = (wm * 16 + 8 * wn + u) * 32 + lane;
        AHI[fi] = make_uint4(h0, h1, h2, h3);
    }
}

// ============================ main kernel ====================================
__global__ void __launch_bounds__(NT, 1)
surface_kernel(
    const float* __restrict__ centers,  const float* __restrict__ enc_g,
    const float* __restrict__ enc_node, const float* __restrict__ neighbors,
    const float* __restrict__ normals,  const float* __restrict__ neigh_normals,
    const float* __restrict__ areas,    const float* __restrict__ neigh_areas,
    const float* __restrict__ basis_W1, const float* __restrict__ basis_b1,
    const float* __restrict__ basis_b2, const float* __restrict__ agg_b2,
    const float* __restrict__ agg_W3,   const float* __restrict__ agg_b3,
    float* __restrict__ out, const int n_nodes)
{
    extern __shared__ uint8_t sb[];
    const int t = threadIdx.x;
    const int wid = t >> 5, lane = t & 31;
    const int wg = t >> 8;             // warpgroup 0/1 == column half
    const int tw = t & 255;            // thread index within wg
    const int widg = wid & 7;          // warp within wg == wm
    const int quad = lane >> 2, q4 = lane & 3;
    const int base = blockIdx.x * NPC;

    float* ctxps = (float*)(sb + OFF_CTXP);
    float* svol  = (float*)(sb + OFF_SVOL);
    float* W1s   = (float*)(sb + OFF_W1S);
    float* b1s   = (float*)(sb + OFF_B1S);
    float* b2s   = (float*)(sb + OFF_B2S);
    float* b4s   = (float*)(sb + OFF_B4S);
    float* w3s   = (float*)(sb + OFF_W3S);
    float* arowp = (float*)(sb + OFF_ARP);
    float* arow  = (float*)(sb + OFF_ARW);
    float* invd  = (float*)(sb + OFF_INVD);
    float* dsum  = (float*)(sb + OFF_DSUM);
    const uint4* Amain = (const uint4*)(sb + OFF_AHI);
    const uint4* Actx  = (const uint4*)(sb + OFF_ACX);

    // prefetch v=0 ctx chunks (per wg stream)
    prefetch_wg<CB>(sb, g_wB + (size_t)wg * WGS + CTXo, tw, wg);

    // ---- build vol rows ----
    if (t < 128) {
        float f[8] = {0.f,0.f,0.f,0.f,0.f,0.f,0.f,0.f};
        const int nl = t / PP, p = t % PP;
        const int node = base + nl;
        if (t < ROWS_ && node < n_nodes) {
            if (p == 0) {
                f[0]=centers[node*3+0]; f[1]=centers[node*3+1]; f[2]=centers[node*3+2];
                f[3]=normals[node*3+0]; f[4]=normals[node*3+1]; f[5]=normals[node*3+2];
                f[6]=logf(areas[node]) * 0.1f;
            } else {
                const int nb = node * NK + (p - 1);
                f[0]=neighbors[nb*3+0]+1e-6f; f[1]=neighbors[nb*3+1]+1e-6f;
                f[2]=neighbors[nb*3+2]+1e-6f;
                f[3]=neigh_normals[nb*3+0]+1e-6f; f[4]=neigh_normals[nb*3+1]+1e-6f;
                f[5]=neigh_normals[nb*3+2]+1e-6f;
                f[6]=logf(neigh_areas[nb]) * 0.1f + 1e-6f;
            }
        }
#pragma unroll
        for (int q = 0; q < 8; q++) svol[t * 8 + q] = f[q];
    }
    __syncthreads();
    if (t < NPC * NK) {
        const int nl = t / NK, j = t % NK;
        float d2 = 0.f;
#pragma unroll
        for (int q = 0; q < 7; q++) {
            const float d = svol[(nl*7)*8 + q] - svol[(nl*7 + 1 + j)*8 + q];
            d2 += d * d;
        }
        invd[nl * 8 + j] = 1.f / sqrtf(d2);
    }
    __syncthreads();
    if (t < NPC) {
        float s = 0.f;
#pragma unroll
        for (int j = 0; j < NK; j++) s += invd[t * 8 + j];
        dsum[t] = s;
    }

    // ---- build ctx A frags ONCE (v-invariant; M=32, K padded to 192) ----
    {
        uint4* ACX = (uint4*)(sb + OFF_ACX);
#pragma unroll
        for (int rep = 0; rep < 2; rep++) {
            const int slot = wid + rep * 16;
            if (slot < 24) {
                const int fm = slot / 12, fk = slot % 12;
                const int rr0 = fm * 16 + quad, rr1 = rr0 + 8;
                const int cc0 = fk * 16 + 2 * q4, cc1 = cc0 + 8;
                float2 vv[4];
                const int rs[2] = {rr0, rr1};
                const int cs[2] = {cc0, cc1};
#pragma unroll
                for (int a = 0; a < 4; a++) {
                    const int r = rs[a & 1], cc = cs[a >> 1];
                    const int node = base + r;
                    float2 val = make_float2(0.f, 0.f);
                    if (r < NPC && node < n_nodes && cc < 160) {
                        if (cc < 32) val = *(const float2*)(enc_node + (size_t)node*32 + cc);
                        else         val = *(const float2*)(enc_g + (size_t)node*128 + (cc-32));
                    }
                    vv[a] = val;
                }
                ACX[slot * 32 + lane] = make_uint4(
                    pack_h2(vv[0].x, vv[0].y), pack_h2(vv[1].x, vv[1].y),
                    pack_h2(vv[2].x, vv[2].y), pack_h2(vv[3].x, vv[3].y));
            }
        }
    }

    const int r0m = 16 * widg + quad;
    float sv0[7], sv1[7];
#pragma unroll
    for (int q = 0; q < 7; q++) {
        sv0[q] = svol[r0m * 8 + q];
        sv1[q] = svol[(r0m + 8) * 8 + q];
    }
    __syncthreads();   // order ACX writes (and invd/dsum) before v-loop

#pragma unroll 1
    for (int v = 0; v < V_; v++) {
        const uint8_t* wv = g_wB + (size_t)v * VSTRIDE + (size_t)wg * WGS;
        // per-v constants
        for (int i = t; i < 1792; i += NT) W1s[i] = __ldg(basis_W1 + (size_t)v * 1792 + i);
        if (t < 256) { b1s[t] = __ldg(basis_b1 + v * 256 + t);
                       b2s[t] = __ldg(basis_b2 + v * 256 + t); }
        else if (t < 384) { b4s[t-256] = __ldg(agg_b2 + v * 128 + (t-256)); }
        else { w3s[t-384] = __ldg(agg_W3 + v * 128 + (t-384)); }

        // ---- ctx GEMM: ctxps[18][wg cols] = ctx @ Wctx + cst3 ----
        {
            const int cwm = widg & 1, cwn = widg >> 1;     // 2m x 4n within wg
            float cacc[4][4];
#pragma unroll
            for (int i = 0; i < 4; i++)
#pragma unroll
                for (int j = 0; j < 4; j++) cacc[i][j] = 0.f;
            const int cnbase = cwn * 32 + 8 * ((lane >> 4) & 1) + (lane & 7);
            mma_loop_wg<3, 4, CB, true>(sb, wv + CTXo, Actx,
                                        tw, wg, lane, cwm * 12, cnbase, cacc);
            prefetch_wg<CB>(sb, wv, tw, wg);   // L2 chunks
            // ctx epilogue (cols disjoint per wg; read later by same wg only)
            const int rr0 = cwm * 16 + quad;
            const float* cstv = g_cst3[v];
#pragma unroll
            for (int jj = 0; jj < 2; jj++)
#pragma unroll
                for (int e = 0; e < 2; e++) {
                    const int col = wg * 128 + cwn * 32 + jj * 16 + e * 8 + 2 * q4;
                    const float2 cst = *(const float2*)(cstv + col);
                    const float* a = cacc[2 * jj + e];
                    if (rr0 < NPC && base + rr0 < n_nodes)
                        *(float2*)(ctxps + rr0 * 260 + col) =
                            make_float2(a[0] + cst.x, a[1] + cst.y);
                    if (rr0 + 8 < NPC && base + rr0 + 8 < n_nodes)
                        *(float2*)(ctxps + (rr0 + 8) * 260 + col) =
                            make_float2(a[2] + cst.x, a[3] + cst.y);
                }
        }
        // no sync needed: L1 writes AHI (disjoint from ACX/ctxps reads)

        // ---- L1: produce A frags directly (overlaps L2 weight copies) ----
        {
            uint4* AHI = (uint4*)(sb + OFF_AHI);
#pragma unroll
            for (int u = 0; u < 8; u++) {
                const int c0 = wg * 128 + 16 * u + 2 * q4;
                const int c2 = c0 + 8;
                float2 a00 = *(const float2*)(b1s + c0);
                float2 a01 = *(const float2*)(b1s + c2);
                float2 a10 = a00, a11 = a01;
#pragma unroll
                for (int q = 0; q < 7; q++) {
                    const float2 w0 = *(const float2*)(W1s + q * 256 + c0);
                    const float2 w2 = *(const float2*)(W1s + q * 256 + c2);
                    ffma2s(a00, sv0[q], w0); ffma2s(a01, sv0[q], w2);
                    ffma2s(a10, sv1[q], w0); ffma2s(a11, sv1[q], w2);
                }
                const int fi = (widg * 16 + 8 * wg + u) * 32 + lane;
                AHI[fi] = make_uint4(
                    relu_hi(a00.x, a00.y), relu_hi(a10.x, a10.y),
                    relu_hi(a01.x, a01.y), relu_hi(a11.x, a11.y));
            }
        }
        __syncthreads();

        const int nbase = 8 * ((lane >> 4) & 1) + (lane & 7);
        // ---- L2 ----
        {
            float acc[16][4];
#pragma unroll
            for (int i = 0; i < 16; i++)
#pragma unroll
                for (int j = 0; j < 4; j++) acc[i][j] = 0.f;
            mma_loop_wg<4, 16, CB>(sb, wv, Amain, tw, wg, lane, widg * 16, nbase, acc);
            prefetch_wg<CB>(sb, wv + L3o, tw, wg);
            __syncthreads();   // both wgs done reading L1 A-frags
            epiA<0>(sb, acc, b2s, widg, wg, lane);
        }
        __syncthreads();
        // ---- L3 ----
        {
            float acc[16][4];
#pragma unroll
            for (int i = 0; i < 16; i++)
#pragma unroll
                for (int j = 0; j < 4; j++) acc[i][j] = 0.f;
            mma_loop_wg<4, 16, CB>(sb, wv + L3o, Amain, tw, wg, lane, widg * 16, nbase, acc);
            prefetch_wg<CB>(sb, wv + L4o, tw, wg);
            __syncthreads();
            epiA<1>(sb, acc, ctxps, widg, wg, lane);
        }
        __syncthreads();
        // ---- L4 + L5 ----
        {
            float acc[8][4];
#pragma unroll
            for (int i = 0; i < 8; i++)
#pragma unroll
                for (int j = 0; j < 4; j++) acc[i][j] = 0.f;
            mma_loop_l4(sb, Amain, wg, lane, widg * 16, nbase, acc);
            if (v + 1 < V_)
                prefetch_wg<CB>(sb, wv + VSTRIDE + CTXo, tw, wg);
            float s0 = 0.f, s1 = 0.f;
#pragma unroll
            for (int j = 0; j < 8; j++) {
                const int c0 = wg * 64 + 8 * j + 2 * q4;
                const float w30 = w3s[c0], w31 = w3s[c0 + 1];
                const float bb0 = b4s[c0], bb1 = b4s[c0 + 1];
                s0 += fmaxf(acc[j][0] + bb0, 0.f) * w30 + fmaxf(acc[j][1] + bb1, 0.f) * w31;
                s1 += fmaxf(acc[j][2] + bb0, 0.f) * w30 + fmaxf(acc[j][3] + bb1, 0.f) * w31;
            }
            s0 += __shfl_xor_sync(0xffffffffu, s0, 1);
            s0 += __shfl_xor_sync(0xffffffffu, s0, 2);
            s1 += __shfl_xor_sync(0xffffffffu, s1, 1);
            s1 += __shfl_xor_sync(0xffffffffu, s1, 2);
            if (q4 == 0) {
                arowp[wg * 128 + r0m] = s0;
                arowp[wg * 128 + r0m + 8] = s1;
            }
        }
        __syncthreads();
        if (t < 128) arow[t] = arowp[t] + arowp[128 + t] + __ldg(agg_b3 + v);
        __syncthreads();
        if (t < NPC) {
            const int node = base + t;
            if (node < n_nodes) {
                const float c = arow[t * 7];
                float s = 0.f;
#pragma unroll
                for (int j = 0; j < NK; j++) s += arow[t * 7 + 1 + j] * invd[t * 8 + j];
                out[node * V_ + v] = 0.5f * c + 0.5f * s / dsum[t];
            }
        }
        __syncthreads();
    }
}

// ============================ launcher =======================================
extern "C" void kernel_launch(void* const* d_in, const int* in_sizes, int n_in,
                              void* d_out, int out_size)
{
    const float* centers       = (const float*)d_in[0];
    const float* enc_g         = (const float*)d_in[1];
    const float* enc_node      = (const float*)d_in[2];
    const float* neighbors     = (const float*)d_in[3];
    const float* normals       = (const float*)d_in[4];
    const float* neigh_normals = (const float*)d_in[5];
    const float* areas         = (const float*)d_in[6];
    const float* neigh_areas   = (const float*)d_in[7];
    const float* gpv           = (const float*)d_in[8];
    const float* gpr           = (const float*)d_in[9];
    const float* param_W       = (const float*)d_in[10];
    const float* param_b       = (const float*)d_in[11];
    const float* basis_W1      = (const float*)d_in[12];
    const float* basis_b1      = (const float*)d_in[13];
    const float* basis_W2      = (const float*)d_in[14];
    const float* basis_b2      = (const float*)d_in[15];
    const float* agg_W1        = (const float*)d_in[16];
    const float* agg_b1        = (const float*)d_in[17];
    const float* agg_W2        = (const float*)d_in[18];
    const float* agg_b2        = (const float*)d_in[19];
    const float* agg_W3        = (const float*)d_in[20];
    const float* agg_b3        = (const float*)d_in[21];
    float* out = (float*)d_out;

    const int n_nodes = in_sizes[0] / 3;
    const int grid = (n_nodes + NPC - 1) / NPC;

    cudaFuncSetAttribute(surface_kernel,
                         cudaFuncAttributeMaxDynamicSharedMemorySize, SMEM_BYTES);

    cst3_kernel<<<V_, 256>>>(gpv, gpr, param_W, param_b, agg_W1, agg_b1);
    wconv_kernel<<<2560, 512>>>(basis_W2, agg_W1, agg_W2);
    surface_kernel<<<grid, NT, SMEM_BYTES>>>(
        centers, enc_g, enc_node, neighbors, normals, neigh_normals,
        areas, neigh_areas,
        basis_W1, basis_b1, basis_b2, agg_b2, agg_W3, agg_b3, out, n_nodes);
}